// round 2
// baseline (speedup 1.0000x reference)
#include <cuda_runtime.h>
#include <math.h>

#define B_SZ 4
#define T_LEN 1024
#define E_LEN 1024
#define S_LEN 2048
#define D_DIM 2048
#define H_DIM 256
#define N_HEADS 16
#define K_HEADS 8

__device__ float g_q[(size_t)B_SZ * T_LEN * N_HEADS * H_DIM];
__device__ float g_k[(size_t)B_SZ * S_LEN * K_HEADS * H_DIM];
__device__ float g_v[(size_t)B_SZ * S_LEN * K_HEADS * H_DIM];
__device__ float g_attn[(size_t)B_SZ * T_LEN * N_HEADS * H_DIM];

// Generic SGEMM 128x128x8, 256 thr, 8x8/thread.
// W(kk,j) = W + (j/colsPerHead)*headStride + kk*kRowStride + (j%colsPerHead)
// out row gr -> b=gr/Mpb, r=gr%Mpb; row ptr = C + b*outBS + (r+rowOff)*ldc
__global__ __launch_bounds__(256) void sgemm_kernel(
    const float* __restrict__ A, const float* __restrict__ W, float* __restrict__ C,
    int Kd, int colsPerHead, long long headStride, int kRowStride,
    int Mpb, long long outBS, int rowOff, int ldc)
{
    __shared__ float As[8][132];
    __shared__ float Bs[8][128];
    const int tid = threadIdx.x;
    const int tileM = blockIdx.y * 128, tileN = blockIdx.x * 128;
    const int tr = tid >> 4, tc = tid & 15;
    const int arow = tid >> 1, acol4 = (tid & 1) << 2;
    const float* Aptr = A + (size_t)(tileM + arow) * Kd + acol4;
    const int brow = tid >> 5, bcol = (tid & 31) << 2;
    const int jcol = tileN + bcol;
    const float* Wptr = W + (size_t)(jcol / colsPerHead) * headStride
                          + (size_t)brow * kRowStride + (jcol % colsPerHead);
    float acc[8][8];
#pragma unroll
    for (int i = 0; i < 8; i++)
#pragma unroll
        for (int j = 0; j < 8; j++) acc[i][j] = 0.f;

    const int nK = Kd >> 3;
    for (int kt = 0; kt < nK; kt++) {
        float4 av = *(const float4*)Aptr;
        float4 bv = *(const float4*)Wptr;
        __syncthreads();
        As[acol4 + 0][arow] = av.x; As[acol4 + 1][arow] = av.y;
        As[acol4 + 2][arow] = av.z; As[acol4 + 3][arow] = av.w;
        *(float4*)&Bs[brow][bcol] = bv;
        __syncthreads();
#pragma unroll
        for (int kk = 0; kk < 8; kk++) {
            float4 a0 = *(const float4*)&As[kk][tr * 8];
            float4 a1 = *(const float4*)&As[kk][tr * 8 + 4];
            float4 b0 = *(const float4*)&Bs[kk][tc * 8];
            float4 b1 = *(const float4*)&Bs[kk][tc * 8 + 4];
            float a[8] = {a0.x,a0.y,a0.z,a0.w,a1.x,a1.y,a1.z,a1.w};
            float b[8] = {b0.x,b0.y,b0.z,b0.w,b1.x,b1.y,b1.z,b1.w};
#pragma unroll
            for (int i = 0; i < 8; i++)
#pragma unroll
                for (int j = 0; j < 8; j++) acc[i][j] += a[i] * b[j];
        }
        Aptr += 8;
        Wptr += (size_t)8 * kRowStride;
    }
#pragma unroll
    for (int i = 0; i < 8; i++) {
        int gr = tileM + tr * 8 + i;
        int bi = gr / Mpb, r = gr - bi * Mpb;
        float* crow = C + (size_t)bi * outBS + (size_t)(r + rowOff) * ldc + tileN + tc * 8;
        *(float4*)crow = make_float4(acc[i][0], acc[i][1], acc[i][2], acc[i][3]);
        *(float4*)(crow + 4) = make_float4(acc[i][4], acc[i][5], acc[i][6], acc[i][7]);
    }
}

// RMS-norm (+optional RoPE, +scale). One 256-thr block per (b,t,head) row.
__global__ __launch_bounds__(256) void rms_rope_kernel(
    float* __restrict__ buf, const float* __restrict__ scale,
    int heads, int rowsPerBatch, int bufRPB, int rowStart, int doRope, float outScale)
{
    __shared__ float sh[256];
    __shared__ float ws[8];
    int idx = blockIdx.x;
    int head = idx % heads;
    int tmp = idx / heads;
    int t = tmp % rowsPerBatch;
    int b = tmp / rowsPerBatch;
    float* ptr = buf + ((size_t)((size_t)b * bufRPB + rowStart + t) * heads + head) * H_DIM;
    int h = threadIdx.x;
    float x = ptr[h];
    float ss = x * x;
#pragma unroll
    for (int o = 16; o > 0; o >>= 1) ss += __shfl_xor_sync(0xffffffffu, ss, o);
    if ((h & 31) == 0) ws[h >> 5] = ss;
    __syncthreads();
    float tot = 0.f;
#pragma unroll
    for (int w = 0; w < 8; w++) tot += ws[w];
    float y = x * rsqrtf(tot * (1.f / 256.f) + 1e-6f) * (1.f + scale[h]);
    if (doRope) {
        sh[h] = y;
        __syncthreads();
        int i = h & 127;
        float ang = (float)t * exp2f(-(float)i * 0.10381025296522988f);
        float sn, cs;
        sincosf(ang, &sn, &cs);
        if (h < 128) y = sh[h] * cs - sh[h + 128] * sn;
        else         y = sh[h] * cs + sh[h - 128] * sn;
    }
    ptr[h] = y * outScale;
}

// Flash attention fp32. Grid (T/64, N, B), 256 thr, 214KB smem.
#define FLASH_SMEM_BYTES ((3 * 64 * 256 + 64 * 68) * 4)

__global__ __launch_bounds__(256, 1) void flash_kernel(
    const float* __restrict__ Q, const float* __restrict__ Kc,
    const float* __restrict__ Vc, float* __restrict__ Oa)
{
    extern __shared__ float sm[];
    float* Qs = sm;
    float* Ks = Qs + 64 * 256;
    float* Vs = Ks + 64 * 256;
    float* Ps = Vs + 64 * 256;
    const int tid = threadIdx.x;
    const int tx = tid & 15, ty = tid >> 4;
    const int qt = blockIdx.x, n = blockIdx.y, b = blockIdx.z;
    const int kh = n >> 1;
    const int qbase = qt << 6;
    float4* Qs4 = (float4*)Qs;
    float4* Ks4 = (float4*)Ks;
    float4* Vs4 = (float4*)Vs;

    const float4* qg = (const float4*)(Q + (((size_t)(b * T_LEN + qbase)) * N_HEADS + n) * H_DIM);
    for (int idx = tid; idx < 4096; idx += 256) {
        int r = idx >> 6, f = idx & 63;
        Qs4[(r << 6) + f] = qg[(size_t)r * 1024 + f];
    }
    const float4* kg = (const float4*)(Kc + ((size_t)b * S_LEN * K_HEADS + kh) * H_DIM);
    const float4* vg = (const float4*)(Vc + ((size_t)b * S_LEN * K_HEADS + kh) * H_DIM);

    float m_i[4], l_i[4], acco[4][16];
#pragma unroll
    for (int i = 0; i < 4; i++) {
        m_i[i] = -INFINITY; l_i[i] = 0.f;
#pragma unroll
        for (int j = 0; j < 16; j++) acco[i][j] = 0.f;
    }
    const int swK = tx & 7;
    int gsw[4];
#pragma unroll
    for (int j4 = 0; j4 < 4; j4++) {
        int g = (tx << 2) + j4;
        gsw[j4] = g ^ ((g >> 3) & 7);
    }
    const int nSelf = qt + 1;
    const int nTiles = nSelf + (E_LEN >> 6);

    for (int tIdx = 0; tIdx < nTiles; tIdx++) {
        const int s0 = (tIdx < nSelf) ? (tIdx << 6) : (T_LEN + ((tIdx - nSelf) << 6));
        const bool diag = (tIdx == qt);
        __syncthreads();
        for (int idx = tid; idx < 4096; idx += 256) {
            int c = idx >> 6, f = idx & 63;
            size_t goff = (size_t)(s0 + c) * 512 + f;
            Ks4[(c << 6) + (f ^ ((c >> 2) & 7))] = kg[goff];
            Vs4[(c << 6) + (f ^ ((f >> 3) & 7))] = vg[goff];
        }
        __syncthreads();

        float sv[4][4];
#pragma unroll
        for (int i = 0; i < 4; i++)
#pragma unroll
            for (int j = 0; j < 4; j++) sv[i][j] = 0.f;
#pragma unroll 2
        for (int fc = 0; fc < 64; fc++) {
            float4 qv[4], kv[4];
#pragma unroll
            for (int i = 0; i < 4; i++) qv[i] = Qs4[(((ty << 2) + i) << 6) + fc];
#pragma unroll
            for (int j = 0; j < 4; j++) kv[j] = Ks4[(((tx << 2) + j) << 6) + (fc ^ swK)];
#pragma unroll
            for (int i = 0; i < 4; i++)
#pragma unroll
                for (int j = 0; j < 4; j++) {
                    sv[i][j] += qv[i].x * kv[j].x;
                    sv[i][j] += qv[i].y * kv[j].y;
                    sv[i][j] += qv[i].z * kv[j].z;
                    sv[i][j] += qv[i].w * kv[j].w;
                }
        }

        float rmax[4];
#pragma unroll
        for (int i = 0; i < 4; i++) {
            rmax[i] = -INFINITY;
#pragma unroll
            for (int j = 0; j < 4; j++) {
                float v = 50.f * tanhf(sv[i][j] * 0.02f);
                if (diag) {
                    int col = s0 + (tx << 2) + j;
                    int row = qbase + (ty << 2) + i;
                    if (col > row) v = -INFINITY;
                }
                sv[i][j] = v;
                rmax[i] = fmaxf(rmax[i], v);
            }
        }
#pragma unroll
        for (int i = 0; i < 4; i++)
#pragma unroll
            for (int o = 8; o > 0; o >>= 1)
                rmax[i] = fmaxf(rmax[i], __shfl_xor_sync(0xffffffffu, rmax[i], o));
        float corr[4], rsum[4];
#pragma unroll
        for (int i = 0; i < 4; i++) {
            float mn = fmaxf(m_i[i], rmax[i]);
            corr[i] = expf(m_i[i] - mn);
            m_i[i] = mn;
            float s = 0.f;
#pragma unroll
            for (int j = 0; j < 4; j++) {
                float p = expf(sv[i][j] - mn);
                sv[i][j] = p;
                s += p;
            }
            rsum[i] = s;
        }
#pragma unroll
        for (int i = 0; i < 4; i++) {
#pragma unroll
            for (int o = 8; o > 0; o >>= 1)
                rsum[i] += __shfl_xor_sync(0xffffffffu, rsum[i], o);
            l_i[i] = l_i[i] * corr[i] + rsum[i];
#pragma unroll
            for (int j = 0; j < 16; j++) acco[i][j] *= corr[i];
#pragma unroll
            for (int j = 0; j < 4; j++)
                Ps[((ty << 2) + i) * 68 + (tx << 2) + j] = sv[i][j];
        }
        __syncthreads();

#pragma unroll 2
        for (int kk = 0; kk < 64; kk++) {
            float pv[4];
#pragma unroll
            for (int i = 0; i < 4; i++) pv[i] = Ps[((ty << 2) + i) * 68 + kk];
            float4 vv[4];
#pragma unroll
            for (int j4 = 0; j4 < 4; j4++) vv[j4] = Vs4[(kk << 6) + gsw[j4]];
#pragma unroll
            for (int i = 0; i < 4; i++)
#pragma unroll
                for (int j4 = 0; j4 < 4; j4++) {
                    acco[i][j4 * 4 + 0] += pv[i] * vv[j4].x;
                    acco[i][j4 * 4 + 1] += pv[i] * vv[j4].y;
                    acco[i][j4 * 4 + 2] += pv[i] * vv[j4].z;
                    acco[i][j4 * 4 + 3] += pv[i] * vv[j4].w;
                }
        }
    }
#pragma unroll
    for (int i = 0; i < 4; i++) {
        float inv = 1.f / l_i[i];
        int t = qbase + (ty << 2) + i;
        float* orow = Oa + (((size_t)(b * T_LEN + t)) * N_HEADS + n) * H_DIM + (tx << 4);
#pragma unroll
        for (int j4 = 0; j4 < 4; j4++) {
            float4 o;
            o.x = acco[i][j4 * 4 + 0] * inv;
            o.y = acco[i][j4 * 4 + 1] * inv;
            o.z = acco[i][j4 * 4 + 2] * inv;
            o.w = acco[i][j4 * 4 + 3] * inv;
            ((float4*)orow)[j4] = o;
        }
    }
}

extern "C" void kernel_launch(void* const* d_in, const int* in_sizes, int n_in,
                              void* d_out, int out_size)
{
    (void)in_sizes; (void)n_in; (void)out_size;
    const float* hs  = (const float*)d_in[0];
    const float* enc = (const float*)d_in[1];
    const float* qw  = (const float*)d_in[4];
    const float* kw  = (const float*)d_in[5];
    const float* vw  = (const float*)d_in[6];
    const float* ow  = (const float*)d_in[7];
    const float* qsc = (const float*)d_in[8];
    const float* ksc = (const float*)d_in[9];
    float* out = (float*)d_out;

    float *qb, *kb, *vb, *ab;
    cudaGetSymbolAddress((void**)&qb, g_q);
    cudaGetSymbolAddress((void**)&kb, g_k);
    cudaGetSymbolAddress((void**)&vb, g_v);
    cudaGetSymbolAddress((void**)&ab, g_attn);

    static int smemSet = 0;
    if (!smemSet) {
        cudaFuncSetAttribute(flash_kernel, cudaFuncAttributeMaxDynamicSharedMemorySize,
                             FLASH_SMEM_BYTES);
        smemSet = 1;
    }

    const long long pHS = (long long)D_DIM * H_DIM;
    const long long kvBS = (long long)S_LEN * K_HEADS * H_DIM;

    // Q = hs @ q_w -> g_q [B*T, N*H]
    sgemm_kernel<<<dim3(32, 32), 256>>>(hs, qw, qb, D_DIM, H_DIM, pHS, H_DIM,
                                        4096, 0, 0, N_HEADS * H_DIM);
    // self K/V -> rows [0,T)
    sgemm_kernel<<<dim3(16, 32), 256>>>(hs, kw, kb, D_DIM, H_DIM, pHS, H_DIM,
                                        T_LEN, kvBS, 0, K_HEADS * H_DIM);
    sgemm_kernel<<<dim3(16, 32), 256>>>(hs, vw, vb, D_DIM, H_DIM, pHS, H_DIM,
                                        T_LEN, kvBS, 0, K_HEADS * H_DIM);
    // cross K/V -> rows [T,S)
    sgemm_kernel<<<dim3(16, 32), 256>>>(enc, kw, kb, D_DIM, H_DIM, pHS, H_DIM,
                                        E_LEN, kvBS, T_LEN, K_HEADS * H_DIM);
    sgemm_kernel<<<dim3(16, 32), 256>>>(enc, vw, vb, D_DIM, H_DIM, pHS, H_DIM,
                                        E_LEN, kvBS, T_LEN, K_HEADS * H_DIM);

    // Q: rms + rope + *SCALE
    rms_rope_kernel<<<B_SZ * T_LEN * N_HEADS, 256>>>(qb, qsc, N_HEADS, T_LEN, T_LEN,
                                                     0, 1, 0.0625f);
    // self K: rms + rope
    rms_rope_kernel<<<B_SZ * T_LEN * K_HEADS, 256>>>(kb, ksc, K_HEADS, T_LEN, S_LEN,
                                                     0, 1, 1.0f);
    // cross K: rms only
    rms_rope_kernel<<<B_SZ * E_LEN * K_HEADS, 256>>>(kb, ksc, K_HEADS, E_LEN, S_LEN,
                                                     T_LEN, 0, 1.0f);

    flash_kernel<<<dim3(T_LEN / 64, N_HEADS, B_SZ), 256, FLASH_SMEM_BYTES>>>(qb, kb, vb, ab);

    // out = attn @ o_w  (o_w flat [N*H, D])
    sgemm_kernel<<<dim3(16, 32), 256>>>(ab, ow, out, N_HEADS * H_DIM, D_DIM, 0, D_DIM,
                                        4096, 0, 0, D_DIM);
}

// round 4
// speedup vs baseline: 1.5912x; 1.5912x over previous
#include <cuda_runtime.h>
#include <cuda_bf16.h>
#include <stdint.h>
#include <math.h>

#define B_SZ 4
#define T_LEN 1024
#define E_LEN 1024
#define S_LEN 2048
#define D_DIM 2048
#define H_DIM 256
#define N_HEADS 16
#define K_HEADS 8

// fp32 scratch
__device__ float g_q[(size_t)B_SZ * T_LEN * N_HEADS * H_DIM];
__device__ float g_k[(size_t)B_SZ * S_LEN * K_HEADS * H_DIM];
__device__ float g_v[(size_t)B_SZ * S_LEN * K_HEADS * H_DIM];
__device__ float g_attn[(size_t)B_SZ * T_LEN * N_HEADS * H_DIM];
// bf16 split buffers (K-concat: act = [hi|lo|hi], weightT = [hi|hi|lo])
__device__ __nv_bfloat16 g_hs3 [(size_t)4096 * 6144];
__device__ __nv_bfloat16 g_enc3[(size_t)4096 * 6144];
__device__ __nv_bfloat16 g_qw3 [(size_t)4096 * 6144];
__device__ __nv_bfloat16 g_kw3 [(size_t)2048 * 6144];
__device__ __nv_bfloat16 g_vw3 [(size_t)2048 * 6144];
__device__ __nv_bfloat16 g_ow3 [(size_t)2048 * 12288];
__device__ __nv_bfloat16 g_at3 [(size_t)4096 * 12288];

// ---------------- helpers ----------------
__device__ __forceinline__ uint32_t smem_u32(const void* p) {
    uint32_t a;
    asm("{ .reg .u64 t; cvta.to.shared.u64 t, %1; cvt.u32.u64 %0, t; }" : "=r"(a) : "l"(p));
    return a;
}
#define CP16(dst, src) \
    asm volatile("cp.async.cg.shared.global [%0], [%1], 16;" :: "r"(dst), "l"(src) : "memory")
#define CP_COMMIT asm volatile("cp.async.commit_group;" ::: "memory")
#define CP_WAIT2  asm volatile("cp.async.wait_group 2;" ::: "memory")
#define LDSM4(r0, r1, r2, r3, addr) \
    asm volatile("ldmatrix.sync.aligned.m8n8.x4.shared.b16 {%0,%1,%2,%3}, [%4];" \
        : "=r"(r0), "=r"(r1), "=r"(r2), "=r"(r3) : "r"(addr))
#define MMA16816(d, a, b0, b1) \
    asm volatile("mma.sync.aligned.m16n8k16.row.col.f32.bf16.bf16.f32 " \
        "{%0,%1,%2,%3}, {%4,%5,%6,%7}, {%8,%9}, {%0,%1,%2,%3};" \
        : "+f"((d)[0]), "+f"((d)[1]), "+f"((d)[2]), "+f"((d)[3]) \
        : "r"((a)[0]), "r"((a)[1]), "r"((a)[2]), "r"((a)[3]), "r"(b0), "r"(b1))

// smem tile swizzle: 128 rows x 64B (32 bf16). 128B line = 2 rows, 8 chunks of 16B.
// chunk = ((row&1)*4 + kbyte/16) ^ (line&7) -> conflict-free ldmatrix phases.
__device__ __forceinline__ uint32_t sw_off(int row, int kbyte) {
    int line = row >> 1;
    int ch = (((row & 1) << 2) + (kbyte >> 4)) ^ (line & 7);
    return (uint32_t)(line * 128 + ch * 16 + (kbyte & 15));
}

// ---------------- split kernels ----------------
__global__ __launch_bounds__(256) void asplit_kernel(
    const float* __restrict__ X, __nv_bfloat16* __restrict__ Y, int Kd)
{
    int r = blockIdx.y;
    int k = blockIdx.x * 256 + threadIdx.x;
    float x = X[(size_t)r * Kd + k];
    __nv_bfloat16 hi = __float2bfloat16(x);
    __nv_bfloat16 lo = __float2bfloat16(x - __bfloat162float(hi));
    size_t base = (size_t)r * 3 * Kd;
    Y[base + k] = hi;
    Y[base + Kd + k] = lo;
    Y[base + 2 * Kd + k] = hi;
}

// W(k,j) = W[(j/cph)*hstr + k*krs + j%cph]; out Yt[j, 3K] = [hi|hi|lo]
__global__ __launch_bounds__(256) void wsplit_kernel(
    const float* __restrict__ W, __nv_bfloat16* __restrict__ Yt,
    int Kd, int cph, long long hstr, int krs)
{
    __shared__ float t[32][33];
    int k0 = blockIdx.y * 32, j0 = blockIdx.x * 32;
    int tx = threadIdx.x & 31, ty8 = threadIdx.x >> 5;
#pragma unroll
    for (int i = 0; i < 4; i++) {
        int kl = ty8 + i * 8;
        int j = j0 + tx;
        t[kl][tx] = W[(size_t)(j / cph) * hstr + (size_t)(k0 + kl) * krs + (j % cph)];
    }
    __syncthreads();
#pragma unroll
    for (int i = 0; i < 4; i++) {
        int j = j0 + ty8 + i * 8;
        int k = k0 + tx;
        float x = t[tx][ty8 + i * 8];
        __nv_bfloat16 hi = __float2bfloat16(x);
        __nv_bfloat16 lo = __float2bfloat16(x - __bfloat162float(hi));
        size_t base = (size_t)j * 3 * Kd;
        Yt[base + k] = hi;
        Yt[base + Kd + k] = hi;
        Yt[base + 2 * Kd + k] = lo;
    }
}

// ---------------- HMMA bf16 GEMM ----------------
// C[gr, n0+j] = sum_k A[gr,k] * Bw[n0+j, k];  A [M,Kp], Bw [N,Kp] row-major bf16.
// CTA tile 128x128x32, 8 warps (4M x 2N), warp tile 32x64 (m16n8k16).
#define GSTAGES 3
#define STG_BYTES 16384
#define GEMM_SMEM (GSTAGES * STG_BYTES)

__global__ void __launch_bounds__(256, 2) gemm_hmma(
    const __nv_bfloat16* __restrict__ A, const __nv_bfloat16* __restrict__ Bw,
    float* __restrict__ C, int Kp, int Mpb, long long outBS, int rowOff, int ldc)
{
    extern __shared__ char smraw[];
    const uint32_t sb = smem_u32(smraw);
    const int tid = threadIdx.x;
    const int lane = tid & 31, wid = tid >> 5;
    const int wm = wid & 3, wn = wid >> 2;
    const int m0 = blockIdx.y * 128, n0 = blockIdx.x * 128;
    const int nIter = Kp >> 5;

    // cp.async mapping: thread t loads 32B of row (t>>1) at elem offset (t&1)*16
    const int crow = tid >> 1;
    const int ck = (tid & 1) << 4;
    const __nv_bfloat16* ga = A + (size_t)(m0 + crow) * Kp + ck;
    const __nv_bfloat16* gb = Bw + (size_t)(n0 + crow) * Kp + ck;
    const uint32_t sw0 = sw_off(crow, ck * 2);
    const uint32_t sw1 = sw_off(crow, ck * 2 + 16);

    // ldmatrix per-lane offsets
    const int r8 = lane & 7, sel = lane >> 3;
    uint32_t aoff[2][2], boff[4][2];
#pragma unroll
    for (int mf = 0; mf < 2; mf++)
#pragma unroll
        for (int ks = 0; ks < 2; ks++) {
            int row = wm * 32 + mf * 16 + r8 + ((sel & 1) << 3);
            int kb = ks * 32 + ((sel >> 1) << 4);
            aoff[mf][ks] = sw_off(row, kb);
        }
#pragma unroll
    for (int np = 0; np < 4; np++)
#pragma unroll
        for (int ks = 0; ks < 2; ks++) {
            int row = wn * 64 + np * 16 + r8 + ((sel >> 1) << 3);
            int kb = ks * 32 + ((sel & 1) << 4);
            boff[np][ks] = 8192u + sw_off(row, kb);
        }

    float acc[2][8][4];
#pragma unroll
    for (int mf = 0; mf < 2; mf++)
#pragma unroll
        for (int nf = 0; nf < 8; nf++)
#pragma unroll
            for (int q = 0; q < 4; q++) acc[mf][nf][q] = 0.f;

    // prologue: stages 0,1
#pragma unroll
    for (int s = 0; s < 2; s++) {
        uint32_t base = sb + (uint32_t)s * STG_BYTES;
        const __nv_bfloat16* pa = ga + s * 32;
        const __nv_bfloat16* pb = gb + s * 32;
        CP16(base + sw0, pa);
        CP16(base + sw1, pa + 8);
        CP16(base + 8192u + sw0, pb);
        CP16(base + 8192u + sw1, pb + 8);
        CP_COMMIT;
    }

    for (int it = 0; it < nIter; it++) {
        if (it + 2 < nIter) {
            int s = (it + 2) % GSTAGES;
            uint32_t base = sb + (uint32_t)s * STG_BYTES;
            const __nv_bfloat16* pa = ga + (size_t)(it + 2) * 32;
            const __nv_bfloat16* pb = gb + (size_t)(it + 2) * 32;
            CP16(base + sw0, pa);
            CP16(base + sw1, pa + 8);
            CP16(base + 8192u + sw0, pb);
            CP16(base + 8192u + sw1, pb + 8);
        }
        CP_COMMIT;
        CP_WAIT2;
        __syncthreads();

        uint32_t sbase = sb + (uint32_t)(it % GSTAGES) * STG_BYTES;
#pragma unroll
        for (int ks = 0; ks < 2; ks++) {
            uint32_t af[2][4];
#pragma unroll
            for (int mf = 0; mf < 2; mf++)
                LDSM4(af[mf][0], af[mf][1], af[mf][2], af[mf][3], sbase + aoff[mf][ks]);
            uint32_t bf[4][4];
#pragma unroll
            for (int np = 0; np < 4; np++)
                LDSM4(bf[np][0], bf[np][1], bf[np][2], bf[np][3], sbase + boff[np][ks]);
#pragma unroll
            for (int mf = 0; mf < 2; mf++)
#pragma unroll
                for (int np = 0; np < 4; np++) {
                    MMA16816(acc[mf][np * 2 + 0], af[mf], bf[np][0], bf[np][1]);
                    MMA16816(acc[mf][np * 2 + 1], af[mf], bf[np][2], bf[np][3]);
                }
        }
        __syncthreads();
    }

    // epilogue: lane l of frag -> rows (l>>2)+{0,8}, cols (l&3)*2+{0,1}
#pragma unroll
    for (int mf = 0; mf < 2; mf++)
#pragma unroll
        for (int rh = 0; rh < 2; rh++) {
            int gr = m0 + wm * 32 + mf * 16 + (lane >> 2) + rh * 8;
            int bi = gr / Mpb;
            int rr = gr - bi * Mpb;
            float* rowp = C + (size_t)bi * outBS + (size_t)(rr + rowOff) * ldc
                        + n0 + wn * 64 + (lane & 3) * 2;
#pragma unroll
            for (int nf = 0; nf < 8; nf++) {
                float2 v = make_float2(acc[mf][nf][rh * 2 + 0], acc[mf][nf][rh * 2 + 1]);
                *(float2*)(rowp + nf * 8) = v;
            }
        }
}

// ---------------- RMS-norm (+RoPE) ----------------
__global__ __launch_bounds__(256) void rms_rope_kernel(
    float* __restrict__ buf, const float* __restrict__ scale,
    int heads, int rowsPerBatch, int bufRPB, int rowStart, int doRope, float outScale)
{
    __shared__ float sh[256];
    __shared__ float ws[8];
    int idx = blockIdx.x;
    int head = idx % heads;
    int tmp = idx / heads;
    int t = tmp % rowsPerBatch;
    int b = tmp / rowsPerBatch;
    float* ptr = buf + ((size_t)((size_t)b * bufRPB + rowStart + t) * heads + head) * H_DIM;
    int h = threadIdx.x;
    float x = ptr[h];
    float ss = x * x;
#pragma unroll
    for (int o = 16; o > 0; o >>= 1) ss += __shfl_xor_sync(0xffffffffu, ss, o);
    if ((h & 31) == 0) ws[h >> 5] = ss;
    __syncthreads();
    float tot = 0.f;
#pragma unroll
    for (int w = 0; w < 8; w++) tot += ws[w];
    float y = x * rsqrtf(tot * (1.f / 256.f) + 1e-6f) * (1.f + scale[h]);
    if (doRope) {
        sh[h] = y;
        __syncthreads();
        int i = h & 127;
        float ang = (float)t * exp2f(-(float)i * 0.10381025296522988f);
        float sn, cs;
        sincosf(ang, &sn, &cs);
        if (h < 128) y = sh[h] * cs - sh[h + 128] * sn;
        else         y = sh[h] * cs + sh[h - 128] * sn;
    }
    ptr[h] = y * outScale;
}

// ---------------- flash attention fp32 ----------------
#define FLASH_SMEM_BYTES ((3 * 64 * 256 + 64 * 68) * 4)

__global__ __launch_bounds__(256, 1) void flash_kernel(
    const float* __restrict__ Q, const float* __restrict__ Kc,
    const float* __restrict__ Vc, float* __restrict__ Oa)
{
    extern __shared__ float sm[];
    float* Qs = sm;
    float* Ks = Qs + 64 * 256;
    float* Vs = Ks + 64 * 256;
    float* Ps = Vs + 64 * 256;
    const int tid = threadIdx.x;
    const int tx = tid & 15, ty = tid >> 4;
    const int qt = blockIdx.x, n = blockIdx.y, b = blockIdx.z;
    const int kh = n >> 1;
    const int qbase = qt << 6;
    float4* Qs4 = (float4*)Qs;
    float4* Ks4 = (float4*)Ks;
    float4* Vs4 = (float4*)Vs;

    const float4* qg = (const float4*)(Q + (((size_t)(b * T_LEN + qbase)) * N_HEADS + n) * H_DIM);
    for (int idx = tid; idx < 4096; idx += 256) {
        int r = idx >> 6, f = idx & 63;
        Qs4[(r << 6) + f] = qg[(size_t)r * 1024 + f];
    }
    const float4* kg = (const float4*)(Kc + ((size_t)b * S_LEN * K_HEADS + kh) * H_DIM);
    const float4* vg = (const float4*)(Vc + ((size_t)b * S_LEN * K_HEADS + kh) * H_DIM);

    float m_i[4], l_i[4], acco[4][16];
#pragma unroll
    for (int i = 0; i < 4; i++) {
        m_i[i] = -INFINITY; l_i[i] = 0.f;
#pragma unroll
        for (int j = 0; j < 16; j++) acco[i][j] = 0.f;
    }
    const int swK = tx & 7;
    int gsw[4];
#pragma unroll
    for (int j4 = 0; j4 < 4; j4++) {
        int g = (tx << 2) + j4;
        gsw[j4] = g ^ ((g >> 3) & 7);
    }
    const int nSelf = qt + 1;
    const int nTiles = nSelf + (E_LEN >> 6);

    for (int tIdx = 0; tIdx < nTiles; tIdx++) {
        const int s0 = (tIdx < nSelf) ? (tIdx << 6) : (T_LEN + ((tIdx - nSelf) << 6));
        const bool diag = (tIdx == qt);
        __syncthreads();
        for (int idx = tid; idx < 4096; idx += 256) {
            int c = idx >> 6, f = idx & 63;
            size_t goff = (size_t)(s0 + c) * 512 + f;
            Ks4[(c << 6) + (f ^ ((c >> 2) & 7))] = kg[goff];
            Vs4[(c << 6) + (f ^ ((f >> 3) & 7))] = vg[goff];
        }
        __syncthreads();

        float sv[4][4];
#pragma unroll
        for (int i = 0; i < 4; i++)
#pragma unroll
            for (int j = 0; j < 4; j++) sv[i][j] = 0.f;
#pragma unroll 2
        for (int fc = 0; fc < 64; fc++) {
            float4 qv[4], kv[4];
#pragma unroll
            for (int i = 0; i < 4; i++) qv[i] = Qs4[(((ty << 2) + i) << 6) + fc];
#pragma unroll
            for (int j = 0; j < 4; j++) kv[j] = Ks4[(((tx << 2) + j) << 6) + (fc ^ swK)];
#pragma unroll
            for (int i = 0; i < 4; i++)
#pragma unroll
                for (int j = 0; j < 4; j++) {
                    sv[i][j] += qv[i].x * kv[j].x;
                    sv[i][j] += qv[i].y * kv[j].y;
                    sv[i][j] += qv[i].z * kv[j].z;
                    sv[i][j] += qv[i].w * kv[j].w;
                }
        }

        float rmax[4];
#pragma unroll
        for (int i = 0; i < 4; i++) {
            rmax[i] = -INFINITY;
#pragma unroll
            for (int j = 0; j < 4; j++) {
                float v = 50.f * tanhf(sv[i][j] * 0.02f);
                if (diag) {
                    int col = s0 + (tx << 2) + j;
                    int row = qbase + (ty << 2) + i;
                    if (col > row) v = -INFINITY;
                }
                sv[i][j] = v;
                rmax[i] = fmaxf(rmax[i], v);
            }
        }
#pragma unroll
        for (int i = 0; i < 4; i++)
#pragma unroll
            for (int o = 8; o > 0; o >>= 1)
                rmax[i] = fmaxf(rmax[i], __shfl_xor_sync(0xffffffffu, rmax[i], o));
        float corr[4], rsum[4];
#pragma unroll
        for (int i = 0; i < 4; i++) {
            float mn = fmaxf(m_i[i], rmax[i]);
            corr[i] = expf(m_i[i] - mn);
            m_i[i] = mn;
            float s = 0.f;
#pragma unroll
            for (int j = 0; j < 4; j++) {
                float p = expf(sv[i][j] - mn);
                sv[i][j] = p;
                s += p;
            }
            rsum[i] = s;
        }
#pragma unroll
        for (int i = 0; i < 4; i++) {
#pragma unroll
            for (int o = 8; o > 0; o >>= 1)
                rsum[i] += __shfl_xor_sync(0xffffffffu, rsum[i], o);
            l_i[i] = l_i[i] * corr[i] + rsum[i];
#pragma unroll
            for (int j = 0; j < 16; j++) acco[i][j] *= corr[i];
#pragma unroll
            for (int j = 0; j < 4; j++)
                Ps[((ty << 2) + i) * 68 + (tx << 2) + j] = sv[i][j];
        }
        __syncthreads();

#pragma unroll 2
        for (int kk = 0; kk < 64; kk++) {
            float pv[4];
#pragma unroll
            for (int i = 0; i < 4; i++) pv[i] = Ps[((ty << 2) + i) * 68 + kk];
            float4 vv[4];
#pragma unroll
            for (int j4 = 0; j4 < 4; j4++) vv[j4] = Vs4[(kk << 6) + gsw[j4]];
#pragma unroll
            for (int i = 0; i < 4; i++)
#pragma unroll
                for (int j4 = 0; j4 < 4; j4++) {
                    acco[i][j4 * 4 + 0] += pv[i] * vv[j4].x;
                    acco[i][j4 * 4 + 1] += pv[i] * vv[j4].y;
                    acco[i][j4 * 4 + 2] += pv[i] * vv[j4].z;
                    acco[i][j4 * 4 + 3] += pv[i] * vv[j4].w;
                }
        }
    }
#pragma unroll
    for (int i = 0; i < 4; i++) {
        float inv = 1.f / l_i[i];
        int t = qbase + (ty << 2) + i;
        float* orow = Oa + (((size_t)(b * T_LEN + t)) * N_HEADS + n) * H_DIM + (tx << 4);
#pragma unroll
        for (int j4 = 0; j4 < 4; j4++) {
            float4 o;
            o.x = acco[i][j4 * 4 + 0] * inv;
            o.y = acco[i][j4 * 4 + 1] * inv;
            o.z = acco[i][j4 * 4 + 2] * inv;
            o.w = acco[i][j4 * 4 + 3] * inv;
            ((float4*)orow)[j4] = o;
        }
    }
}

// ---------------- launch ----------------
extern "C" void kernel_launch(void* const* d_in, const int* in_sizes, int n_in,
                              void* d_out, int out_size)
{
    (void)in_sizes; (void)n_in; (void)out_size;
    const float* hs  = (const float*)d_in[0];
    const float* enc = (const float*)d_in[1];
    const float* qw  = (const float*)d_in[4];
    const float* kw  = (const float*)d_in[5];
    const float* vw  = (const float*)d_in[6];
    const float* ow  = (const float*)d_in[7];
    const float* qsc = (const float*)d_in[8];
    const float* ksc = (const float*)d_in[9];
    float* out = (float*)d_out;

    float *qb, *kb, *vb, *ab;
    cudaGetSymbolAddress((void**)&qb, g_q);
    cudaGetSymbolAddress((void**)&kb, g_k);
    cudaGetSymbolAddress((void**)&vb, g_v);
    cudaGetSymbolAddress((void**)&ab, g_attn);
    __nv_bfloat16 *hs3, *enc3, *qw3, *kw3, *vw3, *ow3, *at3;
    cudaGetSymbolAddress((void**)&hs3, g_hs3);
    cudaGetSymbolAddress((void**)&enc3, g_enc3);
    cudaGetSymbolAddress((void**)&qw3, g_qw3);
    cudaGetSymbolAddress((void**)&kw3, g_kw3);
    cudaGetSymbolAddress((void**)&vw3, g_vw3);
    cudaGetSymbolAddress((void**)&ow3, g_ow3);
    cudaGetSymbolAddress((void**)&at3, g_at3);

    static int cfg = 0;
    if (!cfg) {
        cudaFuncSetAttribute(flash_kernel, cudaFuncAttributeMaxDynamicSharedMemorySize, FLASH_SMEM_BYTES);
        cudaFuncSetAttribute(gemm_hmma, cudaFuncAttributeMaxDynamicSharedMemorySize, GEMM_SMEM);
        cfg = 1;
    }

    // splits
    asplit_kernel<<<dim3(D_DIM / 256, 4096), 256>>>(hs, hs3, D_DIM);
    asplit_kernel<<<dim3(D_DIM / 256, 4096), 256>>>(enc, enc3, D_DIM);
    wsplit_kernel<<<dim3(4096 / 32, D_DIM / 32), 256>>>(qw, qw3, D_DIM, H_DIM, (long long)D_DIM * H_DIM, H_DIM);
    wsplit_kernel<<<dim3(2048 / 32, D_DIM / 32), 256>>>(kw, kw3, D_DIM, H_DIM, (long long)D_DIM * H_DIM, H_DIM);
    wsplit_kernel<<<dim3(2048 / 32, D_DIM / 32), 256>>>(vw, vw3, D_DIM, H_DIM, (long long)D_DIM * H_DIM, H_DIM);
    wsplit_kernel<<<dim3(2048 / 32, 4096 / 32), 256>>>(ow, ow3, 4096, D_DIM, 0LL, D_DIM);

    const long long kvBS = (long long)S_LEN * K_HEADS * H_DIM;
    // Q = hs3 @ qw3^T -> g_q [4096, 4096]
    gemm_hmma<<<dim3(32, 32), 256, GEMM_SMEM>>>(hs3, qw3, qb, 6144, 4096, 0LL, 0, 4096);
    // self K/V -> rows [0,T)
    gemm_hmma<<<dim3(16, 32), 256, GEMM_SMEM>>>(hs3, kw3, kb, 6144, T_LEN, kvBS, 0, 2048);
    gemm_hmma<<<dim3(16, 32), 256, GEMM_SMEM>>>(hs3, vw3, vb, 6144, T_LEN, kvBS, 0, 2048);
    // cross K/V -> rows [T,S)
    gemm_hmma<<<dim3(16, 32), 256, GEMM_SMEM>>>(enc3, kw3, kb, 6144, E_LEN, kvBS, T_LEN, 2048);
    gemm_hmma<<<dim3(16, 32), 256, GEMM_SMEM>>>(enc3, vw3, vb, 6144, E_LEN, kvBS, T_LEN, 2048);

    rms_rope_kernel<<<B_SZ * T_LEN * N_HEADS, 256>>>(qb, qsc, N_HEADS, T_LEN, T_LEN, 0, 1, 0.0625f);
    rms_rope_kernel<<<B_SZ * T_LEN * K_HEADS, 256>>>(kb, ksc, K_HEADS, T_LEN, S_LEN, 0, 1, 1.0f);
    rms_rope_kernel<<<B_SZ * E_LEN * K_HEADS, 256>>>(kb, ksc, K_HEADS, E_LEN, S_LEN, T_LEN, 0, 1.0f);

    flash_kernel<<<dim3(T_LEN / 64, N_HEADS, B_SZ), 256, FLASH_SMEM_BYTES>>>(qb, kb, vb, ab);

    // O = attn @ ow : split attn then HMMA GEMM (K' = 12288)
    asplit_kernel<<<dim3(4096 / 256, 4096), 256>>>(ab, at3, 4096);
    gemm_hmma<<<dim3(16, 32), 256, GEMM_SMEM>>>(at3, ow3, out, 12288, 4096, 0LL, 0, 2048);
}

// round 5
// speedup vs baseline: 2.6915x; 1.6915x over previous
#include <cuda_runtime.h>
#include <cuda_bf16.h>
#include <cuda_fp16.h>
#include <stdint.h>
#include <math.h>

#define B_SZ 4
#define T_LEN 1024
#define E_LEN 1024
#define S_LEN 2048
#define D_DIM 2048
#define H_DIM 256
#define N_HEADS 16
#define K_HEADS 8

// fp32 scratch
__device__ float g_q[(size_t)B_SZ * T_LEN * N_HEADS * H_DIM];
__device__ float g_k[(size_t)B_SZ * S_LEN * K_HEADS * H_DIM];
__device__ float g_v[(size_t)B_SZ * S_LEN * K_HEADS * H_DIM];
__device__ float g_attn[(size_t)B_SZ * T_LEN * N_HEADS * H_DIM];
// fp16 attention operands
__device__ __half g_q16[(size_t)B_SZ * T_LEN * N_HEADS * H_DIM];
__device__ __half g_k16[(size_t)B_SZ * S_LEN * K_HEADS * H_DIM];
__device__ __half g_v16[(size_t)B_SZ * S_LEN * K_HEADS * H_DIM];
// bf16 split buffers (K-concat: act = [hi|lo|hi], weightT = [hi|hi|lo])
__device__ __nv_bfloat16 g_hs3 [(size_t)4096 * 6144];
__device__ __nv_bfloat16 g_enc3[(size_t)4096 * 6144];
__device__ __nv_bfloat16 g_qw3 [(size_t)4096 * 6144];
__device__ __nv_bfloat16 g_kw3 [(size_t)2048 * 6144];
__device__ __nv_bfloat16 g_vw3 [(size_t)2048 * 6144];
__device__ __nv_bfloat16 g_ow3 [(size_t)2048 * 12288];
__device__ __nv_bfloat16 g_at3 [(size_t)4096 * 12288];

// ---------------- helpers ----------------
__device__ __forceinline__ uint32_t smem_u32(const void* p) {
    uint32_t a;
    asm("{ .reg .u64 t; cvta.to.shared.u64 t, %1; cvt.u32.u64 %0, t; }" : "=r"(a) : "l"(p));
    return a;
}
#define CP16(dst, src) \
    asm volatile("cp.async.cg.shared.global [%0], [%1], 16;" :: "r"(dst), "l"(src) : "memory")
#define CP_COMMIT asm volatile("cp.async.commit_group;" ::: "memory")
#define CP_WAIT2  asm volatile("cp.async.wait_group 2;" ::: "memory")
#define CP_WAIT1  asm volatile("cp.async.wait_group 1;" ::: "memory")
#define CP_WAIT0  asm volatile("cp.async.wait_group 0;" ::: "memory")
#define LDSM4(r0, r1, r2, r3, addr) \
    asm volatile("ldmatrix.sync.aligned.m8n8.x4.shared.b16 {%0,%1,%2,%3}, [%4];" \
        : "=r"(r0), "=r"(r1), "=r"(r2), "=r"(r3) : "r"(addr))
#define LDSM4T(r0, r1, r2, r3, addr) \
    asm volatile("ldmatrix.sync.aligned.m8n8.x4.trans.shared.b16 {%0,%1,%2,%3}, [%4];" \
        : "=r"(r0), "=r"(r1), "=r"(r2), "=r"(r3) : "r"(addr))
#define MMA16816(d, a, b0, b1) \
    asm volatile("mma.sync.aligned.m16n8k16.row.col.f32.bf16.bf16.f32 " \
        "{%0,%1,%2,%3}, {%4,%5,%6,%7}, {%8,%9}, {%0,%1,%2,%3};" \
        : "+f"((d)[0]), "+f"((d)[1]), "+f"((d)[2]), "+f"((d)[3]) \
        : "r"((a)[0]), "r"((a)[1]), "r"((a)[2]), "r"((a)[3]), "r"(b0), "r"(b1))
#define MMAH16816(d, a, b0, b1) \
    asm volatile("mma.sync.aligned.m16n8k16.row.col.f32.f16.f16.f32 " \
        "{%0,%1,%2,%3}, {%4,%5,%6,%7}, {%8,%9}, {%0,%1,%2,%3};" \
        : "+f"((d)[0]), "+f"((d)[1]), "+f"((d)[2]), "+f"((d)[3]) \
        : "r"((a)[0]), "r"((a)[1]), "r"((a)[2]), "r"((a)[3]), "r"(b0), "r"(b1))

// gemm smem tile swizzle: 128 rows x 64B. 128B line = 2 rows, 8 chunks of 16B.
__device__ __forceinline__ uint32_t sw_off(int row, int kbyte) {
    int line = row >> 1;
    int ch = (((row & 1) << 2) + (kbyte >> 4)) ^ (line & 7);
    return (uint32_t)(line * 128 + ch * 16 + (kbyte & 15));
}
// flash smem swizzle: 512B rows (256 halfs), 32 chunks of 16B, xor low 3 bits with row&7
__device__ __forceinline__ uint32_t fsw(int row, int kbyte) {
    return (uint32_t)(row * 512 + ((((kbyte >> 4) ^ (row & 7))) << 4) + (kbyte & 15));
}

// ---------------- split kernels ----------------
__global__ __launch_bounds__(256) void asplit_kernel(
    const float* __restrict__ X, __nv_bfloat16* __restrict__ Y, int Kd)
{
    int r = blockIdx.y;
    int k = blockIdx.x * 256 + threadIdx.x;
    float x = X[(size_t)r * Kd + k];
    __nv_bfloat16 hi = __float2bfloat16(x);
    __nv_bfloat16 lo = __float2bfloat16(x - __bfloat162float(hi));
    size_t base = (size_t)r * 3 * Kd;
    Y[base + k] = hi;
    Y[base + Kd + k] = lo;
    Y[base + 2 * Kd + k] = hi;
}

__global__ __launch_bounds__(256) void wsplit_kernel(
    const float* __restrict__ W, __nv_bfloat16* __restrict__ Yt,
    int Kd, int cph, long long hstr, int krs)
{
    __shared__ float t[32][33];
    int k0 = blockIdx.y * 32, j0 = blockIdx.x * 32;
    int tx = threadIdx.x & 31, ty8 = threadIdx.x >> 5;
#pragma unroll
    for (int i = 0; i < 4; i++) {
        int kl = ty8 + i * 8;
        int j = j0 + tx;
        t[kl][tx] = W[(size_t)(j / cph) * hstr + (size_t)(k0 + kl) * krs + (j % cph)];
    }
    __syncthreads();
#pragma unroll
    for (int i = 0; i < 4; i++) {
        int j = j0 + ty8 + i * 8;
        int k = k0 + tx;
        float x = t[tx][ty8 + i * 8];
        __nv_bfloat16 hi = __float2bfloat16(x);
        __nv_bfloat16 lo = __float2bfloat16(x - __bfloat162float(hi));
        size_t base = (size_t)j * 3 * Kd;
        Yt[base + k] = hi;
        Yt[base + Kd + k] = hi;
        Yt[base + 2 * Kd + k] = lo;
    }
}

__global__ __launch_bounds__(256) void f2h_kernel(
    const float* __restrict__ X, __half* __restrict__ Y)
{
    size_t idx = ((size_t)blockIdx.x * 256 + threadIdx.x) * 4;
    float4 v = *(const float4*)(X + idx);
    __half2 h0 = __floats2half2_rn(v.x, v.y);
    __half2 h1 = __floats2half2_rn(v.z, v.w);
    *(uint2*)(Y + idx) = make_uint2(*(uint32_t*)&h0, *(uint32_t*)&h1);
}

// ---------------- HMMA bf16 GEMM (unchanged from R4) ----------------
#define GSTAGES 3
#define STG_BYTES 16384
#define GEMM_SMEM (GSTAGES * STG_BYTES)

__global__ void __launch_bounds__(256, 2) gemm_hmma(
    const __nv_bfloat16* __restrict__ A, const __nv_bfloat16* __restrict__ Bw,
    float* __restrict__ C, int Kp, int Mpb, long long outBS, int rowOff, int ldc)
{
    extern __shared__ char smraw[];
    const uint32_t sb = smem_u32(smraw);
    const int tid = threadIdx.x;
    const int lane = tid & 31, wid = tid >> 5;
    const int wm = wid & 3, wn = wid >> 2;
    const int m0 = blockIdx.y * 128, n0 = blockIdx.x * 128;
    const int nIter = Kp >> 5;

    const int crow = tid >> 1;
    const int ck = (tid & 1) << 4;
    const __nv_bfloat16* ga = A + (size_t)(m0 + crow) * Kp + ck;
    const __nv_bfloat16* gb = Bw + (size_t)(n0 + crow) * Kp + ck;
    const uint32_t sw0 = sw_off(crow, ck * 2);
    const uint32_t sw1 = sw_off(crow, ck * 2 + 16);

    const int r8 = lane & 7, sel = lane >> 3;
    uint32_t aoff[2][2], boff[4][2];
#pragma unroll
    for (int mf = 0; mf < 2; mf++)
#pragma unroll
        for (int ks = 0; ks < 2; ks++) {
            int row = wm * 32 + mf * 16 + r8 + ((sel & 1) << 3);
            int kb = ks * 32 + ((sel >> 1) << 4);
            aoff[mf][ks] = sw_off(row, kb);
        }
#pragma unroll
    for (int np = 0; np < 4; np++)
#pragma unroll
        for (int ks = 0; ks < 2; ks++) {
            int row = wn * 64 + np * 16 + r8 + ((sel >> 1) << 3);
            int kb = ks * 32 + ((sel & 1) << 4);
            boff[np][ks] = 8192u + sw_off(row, kb);
        }

    float acc[2][8][4];
#pragma unroll
    for (int mf = 0; mf < 2; mf++)
#pragma unroll
        for (int nf = 0; nf < 8; nf++)
#pragma unroll
            for (int q = 0; q < 4; q++) acc[mf][nf][q] = 0.f;

#pragma unroll
    for (int s = 0; s < 2; s++) {
        uint32_t base = sb + (uint32_t)s * STG_BYTES;
        const __nv_bfloat16* pa = ga + s * 32;
        const __nv_bfloat16* pb = gb + s * 32;
        CP16(base + sw0, pa);
        CP16(base + sw1, pa + 8);
        CP16(base + 8192u + sw0, pb);
        CP16(base + 8192u + sw1, pb + 8);
        CP_COMMIT;
    }

    for (int it = 0; it < nIter; it++) {
        if (it + 2 < nIter) {
            int s = (it + 2) % GSTAGES;
            uint32_t base = sb + (uint32_t)s * STG_BYTES;
            const __nv_bfloat16* pa = ga + (size_t)(it + 2) * 32;
            const __nv_bfloat16* pb = gb + (size_t)(it + 2) * 32;
            CP16(base + sw0, pa);
            CP16(base + sw1, pa + 8);
            CP16(base + 8192u + sw0, pb);
            CP16(base + 8192u + sw1, pb + 8);
        }
        CP_COMMIT;
        CP_WAIT2;
        __syncthreads();

        uint32_t sbase = sb + (uint32_t)(it % GSTAGES) * STG_BYTES;
#pragma unroll
        for (int ks = 0; ks < 2; ks++) {
            uint32_t af[2][4];
#pragma unroll
            for (int mf = 0; mf < 2; mf++)
                LDSM4(af[mf][0], af[mf][1], af[mf][2], af[mf][3], sbase + aoff[mf][ks]);
            uint32_t bf[4][4];
#pragma unroll
            for (int np = 0; np < 4; np++)
                LDSM4(bf[np][0], bf[np][1], bf[np][2], bf[np][3], sbase + boff[np][ks]);
#pragma unroll
            for (int mf = 0; mf < 2; mf++)
#pragma unroll
                for (int np = 0; np < 4; np++) {
                    MMA16816(acc[mf][np * 2 + 0], af[mf], bf[np][0], bf[np][1]);
                    MMA16816(acc[mf][np * 2 + 1], af[mf], bf[np][2], bf[np][3]);
                }
        }
        __syncthreads();
    }

#pragma unroll
    for (int mf = 0; mf < 2; mf++)
#pragma unroll
        for (int rh = 0; rh < 2; rh++) {
            int gr = m0 + wm * 32 + mf * 16 + (lane >> 2) + rh * 8;
            int bi = gr / Mpb;
            int rr = gr - bi * Mpb;
            float* rowp = C + (size_t)bi * outBS + (size_t)(rr + rowOff) * ldc
                        + n0 + wn * 64 + (lane & 3) * 2;
#pragma unroll
            for (int nf = 0; nf < 8; nf++) {
                float2 v = make_float2(acc[mf][nf][rh * 2 + 0], acc[mf][nf][rh * 2 + 1]);
                *(float2*)(rowp + nf * 8) = v;
            }
        }
}

// ---------------- RMS-norm (+RoPE) -> fp16 ----------------
__global__ __launch_bounds__(256) void rms_rope_h_kernel(
    const float* __restrict__ buf, __half* __restrict__ outh,
    const float* __restrict__ scale,
    int heads, int rowsPerBatch, int bufRPB, int rowStart, int doRope, float outScale)
{
    __shared__ float sh[256];
    __shared__ float ws[8];
    int idx = blockIdx.x;
    int head = idx % heads;
    int tmp = idx / heads;
    int t = tmp % rowsPerBatch;
    int b = tmp / rowsPerBatch;
    size_t off = ((size_t)((size_t)b * bufRPB + rowStart + t) * heads + head) * H_DIM;
    int h = threadIdx.x;
    float x = buf[off + h];
    float ss = x * x;
#pragma unroll
    for (int o = 16; o > 0; o >>= 1) ss += __shfl_xor_sync(0xffffffffu, ss, o);
    if ((h & 31) == 0) ws[h >> 5] = ss;
    __syncthreads();
    float tot = 0.f;
#pragma unroll
    for (int w = 0; w < 8; w++) tot += ws[w];
    float y = x * rsqrtf(tot * (1.f / 256.f) + 1e-6f) * (1.f + scale[h]);
    if (doRope) {
        sh[h] = y;
        __syncthreads();
        int i = h & 127;
        float ang = (float)t * exp2f(-(float)i * 0.10381025296522988f);
        float sn, cs;
        sincosf(ang, &sn, &cs);
        if (h < 128) y = sh[h] * cs - sh[h + 128] * sn;
        else         y = sh[h] * cs + sh[h - 128] * sn;
    }
    outh[off + h] = __float2half(y * outScale);
}

// ---------------- flash attention fp16 HMMA ----------------
// smem: Qs@0 (32K), stage s: Ks@32768+s*65536, Vs@65536+s*65536; Ps@163840 (8K); red@172032
#define FH_K 32768u
#define FH_V 65536u
#define FH_STRIDE 65536u
#define FH_P 163840u
#define FH_RED 172032
#define FH_SMEM (172032 + 1536)

__global__ void __launch_bounds__(256, 1) flash_hmma(
    const __half* __restrict__ Qh, const __half* __restrict__ Kh,
    const __half* __restrict__ Vh, float* __restrict__ Oa)
{
    extern __shared__ char smraw[];
    const uint32_t sb = smem_u32(smraw);
    float* red = (float*)(smraw + FH_RED);   // [0:64) m, [64:128) l, [128:256) rmax, [256:384) rsum
    const int tid = threadIdx.x, lane = tid & 31, w = tid >> 5;
    const int wr = w & 3, wc = w >> 2;       // wc = kv-half (S) / H-half (PV)
    const int qt = blockIdx.x, n = blockIdx.y, b = blockIdx.z;
    const int kh = n >> 1, qbase = qt << 6;

    // Q load (group 0)
    const char* qg = (const char*)(Qh + ((size_t)(b * T_LEN + qbase) * N_HEADS + n) * H_DIM);
#pragma unroll
    for (int p = 0; p < 8; p++) {
        int idx = tid + p * 256;
        int r = idx >> 5, c = idx & 31;
        CP16(sb + fsw(r, c * 16), qg + (size_t)r * (N_HEADS * H_DIM * 2) + c * 16);
    }
    if (tid < 64) { red[tid] = -INFINITY; red[64 + tid] = 0.f; }
    CP_COMMIT;

    const char* kg = (const char*)(Kh + ((size_t)b * S_LEN * K_HEADS + kh) * H_DIM);
    const char* vg = (const char*)(Vh + ((size_t)b * S_LEN * K_HEADS + kh) * H_DIM);
    const int kvstride = K_HEADS * H_DIM * 2;

    const int nSelf = qt + 1;
    const int nT = nSelf + (E_LEN >> 6);

    // tile 0 load (group 1)
#pragma unroll
    for (int p = 0; p < 8; p++) {
        int idx = tid + p * 256;
        int r = idx >> 5, c = idx & 31;
        uint32_t sw = fsw(r, c * 16);
        CP16(sb + FH_K + sw, kg + (size_t)r * kvstride + c * 16);
        CP16(sb + FH_V + sw, vg + (size_t)r * kvstride + c * 16);
    }
    CP_COMMIT;

    float oacc[16][4];
#pragma unroll
    for (int nf = 0; nf < 16; nf++)
#pragma unroll
        for (int q = 0; q < 4; q++) oacc[nf][q] = 0.f;

    const int r8 = lane & 7, sel = lane >> 3;
    // A (Q / Ps): rows
    const int rowA = wr * 16 + r8 + ((sel & 1) << 3);
    const int dselA = sel >> 1;           // +16B within 32B kstep
    // B (K): rows
    const int rowB0 = wc * 32 + r8 + ((sel >> 1) << 3);
    const int dselB = sel & 1;
    const int r1 = wr * 16 + (lane >> 2), r2 = r1 + 8;

    for (int t = 0; t < nT; t++) {
        // prefetch t+1 / wait for t
        if (t + 1 < nT) {
            int s0n = (t + 1 < nSelf) ? ((t + 1) << 6) : (T_LEN + ((t + 1 - nSelf) << 6));
            uint32_t kb = sb + FH_K + (uint32_t)((t + 1) & 1) * FH_STRIDE;
            uint32_t vb = sb + FH_V + (uint32_t)((t + 1) & 1) * FH_STRIDE;
#pragma unroll
            for (int p = 0; p < 8; p++) {
                int idx = tid + p * 256;
                int r = idx >> 5, c = idx & 31;
                uint32_t sw = fsw(r, c * 16);
                CP16(kb + sw, kg + (size_t)(s0n + r) * kvstride + c * 16);
                CP16(vb + sw, vg + (size_t)(s0n + r) * kvstride + c * 16);
            }
            CP_COMMIT;
            CP_WAIT1;
        } else {
            CP_WAIT0;
        }
        __syncthreads();

        const int s0 = (t < nSelf) ? (t << 6) : (T_LEN + ((t - nSelf) << 6));
        const bool diag = (t == qt);
        const uint32_t sK = sb + FH_K + (uint32_t)(t & 1) * FH_STRIDE;
        const uint32_t sV = sb + FH_V + (uint32_t)(t & 1) * FH_STRIDE;
        const uint32_t aBase = sb + (uint32_t)rowA * 512u;
        const int rowAx = rowA & 7;

        // ---- S = Q K^T ----
        float sacc[4][4];
#pragma unroll
        for (int nf = 0; nf < 4; nf++)
#pragma unroll
            for (int q = 0; q < 4; q++) sacc[nf][q] = 0.f;
#pragma unroll 4
        for (int ks = 0; ks < 16; ks++) {
            uint32_t a[4];
            LDSM4(a[0], a[1], a[2], a[3], aBase + (uint32_t)((((ks << 1) + dselA) ^ rowAx) << 4));
#pragma unroll
            for (int nf2 = 0; nf2 < 2; nf2++) {
                int rowB = rowB0 + nf2 * 16;
                uint32_t bb[4];
                LDSM4(bb[0], bb[1], bb[2], bb[3],
                      sK + (uint32_t)rowB * 512u + (uint32_t)((((ks << 1) + dselB) ^ (rowB & 7)) << 4));
                MMAH16816(sacc[nf2 * 2 + 0], a, bb[0], bb[1]);
                MMAH16816(sacc[nf2 * 2 + 1], a, bb[2], bb[3]);
            }
        }

        // ---- softcap + mask + row max ----
        float mx1 = -INFINITY, mx2 = -INFINITY;
#pragma unroll
        for (int nf = 0; nf < 4; nf++)
#pragma unroll
            for (int e = 0; e < 4; e++) {
                float s = sacc[nf][e];
                float cpv = 50.f - __fdividef(100.f, __expf(0.04f * s) + 1.f);
                if (diag) {
                    int col = s0 + wc * 32 + nf * 8 + ((lane & 3) << 1) + (e & 1);
                    int row = qbase + ((e < 2) ? r1 : r2);
                    if (col > row) cpv = -INFINITY;
                }
                sacc[nf][e] = cpv;
                if (e < 2) mx1 = fmaxf(mx1, cpv); else mx2 = fmaxf(mx2, cpv);
            }
        mx1 = fmaxf(mx1, __shfl_xor_sync(0xffffffffu, mx1, 1));
        mx1 = fmaxf(mx1, __shfl_xor_sync(0xffffffffu, mx1, 2));
        mx2 = fmaxf(mx2, __shfl_xor_sync(0xffffffffu, mx2, 1));
        mx2 = fmaxf(mx2, __shfl_xor_sync(0xffffffffu, mx2, 2));
        if ((lane & 3) == 0) { red[128 + wc * 64 + r1] = mx1; red[128 + wc * 64 + r2] = mx2; }
        __syncthreads();

        float m1o = red[r1], m2o = red[r2];
        float mn1 = fmaxf(m1o, fmaxf(red[128 + r1], red[128 + 64 + r1]));
        float mn2 = fmaxf(m2o, fmaxf(red[128 + r2], red[128 + 64 + r2]));
        float corr1 = __expf(m1o - mn1), corr2 = __expf(m2o - mn2);

        // ---- P = exp(s - m), write Ps (fp16), partial sums ----
        float sum1 = 0.f, sum2 = 0.f;
        const uint32_t pwb = sb + FH_P;
#pragma unroll
        for (int nf = 0; nf < 4; nf++) {
            float p0 = __expf(sacc[nf][0] - mn1);
            float p1 = __expf(sacc[nf][1] - mn1);
            float p2 = __expf(sacc[nf][2] - mn2);
            float p3 = __expf(sacc[nf][3] - mn2);
            sum1 += p0 + p1; sum2 += p2 + p3;
            __half2 hA = __floats2half2_rn(p0, p1);
            __half2 hB = __floats2half2_rn(p2, p3);
            int chunk = wc * 4 + nf;
            uint32_t a1 = pwb + (uint32_t)r1 * 128u + (uint32_t)((chunk ^ (r1 & 7)) << 4) + ((lane & 3) << 2);
            uint32_t a2 = pwb + (uint32_t)r2 * 128u + (uint32_t)((chunk ^ (r2 & 7)) << 4) + ((lane & 3) << 2);
            asm volatile("st.shared.b32 [%0], %1;" :: "r"(a1), "r"(*(uint32_t*)&hA) : "memory");
            asm volatile("st.shared.b32 [%0], %1;" :: "r"(a2), "r"(*(uint32_t*)&hB) : "memory");
        }
        sum1 += __shfl_xor_sync(0xffffffffu, sum1, 1);
        sum1 += __shfl_xor_sync(0xffffffffu, sum1, 2);
        sum2 += __shfl_xor_sync(0xffffffffu, sum2, 1);
        sum2 += __shfl_xor_sync(0xffffffffu, sum2, 2);
        if ((lane & 3) == 0) { red[256 + wc * 64 + r1] = sum1; red[256 + wc * 64 + r2] = sum2; }

        // rescale O
#pragma unroll
        for (int nf = 0; nf < 16; nf++) {
            oacc[nf][0] *= corr1; oacc[nf][1] *= corr1;
            oacc[nf][2] *= corr2; oacc[nf][3] *= corr2;
        }
        __syncthreads();

        if (wc == 0 && (lane & 3) == 0) {
            red[64 + r1] = red[64 + r1] * corr1 + red[256 + r1] + red[256 + 64 + r1];
            red[64 + r2] = red[64 + r2] * corr2 + red[256 + r2] + red[256 + 64 + r2];
            red[r1] = mn1; red[r2] = mn2;
        }

        // ---- O += P V ----
        const uint32_t paBase = pwb + (uint32_t)rowA * 128u;
        const int rowAp = rowA & 7;
#pragma unroll
        for (int ks = 0; ks < 4; ks++) {
            uint32_t a[4];
            LDSM4(a[0], a[1], a[2], a[3], paBase + (uint32_t)((((ks << 1) + dselA) ^ rowAp) << 4));
#pragma unroll
            for (int nf2 = 0; nf2 < 8; nf2++) {
                int rowV = ks * 16 + r8 + ((sel & 1) << 3);
                int chunk = wc * 16 + nf2 * 2 + (sel >> 1);
                uint32_t bb[4];
                LDSM4T(bb[0], bb[1], bb[2], bb[3],
                       sV + (uint32_t)rowV * 512u + (uint32_t)((chunk ^ (rowV & 7)) << 4));
                MMAH16816(oacc[nf2 * 2 + 0], a, bb[0], bb[1]);
                MMAH16816(oacc[nf2 * 2 + 1], a, bb[2], bb[3]);
            }
        }
        __syncthreads();
    }

    // ---- epilogue ----
    float inv1 = 1.f / red[64 + r1];
    float inv2 = 1.f / red[64 + r2];
    int t1 = qbase + r1, t2 = qbase + r2;
    float* o1 = Oa + (((size_t)(b * T_LEN + t1)) * N_HEADS + n) * H_DIM + wc * 128 + ((lane & 3) << 1);
    float* o2 = Oa + (((size_t)(b * T_LEN + t2)) * N_HEADS + n) * H_DIM + wc * 128 + ((lane & 3) << 1);
#pragma unroll
    for (int nf = 0; nf < 16; nf++) {
        *(float2*)(o1 + nf * 8) = make_float2(oacc[nf][0] * inv1, oacc[nf][1] * inv1);
        *(float2*)(o2 + nf * 8) = make_float2(oacc[nf][2] * inv2, oacc[nf][3] * inv2);
    }
}

// ---------------- launch ----------------
extern "C" void kernel_launch(void* const* d_in, const int* in_sizes, int n_in,
                              void* d_out, int out_size)
{
    (void)in_sizes; (void)n_in; (void)out_size;
    const float* hs  = (const float*)d_in[0];
    const float* enc = (const float*)d_in[1];
    const float* qw  = (const float*)d_in[4];
    const float* kw  = (const float*)d_in[5];
    const float* vw  = (const float*)d_in[6];
    const float* ow  = (const float*)d_in[7];
    const float* qsc = (const float*)d_in[8];
    const float* ksc = (const float*)d_in[9];
    float* out = (float*)d_out;

    float *qb, *kb, *vb, *ab;
    cudaGetSymbolAddress((void**)&qb, g_q);
    cudaGetSymbolAddress((void**)&kb, g_k);
    cudaGetSymbolAddress((void**)&vb, g_v);
    cudaGetSymbolAddress((void**)&ab, g_attn);
    __half *q16, *k16, *v16;
    cudaGetSymbolAddress((void**)&q16, g_q16);
    cudaGetSymbolAddress((void**)&k16, g_k16);
    cudaGetSymbolAddress((void**)&v16, g_v16);
    __nv_bfloat16 *hs3, *enc3, *qw3, *kw3, *vw3, *ow3, *at3;
    cudaGetSymbolAddress((void**)&hs3, g_hs3);
    cudaGetSymbolAddress((void**)&enc3, g_enc3);
    cudaGetSymbolAddress((void**)&qw3, g_qw3);
    cudaGetSymbolAddress((void**)&kw3, g_kw3);
    cudaGetSymbolAddress((void**)&vw3, g_vw3);
    cudaGetSymbolAddress((void**)&ow3, g_ow3);
    cudaGetSymbolAddress((void**)&at3, g_at3);

    static int cfg = 0;
    if (!cfg) {
        cudaFuncSetAttribute(gemm_hmma, cudaFuncAttributeMaxDynamicSharedMemorySize, GEMM_SMEM);
        cudaFuncSetAttribute(flash_hmma, cudaFuncAttributeMaxDynamicSharedMemorySize, FH_SMEM);
        cfg = 1;
    }

    // splits
    asplit_kernel<<<dim3(D_DIM / 256, 4096), 256>>>(hs, hs3, D_DIM);
    asplit_kernel<<<dim3(D_DIM / 256, 4096), 256>>>(enc, enc3, D_DIM);
    wsplit_kernel<<<dim3(4096 / 32, D_DIM / 32), 256>>>(qw, qw3, D_DIM, H_DIM, (long long)D_DIM * H_DIM, H_DIM);
    wsplit_kernel<<<dim3(2048 / 32, D_DIM / 32), 256>>>(kw, kw3, D_DIM, H_DIM, (long long)D_DIM * H_DIM, H_DIM);
    wsplit_kernel<<<dim3(2048 / 32, D_DIM / 32), 256>>>(vw, vw3, D_DIM, H_DIM, (long long)D_DIM * H_DIM, H_DIM);
    wsplit_kernel<<<dim3(2048 / 32, 4096 / 32), 256>>>(ow, ow3, 4096, D_DIM, 0LL, D_DIM);

    const long long kvBS = (long long)S_LEN * K_HEADS * H_DIM;
    gemm_hmma<<<dim3(32, 32), 256, GEMM_SMEM>>>(hs3, qw3, qb, 6144, 4096, 0LL, 0, 4096);
    gemm_hmma<<<dim3(16, 32), 256, GEMM_SMEM>>>(hs3, kw3, kb, 6144, T_LEN, kvBS, 0, 2048);
    gemm_hmma<<<dim3(16, 32), 256, GEMM_SMEM>>>(hs3, vw3, vb, 6144, T_LEN, kvBS, 0, 2048);
    gemm_hmma<<<dim3(16, 32), 256, GEMM_SMEM>>>(enc3, kw3, kb, 6144, E_LEN, kvBS, T_LEN, 2048);
    gemm_hmma<<<dim3(16, 32), 256, GEMM_SMEM>>>(enc3, vw3, vb, 6144, E_LEN, kvBS, T_LEN, 2048);

    // rms(+rope) -> fp16 operands
    rms_rope_h_kernel<<<B_SZ * T_LEN * N_HEADS, 256>>>(qb, q16, qsc, N_HEADS, T_LEN, T_LEN, 0, 1, 0.0625f);
    rms_rope_h_kernel<<<B_SZ * T_LEN * K_HEADS, 256>>>(kb, k16, ksc, K_HEADS, T_LEN, S_LEN, 0, 1, 1.0f);
    rms_rope_h_kernel<<<B_SZ * E_LEN * K_HEADS, 256>>>(kb, k16, ksc, K_HEADS, E_LEN, S_LEN, T_LEN, 0, 1.0f);
    f2h_kernel<<<(B_SZ * S_LEN * K_HEADS * H_DIM) / 1024, 256>>>(vb, v16);

    flash_hmma<<<dim3(T_LEN / 64, N_HEADS, B_SZ), 256, FH_SMEM>>>(q16, k16, v16, ab);

    // O = attn @ ow
    asplit_kernel<<<dim3(4096 / 256, 4096), 256>>>(ab, at3, 4096);
    gemm_hmma<<<dim3(16, 32), 256, GEMM_SMEM>>>(at3, ow3, out, 12288, 4096, 0LL, 0, 2048);
}

// round 6
// speedup vs baseline: 3.6536x; 1.3575x over previous
#include <cuda_runtime.h>
#include <cuda_fp16.h>
#include <stdint.h>
#include <math.h>

#define B_SZ 4
#define T_LEN 1024
#define E_LEN 1024
#define S_LEN 2048
#define D_DIM 2048
#define H_DIM 256
#define N_HEADS 16
#define K_HEADS 8

// fp32 scratch
__device__ float g_q[(size_t)B_SZ * T_LEN * N_HEADS * H_DIM];
__device__ float g_k[(size_t)B_SZ * S_LEN * K_HEADS * H_DIM];
__device__ float g_v[(size_t)B_SZ * S_LEN * K_HEADS * H_DIM];
__device__ float g_attn[(size_t)B_SZ * T_LEN * N_HEADS * H_DIM];
// fp16 attention operands
__device__ __half g_q16[(size_t)B_SZ * T_LEN * N_HEADS * H_DIM];
__device__ __half g_k16[(size_t)B_SZ * S_LEN * K_HEADS * H_DIM];
__device__ __half g_v16[(size_t)B_SZ * S_LEN * K_HEADS * H_DIM];
// fp16 split buffers (K-concat: act = [hi|lo], weightT = [hi|hi])
__device__ __half g_hs2 [(size_t)4096 * 4096];
__device__ __half g_enc2[(size_t)4096 * 4096];
__device__ __half g_qw2 [(size_t)4096 * 4096];
__device__ __half g_kw2 [(size_t)2048 * 4096];
__device__ __half g_vw2 [(size_t)2048 * 4096];
__device__ __half g_ow2 [(size_t)2048 * 8192];
__device__ __half g_at2 [(size_t)4096 * 8192];

// ---------------- helpers ----------------
__device__ __forceinline__ uint32_t smem_u32(const void* p) {
    uint32_t a;
    asm("{ .reg .u64 t; cvta.to.shared.u64 t, %1; cvt.u32.u64 %0, t; }" : "=r"(a) : "l"(p));
    return a;
}
#define CP16(dst, src) \
    asm volatile("cp.async.cg.shared.global [%0], [%1], 16;" :: "r"(dst), "l"(src) : "memory")
#define CP_COMMIT asm volatile("cp.async.commit_group;" ::: "memory")
#define CP_WAIT2  asm volatile("cp.async.wait_group 2;" ::: "memory")
#define CP_WAIT1  asm volatile("cp.async.wait_group 1;" ::: "memory")
#define CP_WAIT0  asm volatile("cp.async.wait_group 0;" ::: "memory")
#define LDSM4(r0, r1, r2, r3, addr) \
    asm volatile("ldmatrix.sync.aligned.m8n8.x4.shared.b16 {%0,%1,%2,%3}, [%4];" \
        : "=r"(r0), "=r"(r1), "=r"(r2), "=r"(r3) : "r"(addr))
#define LDSM4T(r0, r1, r2, r3, addr) \
    asm volatile("ldmatrix.sync.aligned.m8n8.x4.trans.shared.b16 {%0,%1,%2,%3}, [%4];" \
        : "=r"(r0), "=r"(r1), "=r"(r2), "=r"(r3) : "r"(addr))
#define MMAH16816(d, a, b0, b1) \
    asm volatile("mma.sync.aligned.m16n8k16.row.col.f32.f16.f16.f32 " \
        "{%0,%1,%2,%3}, {%4,%5,%6,%7}, {%8,%9}, {%0,%1,%2,%3};" \
        : "+f"((d)[0]), "+f"((d)[1]), "+f"((d)[2]), "+f"((d)[3]) \
        : "r"((a)[0]), "r"((a)[1]), "r"((a)[2]), "r"((a)[3]), "r"(b0), "r"(b1))

// gemm smem tile swizzle: 128 rows x 64B. 128B line = 2 rows, 8 chunks of 16B.
__device__ __forceinline__ uint32_t sw_off(int row, int kbyte) {
    int line = row >> 1;
    int ch = (((row & 1) << 2) + (kbyte >> 4)) ^ (line & 7);
    return (uint32_t)(line * 128 + ch * 16 + (kbyte & 15));
}
// flash smem swizzle: 512B rows (256 halfs), 32 chunks of 16B
__device__ __forceinline__ uint32_t fsw(int row, int kbyte) {
    return (uint32_t)(row * 512 + ((((kbyte >> 4) ^ (row & 7))) << 4) + (kbyte & 15));
}

// ---------------- split kernels (fp16x2) ----------------
__global__ __launch_bounds__(256) void asplit_kernel(
    const float* __restrict__ X, __half* __restrict__ Y, int Kd)
{
    int r = blockIdx.y;
    int k = blockIdx.x * 256 + threadIdx.x;
    float x = X[(size_t)r * Kd + k];
    __half hi = __float2half(x);
    __half lo = __float2half(x - __half2float(hi));
    size_t base = (size_t)r * 2 * Kd;
    Y[base + k] = hi;
    Y[base + Kd + k] = lo;
}

// W(k,j) = W[(j/cph)*hstr + k*krs + j%cph]; out Yt[j, 2K] = [hi|hi]
__global__ __launch_bounds__(256) void wsplit_kernel(
    const float* __restrict__ W, __half* __restrict__ Yt,
    int Kd, int cph, long long hstr, int krs)
{
    __shared__ float t[32][33];
    int k0 = blockIdx.y * 32, j0 = blockIdx.x * 32;
    int tx = threadIdx.x & 31, ty8 = threadIdx.x >> 5;
#pragma unroll
    for (int i = 0; i < 4; i++) {
        int kl = ty8 + i * 8;
        int j = j0 + tx;
        t[kl][tx] = W[(size_t)(j / cph) * hstr + (size_t)(k0 + kl) * krs + (j % cph)];
    }
    __syncthreads();
#pragma unroll
    for (int i = 0; i < 4; i++) {
        int j = j0 + ty8 + i * 8;
        int k = k0 + tx;
        __half hi = __float2half(t[tx][ty8 + i * 8]);
        size_t base = (size_t)j * 2 * Kd;
        Yt[base + k] = hi;
        Yt[base + Kd + k] = hi;
    }
}

__global__ __launch_bounds__(256) void f2h_kernel(
    const float* __restrict__ X, __half* __restrict__ Y)
{
    size_t idx = ((size_t)blockIdx.x * 256 + threadIdx.x) * 4;
    float4 v = *(const float4*)(X + idx);
    __half2 h0 = __floats2half2_rn(v.x, v.y);
    __half2 h1 = __floats2half2_rn(v.z, v.w);
    *(uint2*)(Y + idx) = make_uint2(*(uint32_t*)&h0, *(uint32_t*)&h1);
}

// ---------------- HMMA fp16 GEMM (structure proven in R4/R5) ----------------
#define GSTAGES 3
#define STG_BYTES 16384
#define GEMM_SMEM (GSTAGES * STG_BYTES)

__global__ void __launch_bounds__(256, 2) gemm_hmma(
    const __half* __restrict__ A, const __half* __restrict__ Bw,
    float* __restrict__ C, int Kp, int Mpb, long long outBS, int rowOff, int ldc)
{
    extern __shared__ char smraw[];
    const uint32_t sb = smem_u32(smraw);
    const int tid = threadIdx.x;
    const int lane = tid & 31, wid = tid >> 5;
    const int wm = wid & 3, wn = wid >> 2;
    const int m0 = blockIdx.y * 128, n0 = blockIdx.x * 128;
    const int nIter = Kp >> 5;

    const int crow = tid >> 1;
    const int ck = (tid & 1) << 4;
    const __half* ga = A + (size_t)(m0 + crow) * Kp + ck;
    const __half* gb = Bw + (size_t)(n0 + crow) * Kp + ck;
    const uint32_t sw0 = sw_off(crow, ck * 2);
    const uint32_t sw1 = sw_off(crow, ck * 2 + 16);

    const int r8 = lane & 7, sel = lane >> 3;
    uint32_t aoff[2][2], boff[4][2];
#pragma unroll
    for (int mf = 0; mf < 2; mf++)
#pragma unroll
        for (int ks = 0; ks < 2; ks++) {
            int row = wm * 32 + mf * 16 + r8 + ((sel & 1) << 3);
            int kb = ks * 32 + ((sel >> 1) << 4);
            aoff[mf][ks] = sw_off(row, kb);
        }
#pragma unroll
    for (int np = 0; np < 4; np++)
#pragma unroll
        for (int ks = 0; ks < 2; ks++) {
            int row = wn * 64 + np * 16 + r8 + ((sel >> 1) << 3);
            int kb = ks * 32 + ((sel & 1) << 4);
            boff[np][ks] = 8192u + sw_off(row, kb);
        }

    float acc[2][8][4];
#pragma unroll
    for (int mf = 0; mf < 2; mf++)
#pragma unroll
        for (int nf = 0; nf < 8; nf++)
#pragma unroll
            for (int q = 0; q < 4; q++) acc[mf][nf][q] = 0.f;

#pragma unroll
    for (int s = 0; s < 2; s++) {
        uint32_t base = sb + (uint32_t)s * STG_BYTES;
        const __half* pa = ga + s * 32;
        const __half* pb = gb + s * 32;
        CP16(base + sw0, pa);
        CP16(base + sw1, pa + 8);
        CP16(base + 8192u + sw0, pb);
        CP16(base + 8192u + sw1, pb + 8);
        CP_COMMIT;
    }

    for (int it = 0; it < nIter; it++) {
        if (it + 2 < nIter) {
            int s = (it + 2) % GSTAGES;
            uint32_t base = sb + (uint32_t)s * STG_BYTES;
            const __half* pa = ga + (size_t)(it + 2) * 32;
            const __half* pb = gb + (size_t)(it + 2) * 32;
            CP16(base + sw0, pa);
            CP16(base + sw1, pa + 8);
            CP16(base + 8192u + sw0, pb);
            CP16(base + 8192u + sw1, pb + 8);
        }
        CP_COMMIT;
        CP_WAIT2;
        __syncthreads();

        uint32_t sbase = sb + (uint32_t)(it % GSTAGES) * STG_BYTES;
#pragma unroll
        for (int ks = 0; ks < 2; ks++) {
            uint32_t af[2][4];
#pragma unroll
            for (int mf = 0; mf < 2; mf++)
                LDSM4(af[mf][0], af[mf][1], af[mf][2], af[mf][3], sbase + aoff[mf][ks]);
            uint32_t bf[4][4];
#pragma unroll
            for (int np = 0; np < 4; np++)
                LDSM4(bf[np][0], bf[np][1], bf[np][2], bf[np][3], sbase + boff[np][ks]);
#pragma unroll
            for (int mf = 0; mf < 2; mf++)
#pragma unroll
                for (int np = 0; np < 4; np++) {
                    MMAH16816(acc[mf][np * 2 + 0], af[mf], bf[np][0], bf[np][1]);
                    MMAH16816(acc[mf][np * 2 + 1], af[mf], bf[np][2], bf[np][3]);
                }
        }
        __syncthreads();
    }

#pragma unroll
    for (int mf = 0; mf < 2; mf++)
#pragma unroll
        for (int rh = 0; rh < 2; rh++) {
            int gr = m0 + wm * 32 + mf * 16 + (lane >> 2) + rh * 8;
            int bi = gr / Mpb;
            int rr = gr - bi * Mpb;
            float* rowp = C + (size_t)bi * outBS + (size_t)(rr + rowOff) * ldc
                        + n0 + wn * 64 + (lane & 3) * 2;
#pragma unroll
            for (int nf = 0; nf < 8; nf++) {
                float2 v = make_float2(acc[mf][nf][rh * 2 + 0], acc[mf][nf][rh * 2 + 1]);
                *(float2*)(rowp + nf * 8) = v;
            }
        }
}

// ---------------- RMS-norm (+RoPE) -> fp16 ----------------
__global__ __launch_bounds__(256) void rms_rope_h_kernel(
    const float* __restrict__ buf, __half* __restrict__ outh,
    const float* __restrict__ scale,
    int heads, int rowsPerBatch, int bufRPB, int rowStart, int doRope, float outScale)
{
    __shared__ float sh[256];
    __shared__ float ws[8];
    int idx = blockIdx.x;
    int head = idx % heads;
    int tmp = idx / heads;
    int t = tmp % rowsPerBatch;
    int b = tmp / rowsPerBatch;
    size_t off = ((size_t)((size_t)b * bufRPB + rowStart + t) * heads + head) * H_DIM;
    int h = threadIdx.x;
    float x = buf[off + h];
    float ss = x * x;
#pragma unroll
    for (int o = 16; o > 0; o >>= 1) ss += __shfl_xor_sync(0xffffffffu, ss, o);
    if ((h & 31) == 0) ws[h >> 5] = ss;
    __syncthreads();
    float tot = 0.f;
#pragma unroll
    for (int w = 0; w < 8; w++) tot += ws[w];
    float y = x * rsqrtf(tot * (1.f / 256.f) + 1e-6f) * (1.f + scale[h]);
    if (doRope) {
        sh[h] = y;
        __syncthreads();
        int i = h & 127;
        float ang = (float)t * exp2f(-(float)i * 0.10381025296522988f);
        float sn, cs;
        sincosf(ang, &sn, &cs);
        if (h < 128) y = sh[h] * cs - sh[h + 128] * sn;
        else         y = sh[h] * cs + sh[h - 128] * sn;
    }
    outh[off + h] = __float2half(y * outScale);
}

// ---------------- flash attention fp16 HMMA (unchanged from R5) ----------------
#define FH_K 32768u
#define FH_V 65536u
#define FH_STRIDE 65536u
#define FH_P 163840u
#define FH_RED 172032
#define FH_SMEM (172032 + 1536)

__global__ void __launch_bounds__(256, 1) flash_hmma(
    const __half* __restrict__ Qh, const __half* __restrict__ Kh,
    const __half* __restrict__ Vh, float* __restrict__ Oa)
{
    extern __shared__ char smraw[];
    const uint32_t sb = smem_u32(smraw);
    float* red = (float*)(smraw + FH_RED);
    const int tid = threadIdx.x, lane = tid & 31, w = tid >> 5;
    const int wr = w & 3, wc = w >> 2;
    const int qt = blockIdx.x, n = blockIdx.y, b = blockIdx.z;
    const int kh = n >> 1, qbase = qt << 6;

    const char* qg = (const char*)(Qh + ((size_t)(b * T_LEN + qbase) * N_HEADS + n) * H_DIM);
#pragma unroll
    for (int p = 0; p < 8; p++) {
        int idx = tid + p * 256;
        int r = idx >> 5, c = idx & 31;
        CP16(sb + fsw(r, c * 16), qg + (size_t)r * (N_HEADS * H_DIM * 2) + c * 16);
    }
    if (tid < 64) { red[tid] = -INFINITY; red[64 + tid] = 0.f; }
    CP_COMMIT;

    const char* kg = (const char*)(Kh + ((size_t)b * S_LEN * K_HEADS + kh) * H_DIM);
    const char* vg = (const char*)(Vh + ((size_t)b * S_LEN * K_HEADS + kh) * H_DIM);
    const int kvstride = K_HEADS * H_DIM * 2;

    const int nSelf = qt + 1;
    const int nT = nSelf + (E_LEN >> 6);

#pragma unroll
    for (int p = 0; p < 8; p++) {
        int idx = tid + p * 256;
        int r = idx >> 5, c = idx & 31;
        uint32_t sw = fsw(r, c * 16);
        CP16(sb + FH_K + sw, kg + (size_t)r * kvstride + c * 16);
        CP16(sb + FH_V + sw, vg + (size_t)r * kvstride + c * 16);
    }
    CP_COMMIT;

    float oacc[16][4];
#pragma unroll
    for (int nf = 0; nf < 16; nf++)
#pragma unroll
        for (int q = 0; q < 4; q++) oacc[nf][q] = 0.f;

    const int r8 = lane & 7, sel = lane >> 3;
    const int rowA = wr * 16 + r8 + ((sel & 1) << 3);
    const int dselA = sel >> 1;
    const int rowB0 = wc * 32 + r8 + ((sel >> 1) << 3);
    const int dselB = sel & 1;
    const int r1 = wr * 16 + (lane >> 2), r2 = r1 + 8;

    for (int t = 0; t < nT; t++) {
        if (t + 1 < nT) {
            int s0n = (t + 1 < nSelf) ? ((t + 1) << 6) : (T_LEN + ((t + 1 - nSelf) << 6));
            uint32_t kb = sb + FH_K + (uint32_t)((t + 1) & 1) * FH_STRIDE;
            uint32_t vb = sb + FH_V + (uint32_t)((t + 1) & 1) * FH_STRIDE;
#pragma unroll
            for (int p = 0; p < 8; p++) {
                int idx = tid + p * 256;
                int r = idx >> 5, c = idx & 31;
                uint32_t sw = fsw(r, c * 16);
                CP16(kb + sw, kg + (size_t)(s0n + r) * kvstride + c * 16);
                CP16(vb + sw, vg + (size_t)(s0n + r) * kvstride + c * 16);
            }
            CP_COMMIT;
            CP_WAIT1;
        } else {
            CP_WAIT0;
        }
        __syncthreads();

        const int s0 = (t < nSelf) ? (t << 6) : (T_LEN + ((t - nSelf) << 6));
        const bool diag = (t == qt);
        const uint32_t sK = sb + FH_K + (uint32_t)(t & 1) * FH_STRIDE;
        const uint32_t sV = sb + FH_V + (uint32_t)(t & 1) * FH_STRIDE;
        const uint32_t aBase = sb + (uint32_t)rowA * 512u;
        const int rowAx = rowA & 7;

        float sacc[4][4];
#pragma unroll
        for (int nf = 0; nf < 4; nf++)
#pragma unroll
            for (int q = 0; q < 4; q++) sacc[nf][q] = 0.f;
#pragma unroll 4
        for (int ks = 0; ks < 16; ks++) {
            uint32_t a[4];
            LDSM4(a[0], a[1], a[2], a[3], aBase + (uint32_t)((((ks << 1) + dselA) ^ rowAx) << 4));
#pragma unroll
            for (int nf2 = 0; nf2 < 2; nf2++) {
                int rowB = rowB0 + nf2 * 16;
                uint32_t bb[4];
                LDSM4(bb[0], bb[1], bb[2], bb[3],
                      sK + (uint32_t)rowB * 512u + (uint32_t)((((ks << 1) + dselB) ^ (rowB & 7)) << 4));
                MMAH16816(sacc[nf2 * 2 + 0], a, bb[0], bb[1]);
                MMAH16816(sacc[nf2 * 2 + 1], a, bb[2], bb[3]);
            }
        }

        float mx1 = -INFINITY, mx2 = -INFINITY;
#pragma unroll
        for (int nf = 0; nf < 4; nf++)
#pragma unroll
            for (int e = 0; e < 4; e++) {
                float s = sacc[nf][e];
                float cpv = 50.f - __fdividef(100.f, __expf(0.04f * s) + 1.f);
                if (diag) {
                    int col = s0 + wc * 32 + nf * 8 + ((lane & 3) << 1) + (e & 1);
                    int row = qbase + ((e < 2) ? r1 : r2);
                    if (col > row) cpv = -INFINITY;
                }
                sacc[nf][e] = cpv;
                if (e < 2) mx1 = fmaxf(mx1, cpv); else mx2 = fmaxf(mx2, cpv);
            }
        mx1 = fmaxf(mx1, __shfl_xor_sync(0xffffffffu, mx1, 1));
        mx1 = fmaxf(mx1, __shfl_xor_sync(0xffffffffu, mx1, 2));
        mx2 = fmaxf(mx2, __shfl_xor_sync(0xffffffffu, mx2, 1));
        mx2 = fmaxf(mx2, __shfl_xor_sync(0xffffffffu, mx2, 2));
        if ((lane & 3) == 0) { red[128 + wc * 64 + r1] = mx1; red[128 + wc * 64 + r2] = mx2; }
        __syncthreads();

        float m1o = red[r1], m2o = red[r2];
        float mn1 = fmaxf(m1o, fmaxf(red[128 + r1], red[128 + 64 + r1]));
        float mn2 = fmaxf(m2o, fmaxf(red[128 + r2], red[128 + 64 + r2]));
        float corr1 = __expf(m1o - mn1), corr2 = __expf(m2o - mn2);

        float sum1 = 0.f, sum2 = 0.f;
        const uint32_t pwb = sb + FH_P;
#pragma unroll
        for (int nf = 0; nf < 4; nf++) {
            float p0 = __expf(sacc[nf][0] - mn1);
            float p1 = __expf(sacc[nf][1] - mn1);
            float p2 = __expf(sacc[nf][2] - mn2);
            float p3 = __expf(sacc[nf][3] - mn2);
            sum1 += p0 + p1; sum2 += p2 + p3;
            __half2 hA = __floats2half2_rn(p0, p1);
            __half2 hB = __floats2half2_rn(p2, p3);
            int chunk = wc * 4 + nf;
            uint32_t a1 = pwb + (uint32_t)r1 * 128u + (uint32_t)((chunk ^ (r1 & 7)) << 4) + ((lane & 3) << 2);
            uint32_t a2 = pwb + (uint32_t)r2 * 128u + (uint32_t)((chunk ^ (r2 & 7)) << 4) + ((lane & 3) << 2);
            asm volatile("st.shared.b32 [%0], %1;" :: "r"(a1), "r"(*(uint32_t*)&hA) : "memory");
            asm volatile("st.shared.b32 [%0], %1;" :: "r"(a2), "r"(*(uint32_t*)&hB) : "memory");
        }
        sum1 += __shfl_xor_sync(0xffffffffu, sum1, 1);
        sum1 += __shfl_xor_sync(0xffffffffu, sum1, 2);
        sum2 += __shfl_xor_sync(0xffffffffu, sum2, 1);
        sum2 += __shfl_xor_sync(0xffffffffu, sum2, 2);
        if ((lane & 3) == 0) { red[256 + wc * 64 + r1] = sum1; red[256 + wc * 64 + r2] = sum2; }

#pragma unroll
        for (int nf = 0; nf < 16; nf++) {
            oacc[nf][0] *= corr1; oacc[nf][1] *= corr1;
            oacc[nf][2] *= corr2; oacc[nf][3] *= corr2;
        }
        __syncthreads();

        if (wc == 0 && (lane & 3) == 0) {
            red[64 + r1] = red[64 + r1] * corr1 + red[256 + r1] + red[256 + 64 + r1];
            red[64 + r2] = red[64 + r2] * corr2 + red[256 + r2] + red[256 + 64 + r2];
            red[r1] = mn1; red[r2] = mn2;
        }

        const uint32_t paBase = pwb + (uint32_t)rowA * 128u;
        const int rowAp = rowA & 7;
#pragma unroll
        for (int ks = 0; ks < 4; ks++) {
            uint32_t a[4];
            LDSM4(a[0], a[1], a[2], a[3], paBase + (uint32_t)((((ks << 1) + dselA) ^ rowAp) << 4));
#pragma unroll
            for (int nf2 = 0; nf2 < 8; nf2++) {
                int rowV = ks * 16 + r8 + ((sel & 1) << 3);
                int chunk = wc * 16 + nf2 * 2 + (sel >> 1);
                uint32_t bb[4];
                LDSM4T(bb[0], bb[1], bb[2], bb[3],
                       sV + (uint32_t)rowV * 512u + (uint32_t)((chunk ^ (rowV & 7)) << 4));
                MMAH16816(oacc[nf2 * 2 + 0], a, bb[0], bb[1]);
                MMAH16816(oacc[nf2 * 2 + 1], a, bb[2], bb[3]);
            }
        }
        __syncthreads();
    }

    float inv1 = 1.f / red[64 + r1];
    float inv2 = 1.f / red[64 + r2];
    int t1 = qbase + r1, t2 = qbase + r2;
    float* o1 = Oa + (((size_t)(b * T_LEN + t1)) * N_HEADS + n) * H_DIM + wc * 128 + ((lane & 3) << 1);
    float* o2 = Oa + (((size_t)(b * T_LEN + t2)) * N_HEADS + n) * H_DIM + wc * 128 + ((lane & 3) << 1);
#pragma unroll
    for (int nf = 0; nf < 16; nf++) {
        *(float2*)(o1 + nf * 8) = make_float2(oacc[nf][0] * inv1, oacc[nf][1] * inv1);
        *(float2*)(o2 + nf * 8) = make_float2(oacc[nf][2] * inv2, oacc[nf][3] * inv2);
    }
}

// ---------------- launch ----------------
extern "C" void kernel_launch(void* const* d_in, const int* in_sizes, int n_in,
                              void* d_out, int out_size)
{
    (void)in_sizes; (void)n_in; (void)out_size;
    const float* hs  = (const float*)d_in[0];
    const float* enc = (const float*)d_in[1];
    const float* qw  = (const float*)d_in[4];
    const float* kw  = (const float*)d_in[5];
    const float* vw  = (const float*)d_in[6];
    const float* ow  = (const float*)d_in[7];
    const float* qsc = (const float*)d_in[8];
    const float* ksc = (const float*)d_in[9];
    float* out = (float*)d_out;

    float *qb, *kb, *vb, *ab;
    cudaGetSymbolAddress((void**)&qb, g_q);
    cudaGetSymbolAddress((void**)&kb, g_k);
    cudaGetSymbolAddress((void**)&vb, g_v);
    cudaGetSymbolAddress((void**)&ab, g_attn);
    __half *q16, *k16, *v16;
    cudaGetSymbolAddress((void**)&q16, g_q16);
    cudaGetSymbolAddress((void**)&k16, g_k16);
    cudaGetSymbolAddress((void**)&v16, g_v16);
    __half *hs2, *enc2, *qw2, *kw2, *vw2, *ow2, *at2;
    cudaGetSymbolAddress((void**)&hs2, g_hs2);
    cudaGetSymbolAddress((void**)&enc2, g_enc2);
    cudaGetSymbolAddress((void**)&qw2, g_qw2);
    cudaGetSymbolAddress((void**)&kw2, g_kw2);
    cudaGetSymbolAddress((void**)&vw2, g_vw2);
    cudaGetSymbolAddress((void**)&ow2, g_ow2);
    cudaGetSymbolAddress((void**)&at2, g_at2);

    static int cfg = 0;
    if (!cfg) {
        cudaFuncSetAttribute(gemm_hmma, cudaFuncAttributeMaxDynamicSharedMemorySize, GEMM_SMEM);
        cudaFuncSetAttribute(flash_hmma, cudaFuncAttributeMaxDynamicSharedMemorySize, FH_SMEM);
        cfg = 1;
    }

    // splits (fp16x2)
    asplit_kernel<<<dim3(D_DIM / 256, 4096), 256>>>(hs, hs2, D_DIM);
    asplit_kernel<<<dim3(D_DIM / 256, 4096), 256>>>(enc, enc2, D_DIM);
    wsplit_kernel<<<dim3(4096 / 32, D_DIM / 32), 256>>>(qw, qw2, D_DIM, H_DIM, (long long)D_DIM * H_DIM, H_DIM);
    wsplit_kernel<<<dim3(2048 / 32, D_DIM / 32), 256>>>(kw, kw2, D_DIM, H_DIM, (long long)D_DIM * H_DIM, H_DIM);
    wsplit_kernel<<<dim3(2048 / 32, D_DIM / 32), 256>>>(vw, vw2, D_DIM, H_DIM, (long long)D_DIM * H_DIM, H_DIM);
    wsplit_kernel<<<dim3(2048 / 32, 4096 / 32), 256>>>(ow, ow2, 4096, D_DIM, 0LL, D_DIM);

    const long long kvBS = (long long)S_LEN * K_HEADS * H_DIM;
    gemm_hmma<<<dim3(32, 32), 256, GEMM_SMEM>>>(hs2, qw2, qb, 4096, 4096, 0LL, 0, 4096);
    gemm_hmma<<<dim3(16, 32), 256, GEMM_SMEM>>>(hs2, kw2, kb, 4096, T_LEN, kvBS, 0, 2048);
    gemm_hmma<<<dim3(16, 32), 256, GEMM_SMEM>>>(hs2, vw2, vb, 4096, T_LEN, kvBS, 0, 2048);
    gemm_hmma<<<dim3(16, 32), 256, GEMM_SMEM>>>(enc2, kw2, kb, 4096, E_LEN, kvBS, T_LEN, 2048);
    gemm_hmma<<<dim3(16, 32), 256, GEMM_SMEM>>>(enc2, vw2, vb, 4096, E_LEN, kvBS, T_LEN, 2048);

    // rms(+rope) -> fp16 operands
    rms_rope_h_kernel<<<B_SZ * T_LEN * N_HEADS, 256>>>(qb, q16, qsc, N_HEADS, T_LEN, T_LEN, 0, 1, 0.0625f);
    rms_rope_h_kernel<<<B_SZ * T_LEN * K_HEADS, 256>>>(kb, k16, ksc, K_HEADS, T_LEN, S_LEN, 0, 1, 1.0f);
    rms_rope_h_kernel<<<B_SZ * E_LEN * K_HEADS, 256>>>(kb, k16, ksc, K_HEADS, E_LEN, S_LEN, T_LEN, 0, 1.0f);
    f2h_kernel<<<(B_SZ * S_LEN * K_HEADS * H_DIM) / 1024, 256>>>(vb, v16);

    flash_hmma<<<dim3(T_LEN / 64, N_HEADS, B_SZ), 256, FH_SMEM>>>(q16, k16, v16, ab);

    // O = attn @ ow  (fp16x2, K' = 8192)
    asplit_kernel<<<dim3(4096 / 256, 4096), 256>>>(ab, at2, 4096);
    gemm_hmma<<<dim3(16, 32), 256, GEMM_SMEM>>>(at2, ow2, out, 8192, 4096, 0LL, 0, 2048);
}

// round 7
// speedup vs baseline: 5.7652x; 1.5779x over previous
#include <cuda_runtime.h>
#include <cuda_fp16.h>
#include <stdint.h>
#include <math.h>

#define B_SZ 4
#define T_LEN 1024
#define E_LEN 1024
#define S_LEN 2048
#define D_DIM 2048
#define H_DIM 256
#define N_HEADS 16
#define K_HEADS 8

// fp32 scratch
__device__ float g_q[(size_t)B_SZ * T_LEN * N_HEADS * H_DIM];
__device__ float g_k[(size_t)B_SZ * S_LEN * K_HEADS * H_DIM];
__device__ float g_v[(size_t)B_SZ * S_LEN * K_HEADS * H_DIM];
__device__ float g_attn[(size_t)B_SZ * T_LEN * N_HEADS * H_DIM];
// fp16 attention operands
__device__ __half g_q16[(size_t)B_SZ * T_LEN * N_HEADS * H_DIM];
__device__ __half g_k16[(size_t)B_SZ * S_LEN * K_HEADS * H_DIM];
__device__ __half g_v16[(size_t)B_SZ * S_LEN * K_HEADS * H_DIM];
// fp16 GEMM operands (plain convert, K'=K)
__device__ __half g_hs2 [(size_t)4096 * 2048];
__device__ __half g_enc2[(size_t)4096 * 2048];
__device__ __half g_qw2 [(size_t)4096 * 2048];
__device__ __half g_kw2 [(size_t)2048 * 2048];
__device__ __half g_vw2 [(size_t)2048 * 2048];
__device__ __half g_ow2 [(size_t)2048 * 4096];
__device__ __half g_at2 [(size_t)4096 * 4096];

// ---------------- helpers ----------------
__device__ __forceinline__ uint32_t smem_u32(const void* p) {
    uint32_t a;
    asm("{ .reg .u64 t; cvta.to.shared.u64 t, %1; cvt.u32.u64 %0, t; }" : "=r"(a) : "l"(p));
    return a;
}
#define CP16(dst, src) \
    asm volatile("cp.async.cg.shared.global [%0], [%1], 16;" :: "r"(dst), "l"(src) : "memory")
#define CP_COMMIT asm volatile("cp.async.commit_group;" ::: "memory")
#define CP_WAIT2  asm volatile("cp.async.wait_group 2;" ::: "memory")
#define CP_WAIT1  asm volatile("cp.async.wait_group 1;" ::: "memory")
#define CP_WAIT0  asm volatile("cp.async.wait_group 0;" ::: "memory")
#define LDSM4(r0, r1, r2, r3, addr) \
    asm volatile("ldmatrix.sync.aligned.m8n8.x4.shared.b16 {%0,%1,%2,%3}, [%4];" \
        : "=r"(r0), "=r"(r1), "=r"(r2), "=r"(r3) : "r"(addr))
#define LDSM4T(r0, r1, r2, r3, addr) \
    asm volatile("ldmatrix.sync.aligned.m8n8.x4.trans.shared.b16 {%0,%1,%2,%3}, [%4];" \
        : "=r"(r0), "=r"(r1), "=r"(r2), "=r"(r3) : "r"(addr))
#define MMAH16816(d, a, b0, b1) \
    asm volatile("mma.sync.aligned.m16n8k16.row.col.f32.f16.f16.f32 " \
        "{%0,%1,%2,%3}, {%4,%5,%6,%7}, {%8,%9}, {%0,%1,%2,%3};" \
        : "+f"((d)[0]), "+f"((d)[1]), "+f"((d)[2]), "+f"((d)[3]) \
        : "r"((a)[0]), "r"((a)[1]), "r"((a)[2]), "r"((a)[3]), "r"(b0), "r"(b1))

// gemm smem tile swizzle: 128 rows x 64B. 128B line = 2 rows, 8 chunks of 16B.
__device__ __forceinline__ uint32_t sw_off(int row, int kbyte) {
    int line = row >> 1;
    int ch = (((row & 1) << 2) + (kbyte >> 4)) ^ (line & 7);
    return (uint32_t)(line * 128 + ch * 16 + (kbyte & 15));
}
// flash smem swizzle: 512B rows (256 halfs), 32 chunks of 16B
__device__ __forceinline__ uint32_t fsw(int row, int kbyte) {
    return (uint32_t)(row * 512 + ((((kbyte >> 4) ^ (row & 7))) << 4) + (kbyte & 15));
}

// ---------------- convert kernels ----------------
// plain fp32 -> fp16, same [rows, Kd] layout
__global__ __launch_bounds__(256) void a2h_kernel(
    const float* __restrict__ X, __half* __restrict__ Y)
{
    size_t idx = ((size_t)blockIdx.x * 256 + threadIdx.x) * 4;
    float4 v = *(const float4*)(X + idx);
    __half2 h0 = __floats2half2_rn(v.x, v.y);
    __half2 h1 = __floats2half2_rn(v.z, v.w);
    *(uint2*)(Y + idx) = make_uint2(*(uint32_t*)&h0, *(uint32_t*)&h1);
}

// W(k,j) = W[(j/cph)*hstr + k*krs + j%cph]; out Yt[j, Kd] fp16 (transposed)
__global__ __launch_bounds__(256) void wsplit_kernel(
    const float* __restrict__ W, __half* __restrict__ Yt,
    int Kd, int cph, long long hstr, int krs)
{
    __shared__ float t[32][33];
    int k0 = blockIdx.y * 32, j0 = blockIdx.x * 32;
    int tx = threadIdx.x & 31, ty8 = threadIdx.x >> 5;
#pragma unroll
    for (int i = 0; i < 4; i++) {
        int kl = ty8 + i * 8;
        int j = j0 + tx;
        t[kl][tx] = W[(size_t)(j / cph) * hstr + (size_t)(k0 + kl) * krs + (j % cph)];
    }
    __syncthreads();
#pragma unroll
    for (int i = 0; i < 4; i++) {
        int j = j0 + ty8 + i * 8;
        int k = k0 + tx;
        Yt[(size_t)j * Kd + k] = __float2half(t[tx][ty8 + i * 8]);
    }
}

// ---------------- HMMA fp16 GEMM (proven R4-R6) ----------------
#define GSTAGES 3
#define STG_BYTES 16384
#define GEMM_SMEM (GSTAGES * STG_BYTES)

__global__ void __launch_bounds__(256, 2) gemm_hmma(
    const __half* __restrict__ A, const __half* __restrict__ Bw,
    float* __restrict__ C, int Kp, int Mpb, long long outBS, int rowOff, int ldc)
{
    extern __shared__ char smraw[];
    const uint32_t sb = smem_u32(smraw);
    const int tid = threadIdx.x;
    const int lane = tid & 31, wid = tid >> 5;
    const int wm = wid & 3, wn = wid >> 2;
    const int m0 = blockIdx.y * 128, n0 = blockIdx.x * 128;
    const int nIter = Kp >> 5;

    const int crow = tid >> 1;
    const int ck = (tid & 1) << 4;
    const __half* ga = A + (size_t)(m0 + crow) * Kp + ck;
    const __half* gb = Bw + (size_t)(n0 + crow) * Kp + ck;
    const uint32_t sw0 = sw_off(crow, ck * 2);
    const uint32_t sw1 = sw_off(crow, ck * 2 + 16);

    const int r8 = lane & 7, sel = lane >> 3;
    uint32_t aoff[2][2], boff[4][2];
#pragma unroll
    for (int mf = 0; mf < 2; mf++)
#pragma unroll
        for (int ks = 0; ks < 2; ks++) {
            int row = wm * 32 + mf * 16 + r8 + ((sel & 1) << 3);
            int kb = ks * 32 + ((sel >> 1) << 4);
            aoff[mf][ks] = sw_off(row, kb);
        }
#pragma unroll
    for (int np = 0; np < 4; np++)
#pragma unroll
        for (int ks = 0; ks < 2; ks++) {
            int row = wn * 64 + np * 16 + r8 + ((sel >> 1) << 3);
            int kb = ks * 32 + ((sel & 1) << 4);
            boff[np][ks] = 8192u + sw_off(row, kb);
        }

    float acc[2][8][4];
#pragma unroll
    for (int mf = 0; mf < 2; mf++)
#pragma unroll
        for (int nf = 0; nf < 8; nf++)
#pragma unroll
            for (int q = 0; q < 4; q++) acc[mf][nf][q] = 0.f;

#pragma unroll
    for (int s = 0; s < 2; s++) {
        uint32_t base = sb + (uint32_t)s * STG_BYTES;
        const __half* pa = ga + s * 32;
        const __half* pb = gb + s * 32;
        CP16(base + sw0, pa);
        CP16(base + sw1, pa + 8);
        CP16(base + 8192u + sw0, pb);
        CP16(base + 8192u + sw1, pb + 8);
        CP_COMMIT;
    }

    for (int it = 0; it < nIter; it++) {
        if (it + 2 < nIter) {
            int s = (it + 2) % GSTAGES;
            uint32_t base = sb + (uint32_t)s * STG_BYTES;
            const __half* pa = ga + (size_t)(it + 2) * 32;
            const __half* pb = gb + (size_t)(it + 2) * 32;
            CP16(base + sw0, pa);
            CP16(base + sw1, pa + 8);
            CP16(base + 8192u + sw0, pb);
            CP16(base + 8192u + sw1, pb + 8);
        }
        CP_COMMIT;
        CP_WAIT2;
        __syncthreads();

        uint32_t sbase = sb + (uint32_t)(it % GSTAGES) * STG_BYTES;
#pragma unroll
        for (int ks = 0; ks < 2; ks++) {
            uint32_t af[2][4];
#pragma unroll
            for (int mf = 0; mf < 2; mf++)
                LDSM4(af[mf][0], af[mf][1], af[mf][2], af[mf][3], sbase + aoff[mf][ks]);
            uint32_t bf[4][4];
#pragma unroll
            for (int np = 0; np < 4; np++)
                LDSM4(bf[np][0], bf[np][1], bf[np][2], bf[np][3], sbase + boff[np][ks]);
#pragma unroll
            for (int mf = 0; mf < 2; mf++)
#pragma unroll
                for (int np = 0; np < 4; np++) {
                    MMAH16816(acc[mf][np * 2 + 0], af[mf], bf[np][0], bf[np][1]);
                    MMAH16816(acc[mf][np * 2 + 1], af[mf], bf[np][2], bf[np][3]);
                }
        }
        __syncthreads();
    }

#pragma unroll
    for (int mf = 0; mf < 2; mf++)
#pragma unroll
        for (int rh = 0; rh < 2; rh++) {
            int gr = m0 + wm * 32 + mf * 16 + (lane >> 2) + rh * 8;
            int bi = gr / Mpb;
            int rr = gr - bi * Mpb;
            float* rowp = C + (size_t)bi * outBS + (size_t)(rr + rowOff) * ldc
                        + n0 + wn * 64 + (lane & 3) * 2;
#pragma unroll
            for (int nf = 0; nf < 8; nf++) {
                float2 v = make_float2(acc[mf][nf][rh * 2 + 0], acc[mf][nf][rh * 2 + 1]);
                *(float2*)(rowp + nf * 8) = v;
            }
        }
}

// ---------------- RMS-norm (+RoPE) -> fp16 ----------------
__global__ __launch_bounds__(256) void rms_rope_h_kernel(
    const float* __restrict__ buf, __half* __restrict__ outh,
    const float* __restrict__ scale,
    int heads, int rowsPerBatch, int bufRPB, int rowStart, int doRope, float outScale)
{
    __shared__ float sh[256];
    __shared__ float ws[8];
    int idx = blockIdx.x;
    int head = idx % heads;
    int tmp = idx / heads;
    int t = tmp % rowsPerBatch;
    int b = tmp / rowsPerBatch;
    size_t off = ((size_t)((size_t)b * bufRPB + rowStart + t) * heads + head) * H_DIM;
    int h = threadIdx.x;
    float x = buf[off + h];
    float ss = x * x;
#pragma unroll
    for (int o = 16; o > 0; o >>= 1) ss += __shfl_xor_sync(0xffffffffu, ss, o);
    if ((h & 31) == 0) ws[h >> 5] = ss;
    __syncthreads();
    float tot = 0.f;
#pragma unroll
    for (int w = 0; w < 8; w++) tot += ws[w];
    float y = x * rsqrtf(tot * (1.f / 256.f) + 1e-6f) * (1.f + scale[h]);
    if (doRope) {
        sh[h] = y;
        __syncthreads();
        int i = h & 127;
        float ang = (float)t * exp2f(-(float)i * 0.10381025296522988f);
        float sn, cs;
        sincosf(ang, &sn, &cs);
        if (h < 128) y = sh[h] * cs - sh[h + 128] * sn;
        else         y = sh[h] * cs + sh[h - 128] * sn;
    }
    outh[off + h] = __float2half(y * outScale);
}

// ---------------- flash attention fp16 HMMA (unchanged R5/R6) ----------------
#define FH_K 32768u
#define FH_V 65536u
#define FH_STRIDE 65536u
#define FH_P 163840u
#define FH_RED 172032
#define FH_SMEM (172032 + 1536)

__global__ void __launch_bounds__(256, 1) flash_hmma(
    const __half* __restrict__ Qh, const __half* __restrict__ Kh,
    const __half* __restrict__ Vh, float* __restrict__ Oa)
{
    extern __shared__ char smraw[];
    const uint32_t sb = smem_u32(smraw);
    float* red = (float*)(smraw + FH_RED);
    const int tid = threadIdx.x, lane = tid & 31, w = tid >> 5;
    const int wr = w & 3, wc = w >> 2;
    const int qt = blockIdx.x, n = blockIdx.y, b = blockIdx.z;
    const int kh = n >> 1, qbase = qt << 6;

    const char* qg = (const char*)(Qh + ((size_t)(b * T_LEN + qbase) * N_HEADS + n) * H_DIM);
#pragma unroll
    for (int p = 0; p < 8; p++) {
        int idx = tid + p * 256;
        int r = idx >> 5, c = idx & 31;
        CP16(sb + fsw(r, c * 16), qg + (size_t)r * (N_HEADS * H_DIM * 2) + c * 16);
    }
    if (tid < 64) { red[tid] = -INFINITY; red[64 + tid] = 0.f; }
    CP_COMMIT;

    const char* kg = (const char*)(Kh + ((size_t)b * S_LEN * K_HEADS + kh) * H_DIM);
    const char* vg = (const char*)(Vh + ((size_t)b * S_LEN * K_HEADS + kh) * H_DIM);
    const int kvstride = K_HEADS * H_DIM * 2;

    const int nSelf = qt + 1;
    const int nT = nSelf + (E_LEN >> 6);

#pragma unroll
    for (int p = 0; p < 8; p++) {
        int idx = tid + p * 256;
        int r = idx >> 5, c = idx & 31;
        uint32_t sw = fsw(r, c * 16);
        CP16(sb + FH_K + sw, kg + (size_t)r * kvstride + c * 16);
        CP16(sb + FH_V + sw, vg + (size_t)r * kvstride + c * 16);
    }
    CP_COMMIT;

    float oacc[16][4];
#pragma unroll
    for (int nf = 0; nf < 16; nf++)
#pragma unroll
        for (int q = 0; q < 4; q++) oacc[nf][q] = 0.f;

    const int r8 = lane & 7, sel = lane >> 3;
    const int rowA = wr * 16 + r8 + ((sel & 1) << 3);
    const int dselA = sel >> 1;
    const int rowB0 = wc * 32 + r8 + ((sel >> 1) << 3);
    const int dselB = sel & 1;
    const int r1 = wr * 16 + (lane >> 2), r2 = r1 + 8;

    for (int t = 0; t < nT; t++) {
        if (t + 1 < nT) {
            int s0n = (t + 1 < nSelf) ? ((t + 1) << 6) : (T_LEN + ((t + 1 - nSelf) << 6));
            uint32_t kb = sb + FH_K + (uint32_t)((t + 1) & 1) * FH_STRIDE;
            uint32_t vb = sb + FH_V + (uint32_t)((t + 1) & 1) * FH_STRIDE;
#pragma unroll
            for (int p = 0; p < 8; p++) {
                int idx = tid + p * 256;
                int r = idx >> 5, c = idx & 31;
                uint32_t sw = fsw(r, c * 16);
                CP16(kb + sw, kg + (size_t)(s0n + r) * kvstride + c * 16);
                CP16(vb + sw, vg + (size_t)(s0n + r) * kvstride + c * 16);
            }
            CP_COMMIT;
            CP_WAIT1;
        } else {
            CP_WAIT0;
        }
        __syncthreads();

        const int s0 = (t < nSelf) ? (t << 6) : (T_LEN + ((t - nSelf) << 6));
        const bool diag = (t == qt);
        const uint32_t sK = sb + FH_K + (uint32_t)(t & 1) * FH_STRIDE;
        const uint32_t sV = sb + FH_V + (uint32_t)(t & 1) * FH_STRIDE;
        const uint32_t aBase = sb + (uint32_t)rowA * 512u;
        const int rowAx = rowA & 7;

        float sacc[4][4];
#pragma unroll
        for (int nf = 0; nf < 4; nf++)
#pragma unroll
            for (int q = 0; q < 4; q++) sacc[nf][q] = 0.f;
#pragma unroll 4
        for (int ks = 0; ks < 16; ks++) {
            uint32_t a[4];
            LDSM4(a[0], a[1], a[2], a[3], aBase + (uint32_t)((((ks << 1) + dselA) ^ rowAx) << 4));
#pragma unroll
            for (int nf2 = 0; nf2 < 2; nf2++) {
                int rowB = rowB0 + nf2 * 16;
                uint32_t bb[4];
                LDSM4(bb[0], bb[1], bb[2], bb[3],
                      sK + (uint32_t)rowB * 512u + (uint32_t)((((ks << 1) + dselB) ^ (rowB & 7)) << 4));
                MMAH16816(sacc[nf2 * 2 + 0], a, bb[0], bb[1]);
                MMAH16816(sacc[nf2 * 2 + 1], a, bb[2], bb[3]);
            }
        }

        float mx1 = -INFINITY, mx2 = -INFINITY;
#pragma unroll
        for (int nf = 0; nf < 4; nf++)
#pragma unroll
            for (int e = 0; e < 4; e++) {
                float s = sacc[nf][e];
                float cpv = 50.f - __fdividef(100.f, __expf(0.04f * s) + 1.f);
                if (diag) {
                    int col = s0 + wc * 32 + nf * 8 + ((lane & 3) << 1) + (e & 1);
                    int row = qbase + ((e < 2) ? r1 : r2);
                    if (col > row) cpv = -INFINITY;
                }
                sacc[nf][e] = cpv;
                if (e < 2) mx1 = fmaxf(mx1, cpv); else mx2 = fmaxf(mx2, cpv);
            }
        mx1 = fmaxf(mx1, __shfl_xor_sync(0xffffffffu, mx1, 1));
        mx1 = fmaxf(mx1, __shfl_xor_sync(0xffffffffu, mx1, 2));
        mx2 = fmaxf(mx2, __shfl_xor_sync(0xffffffffu, mx2, 1));
        mx2 = fmaxf(mx2, __shfl_xor_sync(0xffffffffu, mx2, 2));
        if ((lane & 3) == 0) { red[128 + wc * 64 + r1] = mx1; red[128 + wc * 64 + r2] = mx2; }
        __syncthreads();

        float m1o = red[r1], m2o = red[r2];
        float mn1 = fmaxf(m1o, fmaxf(red[128 + r1], red[128 + 64 + r1]));
        float mn2 = fmaxf(m2o, fmaxf(red[128 + r2], red[128 + 64 + r2]));
        float corr1 = __expf(m1o - mn1), corr2 = __expf(m2o - mn2);

        float sum1 = 0.f, sum2 = 0.f;
        const uint32_t pwb = sb + FH_P;
#pragma unroll
        for (int nf = 0; nf < 4; nf++) {
            float p0 = __expf(sacc[nf][0] - mn1);
            float p1 = __expf(sacc[nf][1] - mn1);
            float p2 = __expf(sacc[nf][2] - mn2);
            float p3 = __expf(sacc[nf][3] - mn2);
            sum1 += p0 + p1; sum2 += p2 + p3;
            __half2 hA = __floats2half2_rn(p0, p1);
            __half2 hB = __floats2half2_rn(p2, p3);
            int chunk = wc * 4 + nf;
            uint32_t a1 = pwb + (uint32_t)r1 * 128u + (uint32_t)((chunk ^ (r1 & 7)) << 4) + ((lane & 3) << 2);
            uint32_t a2 = pwb + (uint32_t)r2 * 128u + (uint32_t)((chunk ^ (r2 & 7)) << 4) + ((lane & 3) << 2);
            asm volatile("st.shared.b32 [%0], %1;" :: "r"(a1), "r"(*(uint32_t*)&hA) : "memory");
            asm volatile("st.shared.b32 [%0], %1;" :: "r"(a2), "r"(*(uint32_t*)&hB) : "memory");
        }
        sum1 += __shfl_xor_sync(0xffffffffu, sum1, 1);
        sum1 += __shfl_xor_sync(0xffffffffu, sum1, 2);
        sum2 += __shfl_xor_sync(0xffffffffu, sum2, 1);
        sum2 += __shfl_xor_sync(0xffffffffu, sum2, 2);
        if ((lane & 3) == 0) { red[256 + wc * 64 + r1] = sum1; red[256 + wc * 64 + r2] = sum2; }

#pragma unroll
        for (int nf = 0; nf < 16; nf++) {
            oacc[nf][0] *= corr1; oacc[nf][1] *= corr1;
            oacc[nf][2] *= corr2; oacc[nf][3] *= corr2;
        }
        __syncthreads();

        if (wc == 0 && (lane & 3) == 0) {
            red[64 + r1] = red[64 + r1] * corr1 + red[256 + r1] + red[256 + 64 + r1];
            red[64 + r2] = red[64 + r2] * corr2 + red[256 + r2] + red[256 + 64 + r2];
            red[r1] = mn1; red[r2] = mn2;
        }

        const uint32_t paBase = pwb + (uint32_t)rowA * 128u;
        const int rowAp = rowA & 7;
#pragma unroll
        for (int ks = 0; ks < 4; ks++) {
            uint32_t a[4];
            LDSM4(a[0], a[1], a[2], a[3], paBase + (uint32_t)((((ks << 1) + dselA) ^ rowAp) << 4));
#pragma unroll
            for (int nf2 = 0; nf2 < 8; nf2++) {
                int rowV = ks * 16 + r8 + ((sel & 1) << 3);
                int chunk = wc * 16 + nf2 * 2 + (sel >> 1);
                uint32_t bb[4];
                LDSM4T(bb[0], bb[1], bb[2], bb[3],
                       sV + (uint32_t)rowV * 512u + (uint32_t)((chunk ^ (rowV & 7)) << 4));
                MMAH16816(oacc[nf2 * 2 + 0], a, bb[0], bb[1]);
                MMAH16816(oacc[nf2 * 2 + 1], a, bb[2], bb[3]);
            }
        }
        __syncthreads();
    }

    float inv1 = 1.f / red[64 + r1];
    float inv2 = 1.f / red[64 + r2];
    int t1 = qbase + r1, t2 = qbase + r2;
    float* o1 = Oa + (((size_t)(b * T_LEN + t1)) * N_HEADS + n) * H_DIM + wc * 128 + ((lane & 3) << 1);
    float* o2 = Oa + (((size_t)(b * T_LEN + t2)) * N_HEADS + n) * H_DIM + wc * 128 + ((lane & 3) << 1);
#pragma unroll
    for (int nf = 0; nf < 16; nf++) {
        *(float2*)(o1 + nf * 8) = make_float2(oacc[nf][0] * inv1, oacc[nf][1] * inv1);
        *(float2*)(o2 + nf * 8) = make_float2(oacc[nf][2] * inv2, oacc[nf][3] * inv2);
    }
}

// ---------------- launch ----------------
extern "C" void kernel_launch(void* const* d_in, const int* in_sizes, int n_in,
                              void* d_out, int out_size)
{
    (void)in_sizes; (void)n_in; (void)out_size;
    const float* hs  = (const float*)d_in[0];
    const float* enc = (const float*)d_in[1];
    const float* qw  = (const float*)d_in[4];
    const float* kw  = (const float*)d_in[5];
    const float* vw  = (const float*)d_in[6];
    const float* ow  = (const float*)d_in[7];
    const float* qsc = (const float*)d_in[8];
    const float* ksc = (const float*)d_in[9];
    float* out = (float*)d_out;

    float *qb, *kb, *vb, *ab;
    cudaGetSymbolAddress((void**)&qb, g_q);
    cudaGetSymbolAddress((void**)&kb, g_k);
    cudaGetSymbolAddress((void**)&vb, g_v);
    cudaGetSymbolAddress((void**)&ab, g_attn);
    __half *q16, *k16, *v16;
    cudaGetSymbolAddress((void**)&q16, g_q16);
    cudaGetSymbolAddress((void**)&k16, g_k16);
    cudaGetSymbolAddress((void**)&v16, g_v16);
    __half *hs2, *enc2, *qw2, *kw2, *vw2, *ow2, *at2;
    cudaGetSymbolAddress((void**)&hs2, g_hs2);
    cudaGetSymbolAddress((void**)&enc2, g_enc2);
    cudaGetSymbolAddress((void**)&qw2, g_qw2);
    cudaGetSymbolAddress((void**)&kw2, g_kw2);
    cudaGetSymbolAddress((void**)&vw2, g_vw2);
    cudaGetSymbolAddress((void**)&ow2, g_ow2);
    cudaGetSymbolAddress((void**)&at2, g_at2);

    static int cfg = 0;
    if (!cfg) {
        cudaFuncSetAttribute(gemm_hmma, cudaFuncAttributeMaxDynamicSharedMemorySize, GEMM_SMEM);
        cudaFuncSetAttribute(flash_hmma, cudaFuncAttributeMaxDynamicSharedMemorySize, FH_SMEM);
        cfg = 1;
    }

    // converts (plain fp16)
    a2h_kernel<<<(4096LL * 2048) / 1024, 256>>>(hs, hs2);
    a2h_kernel<<<(4096LL * 2048) / 1024, 256>>>(enc, enc2);
    wsplit_kernel<<<dim3(4096 / 32, D_DIM / 32), 256>>>(qw, qw2, D_DIM, H_DIM, (long long)D_DIM * H_DIM, H_DIM);
    wsplit_kernel<<<dim3(2048 / 32, D_DIM / 32), 256>>>(kw, kw2, D_DIM, H_DIM, (long long)D_DIM * H_DIM, H_DIM);
    wsplit_kernel<<<dim3(2048 / 32, D_DIM / 32), 256>>>(vw, vw2, D_DIM, H_DIM, (long long)D_DIM * H_DIM, H_DIM);
    wsplit_kernel<<<dim3(2048 / 32, 4096 / 32), 256>>>(ow, ow2, 4096, D_DIM, 0LL, D_DIM);

    const long long kvBS = (long long)S_LEN * K_HEADS * H_DIM;
    gemm_hmma<<<dim3(32, 32), 256, GEMM_SMEM>>>(hs2, qw2, qb, 2048, 4096, 0LL, 0, 4096);
    gemm_hmma<<<dim3(16, 32), 256, GEMM_SMEM>>>(hs2, kw2, kb, 2048, T_LEN, kvBS, 0, 2048);
    gemm_hmma<<<dim3(16, 32), 256, GEMM_SMEM>>>(hs2, vw2, vb, 2048, T_LEN, kvBS, 0, 2048);
    gemm_hmma<<<dim3(16, 32), 256, GEMM_SMEM>>>(enc2, kw2, kb, 2048, E_LEN, kvBS, T_LEN, 2048);
    gemm_hmma<<<dim3(16, 32), 256, GEMM_SMEM>>>(enc2, vw2, vb, 2048, E_LEN, kvBS, T_LEN, 2048);

    // rms(+rope) -> fp16 operands
    rms_rope_h_kernel<<<B_SZ * T_LEN * N_HEADS, 256>>>(qb, q16, qsc, N_HEADS, T_LEN, T_LEN, 0, 1, 0.0625f);
    rms_rope_h_kernel<<<B_SZ * T_LEN * K_HEADS, 256>>>(kb, k16, ksc, K_HEADS, T_LEN, S_LEN, 0, 1, 1.0f);
    rms_rope_h_kernel<<<B_SZ * E_LEN * K_HEADS, 256>>>(kb, k16, ksc, K_HEADS, E_LEN, S_LEN, T_LEN, 0, 1.0f);
    a2h_kernel<<<(B_SZ * S_LEN * K_HEADS * H_DIM) / 1024, 256>>>(vb, v16);

    flash_hmma<<<dim3(T_LEN / 64, N_HEADS, B_SZ), 256, FH_SMEM>>>(q16, k16, v16, ab);

    // O = attn @ ow  (fp16, K = 4096)
    a2h_kernel<<<(4096LL * 4096) / 1024, 256>>>(ab, at2);
    gemm_hmma<<<dim3(16, 32), 256, GEMM_SMEM>>>(at2, ow2, out, 4096, 4096, 0LL, 0, 2048);
}

// round 8
// speedup vs baseline: 6.8568x; 1.1893x over previous
#include <cuda_runtime.h>
#include <cuda_fp16.h>
#include <stdint.h>
#include <math.h>

#define B_SZ 4
#define T_LEN 1024
#define E_LEN 1024
#define S_LEN 2048
#define D_DIM 2048
#define H_DIM 256
#define N_HEADS 16
#define K_HEADS 8

// fp32 scratch
__device__ float g_q[(size_t)B_SZ * T_LEN * N_HEADS * H_DIM];
__device__ float g_k[(size_t)B_SZ * S_LEN * K_HEADS * H_DIM];
__device__ float g_v[(size_t)B_SZ * S_LEN * K_HEADS * H_DIM];
// fp16 attention operands
__device__ __half g_q16[(size_t)B_SZ * T_LEN * N_HEADS * H_DIM];
__device__ __half g_k16[(size_t)B_SZ * S_LEN * K_HEADS * H_DIM];
__device__ __half g_v16[(size_t)B_SZ * S_LEN * K_HEADS * H_DIM];
// fp16 GEMM operands
__device__ __half g_hs2 [(size_t)4096 * 2048];
__device__ __half g_enc2[(size_t)4096 * 2048];
__device__ __half g_qw2 [(size_t)4096 * 2048];
__device__ __half g_kw2 [(size_t)2048 * 2048];
__device__ __half g_vw2 [(size_t)2048 * 2048];
__device__ __half g_ow2 [(size_t)2048 * 4096];
__device__ __half g_at2 [(size_t)4096 * 4096];   // flash output (fp16), O-GEMM input

// ---------------- helpers ----------------
__device__ __forceinline__ uint32_t smem_u32(const void* p) {
    uint32_t a;
    asm("{ .reg .u64 t; cvta.to.shared.u64 t, %1; cvt.u32.u64 %0, t; }" : "=r"(a) : "l"(p));
    return a;
}
#define CP16(dst, src) \
    asm volatile("cp.async.cg.shared.global [%0], [%1], 16;" :: "r"(dst), "l"(src) : "memory")
#define CP_COMMIT asm volatile("cp.async.commit_group;" ::: "memory")
#define CP_WAIT2  asm volatile("cp.async.wait_group 2;" ::: "memory")
#define CP_WAIT1  asm volatile("cp.async.wait_group 1;" ::: "memory")
#define CP_WAIT0  asm volatile("cp.async.wait_group 0;" ::: "memory")
#define LDSM4(r0, r1, r2, r3, addr) \
    asm volatile("ldmatrix.sync.aligned.m8n8.x4.shared.b16 {%0,%1,%2,%3}, [%4];" \
        : "=r"(r0), "=r"(r1), "=r"(r2), "=r"(r3) : "r"(addr))
#define LDSM4T(r0, r1, r2, r3, addr) \
    asm volatile("ldmatrix.sync.aligned.m8n8.x4.trans.shared.b16 {%0,%1,%2,%3}, [%4];" \
        : "=r"(r0), "=r"(r1), "=r"(r2), "=r"(r3) : "r"(addr))
#define MMAH16816(d, a, b0, b1) \
    asm volatile("mma.sync.aligned.m16n8k16.row.col.f32.f16.f16.f32 " \
        "{%0,%1,%2,%3}, {%4,%5,%6,%7}, {%8,%9}, {%0,%1,%2,%3};" \
        : "+f"((d)[0]), "+f"((d)[1]), "+f"((d)[2]), "+f"((d)[3]) \
        : "r"((a)[0]), "r"((a)[1]), "r"((a)[2]), "r"((a)[3]), "r"(b0), "r"(b1))

// 128B-row swizzle (8 chunks of 16B, xor with row&7)
__device__ __forceinline__ uint32_t gsw(int row, int kchunk) {
    return (uint32_t)(row * 128 + ((kchunk ^ (row & 7)) << 4));
}
// flash smem swizzle: 512B rows
__device__ __forceinline__ uint32_t fsw(int row, int kbyte) {
    return (uint32_t)(row * 512 + ((((kbyte >> 4) ^ (row & 7))) << 4) + (kbyte & 15));
}

// ---------------- convert kernels ----------------
__global__ __launch_bounds__(256) void a2h_kernel(
    const float* __restrict__ X, __half* __restrict__ Y)
{
    size_t idx = ((size_t)blockIdx.x * 256 + threadIdx.x) * 4;
    float4 v = *(const float4*)(X + idx);
    __half2 h0 = __floats2half2_rn(v.x, v.y);
    __half2 h1 = __floats2half2_rn(v.z, v.w);
    *(uint2*)(Y + idx) = make_uint2(*(uint32_t*)&h0, *(uint32_t*)&h1);
}

// W(k,j) = W[(j/cph)*hstr + k*krs + j%cph]; out Yt[j, Kd] fp16 (transposed)
__global__ __launch_bounds__(256) void wsplit_kernel(
    const float* __restrict__ W, __half* __restrict__ Yt,
    int Kd, int cph, long long hstr, int krs)
{
    __shared__ float t[32][33];
    int k0 = blockIdx.y * 32, j0 = blockIdx.x * 32;
    int tx = threadIdx.x & 31, ty8 = threadIdx.x >> 5;
#pragma unroll
    for (int i = 0; i < 4; i++) {
        int kl = ty8 + i * 8;
        int j = j0 + tx;
        t[kl][tx] = W[(size_t)(j / cph) * hstr + (size_t)(k0 + kl) * krs + (j % cph)];
    }
    __syncthreads();
#pragma unroll
    for (int i = 0; i < 4; i++) {
        int j = j0 + ty8 + i * 8;
        int k = k0 + tx;
        Yt[(size_t)j * Kd + k] = __float2half(t[tx][ty8 + i * 8]);
    }
}

// ---------------- HMMA fp16 GEMM, K-chunk 64 ----------------
#define GSTAGES 3
#define STG_BYTES 32768
#define GEMM_SMEM (GSTAGES * STG_BYTES)

__global__ void __launch_bounds__(256, 2) gemm_hmma(
    const __half* __restrict__ A, const __half* __restrict__ Bw,
    float* __restrict__ C, int Kp, int Mpb, long long outBS, int rowOff, int ldc)
{
    extern __shared__ char smraw[];
    const uint32_t sb = smem_u32(smraw);
    const int tid = threadIdx.x;
    const int lane = tid & 31, wid = tid >> 5;
    const int wm = wid & 3, wn = wid >> 2;
    const int m0 = blockIdx.y * 128, n0 = blockIdx.x * 128;
    const int nIter = Kp >> 6;

    // cp.async mapping: idx = tid + p*256 (p<4): row = idx>>3, kchunk = idx&7
    const int crow = tid >> 3;            // base row for p=0 (rows 0..31)
    const int ckc = tid & 7;
    const uint32_t csw = gsw(crow, ckc);  // note: rows advance by 32 per p -> row&7 unchanged
    const __half* ga = A + (size_t)(m0 + crow) * Kp + ckc * 8;
    const __half* gb = Bw + (size_t)(n0 + crow) * Kp + ckc * 8;

    const int r8 = lane & 7, sel = lane >> 3;
    // A frag rows (2), B frag rows (4)
    uint32_t aRB[2]; int aRX[2];
    const int dselA = sel >> 1;
#pragma unroll
    for (int mf = 0; mf < 2; mf++) {
        int row = wm * 32 + mf * 16 + r8 + ((sel & 1) << 3);
        aRB[mf] = (uint32_t)(row * 128);
        aRX[mf] = row & 7;
    }
    uint32_t bRB[4]; int bRX[4];
    const int dselB = sel & 1;
#pragma unroll
    for (int np = 0; np < 4; np++) {
        int row = wn * 64 + np * 16 + r8 + ((sel >> 1) << 3);
        bRB[np] = 16384u + (uint32_t)(row * 128);
        bRX[np] = row & 7;
    }

    float acc[2][8][4];
#pragma unroll
    for (int mf = 0; mf < 2; mf++)
#pragma unroll
        for (int nf = 0; nf < 8; nf++)
#pragma unroll
            for (int q = 0; q < 4; q++) acc[mf][nf][q] = 0.f;

    // prologue: stages 0,1
#pragma unroll
    for (int s = 0; s < 2; s++) {
        uint32_t base = sb + (uint32_t)s * STG_BYTES;
        const __half* pa = ga + s * 64;
        const __half* pb = gb + s * 64;
#pragma unroll
        for (int p = 0; p < 4; p++) {
            uint32_t so = csw + (uint32_t)p * 4096u;   // +32 rows per p
            CP16(base + so, pa + (size_t)p * 32 * Kp);
            CP16(base + 16384u + so, pb + (size_t)p * 32 * Kp);
        }
        CP_COMMIT;
    }

    for (int it = 0; it < nIter; it++) {
        if (it + 2 < nIter) {
            int s = (it + 2) % GSTAGES;
            uint32_t base = sb + (uint32_t)s * STG_BYTES;
            const __half* pa = ga + (size_t)(it + 2) * 64;
            const __half* pb = gb + (size_t)(it + 2) * 64;
#pragma unroll
            for (int p = 0; p < 4; p++) {
                uint32_t so = csw + (uint32_t)p * 4096u;
                CP16(base + so, pa + (size_t)p * 32 * Kp);
                CP16(base + 16384u + so, pb + (size_t)p * 32 * Kp);
            }
        }
        CP_COMMIT;
        CP_WAIT2;
        __syncthreads();

        uint32_t sbase = sb + (uint32_t)(it % GSTAGES) * STG_BYTES;
#pragma unroll
        for (int ks = 0; ks < 4; ks++) {
            uint32_t af[2][4];
#pragma unroll
            for (int mf = 0; mf < 2; mf++)
                LDSM4(af[mf][0], af[mf][1], af[mf][2], af[mf][3],
                      sbase + aRB[mf] + (uint32_t)((((ks << 1) + dselA) ^ aRX[mf]) << 4));
            uint32_t bf[4][4];
#pragma unroll
            for (int np = 0; np < 4; np++)
                LDSM4(bf[np][0], bf[np][1], bf[np][2], bf[np][3],
                      sbase + bRB[np] + (uint32_t)((((ks << 1) + dselB) ^ bRX[np]) << 4));
#pragma unroll
            for (int mf = 0; mf < 2; mf++)
#pragma unroll
                for (int np = 0; np < 4; np++) {
                    MMAH16816(acc[mf][np * 2 + 0], af[mf], bf[np][0], bf[np][1]);
                    MMAH16816(acc[mf][np * 2 + 1], af[mf], bf[np][2], bf[np][3]);
                }
        }
        __syncthreads();
    }

#pragma unroll
    for (int mf = 0; mf < 2; mf++)
#pragma unroll
        for (int rh = 0; rh < 2; rh++) {
            int gr = m0 + wm * 32 + mf * 16 + (lane >> 2) + rh * 8;
            int bi = gr / Mpb;
            int rr = gr - bi * Mpb;
            float* rowp = C + (size_t)bi * outBS + (size_t)(rr + rowOff) * ldc
                        + n0 + wn * 64 + (lane & 3) * 2;
#pragma unroll
            for (int nf = 0; nf < 8; nf++) {
                float2 v = make_float2(acc[mf][nf][rh * 2 + 0], acc[mf][nf][rh * 2 + 1]);
                *(float2*)(rowp + nf * 8) = v;
            }
        }
}

// ---------------- RMS-norm (+RoPE) -> fp16 ----------------
__global__ __launch_bounds__(256) void rms_rope_h_kernel(
    const float* __restrict__ buf, __half* __restrict__ outh,
    const float* __restrict__ scale,
    int heads, int rowsPerBatch, int bufRPB, int rowStart, int doRope, float outScale)
{
    __shared__ float sh[256];
    __shared__ float ws[8];
    int idx = blockIdx.x;
    int head = idx % heads;
    int tmp = idx / heads;
    int t = tmp % rowsPerBatch;
    int b = tmp / rowsPerBatch;
    size_t off = ((size_t)((size_t)b * bufRPB + rowStart + t) * heads + head) * H_DIM;
    int h = threadIdx.x;
    float x = buf[off + h];
    float ss = x * x;
#pragma unroll
    for (int o = 16; o > 0; o >>= 1) ss += __shfl_xor_sync(0xffffffffu, ss, o);
    if ((h & 31) == 0) ws[h >> 5] = ss;
    __syncthreads();
    float tot = 0.f;
#pragma unroll
    for (int w = 0; w < 8; w++) tot += ws[w];
    float y = x * rsqrtf(tot * (1.f / 256.f) + 1e-6f) * (1.f + scale[h]);
    if (doRope) {
        sh[h] = y;
        __syncthreads();
        int i = h & 127;
        float ang = (float)t * exp2f(-(float)i * 0.10381025296522988f);
        float sn, cs;
        sincosf(ang, &sn, &cs);
        if (h < 128) y = sh[h] * cs - sh[h + 128] * sn;
        else         y = sh[h] * cs + sh[h - 128] * sn;
    }
    outh[off + h] = __float2half(y * outScale);
}

// ---------------- flash attention fp16 HMMA (epilogue -> fp16) ----------------
#define FH_K 32768u
#define FH_V 65536u
#define FH_STRIDE 65536u
#define FH_P 163840u
#define FH_RED 172032
#define FH_SMEM (172032 + 1536)

__global__ void __launch_bounds__(256, 1) flash_hmma(
    const __half* __restrict__ Qh, const __half* __restrict__ Kh,
    const __half* __restrict__ Vh, __half* __restrict__ Oh)
{
    extern __shared__ char smraw[];
    const uint32_t sb = smem_u32(smraw);
    float* red = (float*)(smraw + FH_RED);
    const int tid = threadIdx.x, lane = tid & 31, w = tid >> 5;
    const int wr = w & 3, wc = w >> 2;
    const int qt = blockIdx.x, n = blockIdx.y, b = blockIdx.z;
    const int kh = n >> 1, qbase = qt << 6;

    const char* qg = (const char*)(Qh + ((size_t)(b * T_LEN + qbase) * N_HEADS + n) * H_DIM);
#pragma unroll
    for (int p = 0; p < 8; p++) {
        int idx = tid + p * 256;
        int r = idx >> 5, c = idx & 31;
        CP16(sb + fsw(r, c * 16), qg + (size_t)r * (N_HEADS * H_DIM * 2) + c * 16);
    }
    if (tid < 64) { red[tid] = -INFINITY; red[64 + tid] = 0.f; }
    CP_COMMIT;

    const char* kg = (const char*)(Kh + ((size_t)b * S_LEN * K_HEADS + kh) * H_DIM);
    const char* vg = (const char*)(Vh + ((size_t)b * S_LEN * K_HEADS + kh) * H_DIM);
    const int kvstride = K_HEADS * H_DIM * 2;

    const int nSelf = qt + 1;
    const int nT = nSelf + (E_LEN >> 6);

#pragma unroll
    for (int p = 0; p < 8; p++) {
        int idx = tid + p * 256;
        int r = idx >> 5, c = idx & 31;
        uint32_t sw = fsw(r, c * 16);
        CP16(sb + FH_K + sw, kg + (size_t)r * kvstride + c * 16);
        CP16(sb + FH_V + sw, vg + (size_t)r * kvstride + c * 16);
    }
    CP_COMMIT;

    float oacc[16][4];
#pragma unroll
    for (int nf = 0; nf < 16; nf++)
#pragma unroll
        for (int q = 0; q < 4; q++) oacc[nf][q] = 0.f;

    const int r8 = lane & 7, sel = lane >> 3;
    const int rowA = wr * 16 + r8 + ((sel & 1) << 3);
    const int dselA = sel >> 1;
    const int rowB0 = wc * 32 + r8 + ((sel >> 1) << 3);
    const int dselB = sel & 1;
    const int r1 = wr * 16 + (lane >> 2), r2 = r1 + 8;

    for (int t = 0; t < nT; t++) {
        if (t + 1 < nT) {
            int s0n = (t + 1 < nSelf) ? ((t + 1) << 6) : (T_LEN + ((t + 1 - nSelf) << 6));
            uint32_t kb = sb + FH_K + (uint32_t)((t + 1) & 1) * FH_STRIDE;
            uint32_t vb = sb + FH_V + (uint32_t)((t + 1) & 1) * FH_STRIDE;
#pragma unroll
            for (int p = 0; p < 8; p++) {
                int idx = tid + p * 256;
                int r = idx >> 5, c = idx & 31;
                uint32_t sw = fsw(r, c * 16);
                CP16(kb + sw, kg + (size_t)(s0n + r) * kvstride + c * 16);
                CP16(vb + sw, vg + (size_t)(s0n + r) * kvstride + c * 16);
            }
            CP_COMMIT;
            CP_WAIT1;
        } else {
            CP_WAIT0;
        }
        __syncthreads();

        const int s0 = (t < nSelf) ? (t << 6) : (T_LEN + ((t - nSelf) << 6));
        const bool diag = (t == qt);
        const uint32_t sK = sb + FH_K + (uint32_t)(t & 1) * FH_STRIDE;
        const uint32_t sV = sb + FH_V + (uint32_t)(t & 1) * FH_STRIDE;
        const uint32_t aBase = sb + (uint32_t)rowA * 512u;
        const int rowAx = rowA & 7;

        float sacc[4][4];
#pragma unroll
        for (int nf = 0; nf < 4; nf++)
#pragma unroll
            for (int q = 0; q < 4; q++) sacc[nf][q] = 0.f;
#pragma unroll 4
        for (int ks = 0; ks < 16; ks++) {
            uint32_t a[4];
            LDSM4(a[0], a[1], a[2], a[3], aBase + (uint32_t)((((ks << 1) + dselA) ^ rowAx) << 4));
#pragma unroll
            for (int nf2 = 0; nf2 < 2; nf2++) {
                int rowB = rowB0 + nf2 * 16;
                uint32_t bb[4];
                LDSM4(bb[0], bb[1], bb[2], bb[3],
                      sK + (uint32_t)rowB * 512u + (uint32_t)((((ks << 1) + dselB) ^ (rowB & 7)) << 4));
                MMAH16816(sacc[nf2 * 2 + 0], a, bb[0], bb[1]);
                MMAH16816(sacc[nf2 * 2 + 1], a, bb[2], bb[3]);
            }
        }

        float mx1 = -INFINITY, mx2 = -INFINITY;
#pragma unroll
        for (int nf = 0; nf < 4; nf++)
#pragma unroll
            for (int e = 0; e < 4; e++) {
                float s = sacc[nf][e];
                float cpv = 50.f - __fdividef(100.f, __expf(0.04f * s) + 1.f);
                if (diag) {
                    int col = s0 + wc * 32 + nf * 8 + ((lane & 3) << 1) + (e & 1);
                    int row = qbase + ((e < 2) ? r1 : r2);
                    if (col > row) cpv = -INFINITY;
                }
                sacc[nf][e] = cpv;
                if (e < 2) mx1 = fmaxf(mx1, cpv); else mx2 = fmaxf(mx2, cpv);
            }
        mx1 = fmaxf(mx1, __shfl_xor_sync(0xffffffffu, mx1, 1));
        mx1 = fmaxf(mx1, __shfl_xor_sync(0xffffffffu, mx1, 2));
        mx2 = fmaxf(mx2, __shfl_xor_sync(0xffffffffu, mx2, 1));
        mx2 = fmaxf(mx2, __shfl_xor_sync(0xffffffffu, mx2, 2));
        if ((lane & 3) == 0) { red[128 + wc * 64 + r1] = mx1; red[128 + wc * 64 + r2] = mx2; }
        __syncthreads();

        float m1o = red[r1], m2o = red[r2];
        float mn1 = fmaxf(m1o, fmaxf(red[128 + r1], red[128 + 64 + r1]));
        float mn2 = fmaxf(m2o, fmaxf(red[128 + r2], red[128 + 64 + r2]));
        float corr1 = __expf(m1o - mn1), corr2 = __expf(m2o - mn2);

        float sum1 = 0.f, sum2 = 0.f;
        const uint32_t pwb = sb + FH_P;
#pragma unroll
        for (int nf = 0; nf < 4; nf++) {
            float p0 = __expf(sacc[nf][0] - mn1);
            float p1 = __expf(sacc[nf][1] - mn1);
            float p2 = __expf(sacc[nf][2] - mn2);
            float p3 = __expf(sacc[nf][3] - mn2);
            sum1 += p0 + p1; sum2 += p2 + p3;
            __half2 hA = __floats2half2_rn(p0, p1);
            __half2 hB = __floats2half2_rn(p2, p3);
            int chunk = wc * 4 + nf;
            uint32_t a1 = pwb + (uint32_t)r1 * 128u + (uint32_t)((chunk ^ (r1 & 7)) << 4) + ((lane & 3) << 2);
            uint32_t a2 = pwb + (uint32_t)r2 * 128u + (uint32_t)((chunk ^ (r2 & 7)) << 4) + ((lane & 3) << 2);
            asm volatile("st.shared.b32 [%0], %1;" :: "r"(a1), "r"(*(uint32_t*)&hA) : "memory");
            asm volatile("st.shared.b32 [%0], %1;" :: "r"(a2), "r"(*(uint32_t*)&hB) : "memory");
        }
        sum1 += __shfl_xor_sync(0xffffffffu, sum1, 1);
        sum1 += __shfl_xor_sync(0xffffffffu, sum1, 2);
        sum2 += __shfl_xor_sync(0xffffffffu, sum2, 1);
        sum2 += __shfl_xor_sync(0xffffffffu, sum2, 2);
        if ((lane & 3) == 0) { red[256 + wc * 64 + r1] = sum1; red[256 + wc * 64 + r2] = sum2; }

#pragma unroll
        for (int nf = 0; nf < 16; nf++) {
            oacc[nf][0] *= corr1; oacc[nf][1] *= corr1;
            oacc[nf][2] *= corr2; oacc[nf][3] *= corr2;
        }
        __syncthreads();

        if (wc == 0 && (lane & 3) == 0) {
            red[64 + r1] = red[64 + r1] * corr1 + red[256 + r1] + red[256 + 64 + r1];
            red[64 + r2] = red[64 + r2] * corr2 + red[256 + r2] + red[256 + 64 + r2];
            red[r1] = mn1; red[r2] = mn2;
        }

        const uint32_t paBase = pwb + (uint32_t)rowA * 128u;
        const int rowAp = rowA & 7;
#pragma unroll
        for (int ks = 0; ks < 4; ks++) {
            uint32_t a[4];
            LDSM4(a[0], a[1], a[2], a[3], paBase + (uint32_t)((((ks << 1) + dselA) ^ rowAp) << 4));
#pragma unroll
            for (int nf2 = 0; nf2 < 8; nf2++) {
                int rowV = ks * 16 + r8 + ((sel & 1) << 3);
                int chunk = wc * 16 + nf2 * 2 + (sel >> 1);
                uint32_t bb[4];
                LDSM4T(bb[0], bb[1], bb[2], bb[3],
                       sV + (uint32_t)rowV * 512u + (uint32_t)((chunk ^ (rowV & 7)) << 4));
                MMAH16816(oacc[nf2 * 2 + 0], a, bb[0], bb[1]);
                MMAH16816(oacc[nf2 * 2 + 1], a, bb[2], bb[3]);
            }
        }
        __syncthreads();
    }

    // epilogue: write fp16 directly (O-GEMM input layout [tok, N*H])
    float inv1 = 1.f / red[64 + r1];
    float inv2 = 1.f / red[64 + r2];
    int t1 = qbase + r1, t2 = qbase + r2;
    __half* o1 = Oh + ((size_t)(b * T_LEN + t1)) * (N_HEADS * H_DIM) + n * H_DIM + wc * 128 + ((lane & 3) << 1);
    __half* o2 = Oh + ((size_t)(b * T_LEN + t2)) * (N_HEADS * H_DIM) + n * H_DIM + wc * 128 + ((lane & 3) << 1);
#pragma unroll
    for (int nf = 0; nf < 16; nf++) {
        __half2 v1 = __floats2half2_rn(oacc[nf][0] * inv1, oacc[nf][1] * inv1);
        __half2 v2 = __floats2half2_rn(oacc[nf][2] * inv2, oacc[nf][3] * inv2);
        *(__half2*)(o1 + nf * 8) = v1;
        *(__half2*)(o2 + nf * 8) = v2;
    }
}

// ---------------- launch ----------------
extern "C" void kernel_launch(void* const* d_in, const int* in_sizes, int n_in,
                              void* d_out, int out_size)
{
    (void)in_sizes; (void)n_in; (void)out_size;
    const float* hs  = (const float*)d_in[0];
    const float* enc = (const float*)d_in[1];
    const float* qw  = (const float*)d_in[4];
    const float* kw  = (const float*)d_in[5];
    const float* vw  = (const float*)d_in[6];
    const float* ow  = (const float*)d_in[7];
    const float* qsc = (const float*)d_in[8];
    const float* ksc = (const float*)d_in[9];
    float* out = (float*)d_out;

    float *qb, *kb, *vb;
    cudaGetSymbolAddress((void**)&qb, g_q);
    cudaGetSymbolAddress((void**)&kb, g_k);
    cudaGetSymbolAddress((void**)&vb, g_v);
    __half *q16, *k16, *v16;
    cudaGetSymbolAddress((void**)&q16, g_q16);
    cudaGetSymbolAddress((void**)&k16, g_k16);
    cudaGetSymbolAddress((void**)&v16, g_v16);
    __half *hs2, *enc2, *qw2, *kw2, *vw2, *ow2, *at2;
    cudaGetSymbolAddress((void**)&hs2, g_hs2);
    cudaGetSymbolAddress((void**)&enc2, g_enc2);
    cudaGetSymbolAddress((void**)&qw2, g_qw2);
    cudaGetSymbolAddress((void**)&kw2, g_kw2);
    cudaGetSymbolAddress((void**)&vw2, g_vw2);
    cudaGetSymbolAddress((void**)&ow2, g_ow2);
    cudaGetSymbolAddress((void**)&at2, g_at2);

    static int cfg = 0;
    if (!cfg) {
        cudaFuncSetAttribute(gemm_hmma, cudaFuncAttributeMaxDynamicSharedMemorySize, GEMM_SMEM);
        cudaFuncSetAttribute(flash_hmma, cudaFuncAttributeMaxDynamicSharedMemorySize, FH_SMEM);
        cfg = 1;
    }

    // converts
    a2h_kernel<<<(4096LL * 2048) / 1024, 256>>>(hs, hs2);
    a2h_kernel<<<(4096LL * 2048) / 1024, 256>>>(enc, enc2);
    wsplit_kernel<<<dim3(4096 / 32, D_DIM / 32), 256>>>(qw, qw2, D_DIM, H_DIM, (long long)D_DIM * H_DIM, H_DIM);
    wsplit_kernel<<<dim3(2048 / 32, D_DIM / 32), 256>>>(kw, kw2, D_DIM, H_DIM, (long long)D_DIM * H_DIM, H_DIM);
    wsplit_kernel<<<dim3(2048 / 32, D_DIM / 32), 256>>>(vw, vw2, D_DIM, H_DIM, (long long)D_DIM * H_DIM, H_DIM);
    wsplit_kernel<<<dim3(2048 / 32, 4096 / 32), 256>>>(ow, ow2, 4096, D_DIM, 0LL, D_DIM);

    const long long kvBS = (long long)S_LEN * K_HEADS * H_DIM;
    gemm_hmma<<<dim3(32, 32), 256, GEMM_SMEM>>>(hs2, qw2, qb, 2048, 4096, 0LL, 0, 4096);
    gemm_hmma<<<dim3(16, 32), 256, GEMM_SMEM>>>(hs2, kw2, kb, 2048, T_LEN, kvBS, 0, 2048);
    gemm_hmma<<<dim3(16, 32), 256, GEMM_SMEM>>>(hs2, vw2, vb, 2048, T_LEN, kvBS, 0, 2048);
    gemm_hmma<<<dim3(16, 32), 256, GEMM_SMEM>>>(enc2, kw2, kb, 2048, E_LEN, kvBS, T_LEN, 2048);
    gemm_hmma<<<dim3(16, 32), 256, GEMM_SMEM>>>(enc2, vw2, vb, 2048, E_LEN, kvBS, T_LEN, 2048);

    // rms(+rope) -> fp16 operands
    rms_rope_h_kernel<<<B_SZ * T_LEN * N_HEADS, 256>>>(qb, q16, qsc, N_HEADS, T_LEN, T_LEN, 0, 1, 0.0625f);
    rms_rope_h_kernel<<<B_SZ * T_LEN * K_HEADS, 256>>>(kb, k16, ksc, K_HEADS, T_LEN, S_LEN, 0, 1, 1.0f);
    rms_rope_h_kernel<<<B_SZ * E_LEN * K_HEADS, 256>>>(kb, k16, ksc, K_HEADS, E_LEN, S_LEN, T_LEN, 0, 1.0f);
    a2h_kernel<<<(B_SZ * S_LEN * K_HEADS * H_DIM) / 1024, 256>>>(vb, v16);

    // flash -> fp16 at2 directly
    flash_hmma<<<dim3(T_LEN / 64, N_HEADS, B_SZ), 256, FH_SMEM>>>(q16, k16, v16, at2);

    // O = attn @ ow  (fp16, K = 4096)
    gemm_hmma<<<dim3(16, 32), 256, GEMM_SMEM>>>(at2, ow2, out, 4096, 4096, 0LL, 0, 2048);
}

// round 9
// speedup vs baseline: 7.9987x; 1.1665x over previous
#include <cuda_runtime.h>
#include <cuda_fp16.h>
#include <stdint.h>
#include <math.h>

#define B_SZ 4
#define T_LEN 1024
#define E_LEN 1024
#define S_LEN 2048
#define D_DIM 2048
#define H_DIM 256
#define N_HEADS 16
#define K_HEADS 8

// fp32 scratch
__device__ float g_q[(size_t)B_SZ * T_LEN * N_HEADS * H_DIM];
__device__ float g_k[(size_t)B_SZ * S_LEN * K_HEADS * H_DIM];
// fp16 attention operands
__device__ __half g_q16[(size_t)B_SZ * T_LEN * N_HEADS * H_DIM];
__device__ __half g_k16[(size_t)B_SZ * S_LEN * K_HEADS * H_DIM];
__device__ __half g_v16[(size_t)B_SZ * S_LEN * K_HEADS * H_DIM];
// fp16 GEMM operands
__device__ __half g_hs2 [(size_t)4096 * 2048];
__device__ __half g_enc2[(size_t)4096 * 2048];
__device__ __half g_qw2 [(size_t)4096 * 2048];
__device__ __half g_kw2 [(size_t)2048 * 2048];
__device__ __half g_vw2 [(size_t)2048 * 2048];
__device__ __half g_ow2 [(size_t)2048 * 4096];
__device__ __half g_at2 [(size_t)4096 * 4096];

// ---------------- helpers ----------------
__device__ __forceinline__ uint32_t smem_u32(const void* p) {
    uint32_t a;
    asm("{ .reg .u64 t; cvta.to.shared.u64 t, %1; cvt.u32.u64 %0, t; }" : "=r"(a) : "l"(p));
    return a;
}
#define CP16(dst, src) \
    asm volatile("cp.async.cg.shared.global [%0], [%1], 16;" :: "r"(dst), "l"(src) : "memory")
#define CP_COMMIT asm volatile("cp.async.commit_group;" ::: "memory")
#define CP_WAIT2  asm volatile("cp.async.wait_group 2;" ::: "memory")
#define CP_WAIT1  asm volatile("cp.async.wait_group 1;" ::: "memory")
#define CP_WAIT0  asm volatile("cp.async.wait_group 0;" ::: "memory")
#define LDSM4(r0, r1, r2, r3, addr) \
    asm volatile("ldmatrix.sync.aligned.m8n8.x4.shared.b16 {%0,%1,%2,%3}, [%4];" \
        : "=r"(r0), "=r"(r1), "=r"(r2), "=r"(r3) : "r"(addr))
#define LDSM4T(r0, r1, r2, r3, addr) \
    asm volatile("ldmatrix.sync.aligned.m8n8.x4.trans.shared.b16 {%0,%1,%2,%3}, [%4];" \
        : "=r"(r0), "=r"(r1), "=r"(r2), "=r"(r3) : "r"(addr))
#define MMAH16816(d, a, b0, b1) \
    asm volatile("mma.sync.aligned.m16n8k16.row.col.f32.f16.f16.f32 " \
        "{%0,%1,%2,%3}, {%4,%5,%6,%7}, {%8,%9}, {%0,%1,%2,%3};" \
        : "+f"((d)[0]), "+f"((d)[1]), "+f"((d)[2]), "+f"((d)[3]) \
        : "r"((a)[0]), "r"((a)[1]), "r"((a)[2]), "r"((a)[3]), "r"(b0), "r"(b1))

__device__ __forceinline__ uint32_t gsw(int row, int kchunk) {
    return (uint32_t)(row * 128 + ((kchunk ^ (row & 7)) << 4));
}
__device__ __forceinline__ uint32_t fsw(int row, int kbyte) {
    return (uint32_t)(row * 512 + ((((kbyte >> 4) ^ (row & 7))) << 4) + (kbyte & 15));
}

// ---------------- convert kernels ----------------
__global__ __launch_bounds__(256) void a2h_kernel(
    const float* __restrict__ X, __half* __restrict__ Y)
{
    size_t idx = ((size_t)blockIdx.x * 256 + threadIdx.x) * 4;
    float4 v = *(const float4*)(X + idx);
    __half2 h0 = __floats2half2_rn(v.x, v.y);
    __half2 h1 = __floats2half2_rn(v.z, v.w);
    *(uint2*)(Y + idx) = make_uint2(*(uint32_t*)&h0, *(uint32_t*)&h1);
}

// W(k,j) = W[(j/cph)*hstr + k*krs + j%cph]; out Yt[j, Kd] fp16 (transposed)
__global__ __launch_bounds__(256) void wsplit_kernel(
    const float* __restrict__ W, __half* __restrict__ Yt,
    int Kd, int cph, long long hstr, int krs)
{
    __shared__ float t[32][33];
    int k0 = blockIdx.y * 32, j0 = blockIdx.x * 32;
    int tx = threadIdx.x & 31, ty8 = threadIdx.x >> 5;
#pragma unroll
    for (int i = 0; i < 4; i++) {
        int kl = ty8 + i * 8;
        int j = j0 + tx;
        t[kl][tx] = W[(size_t)(j / cph) * hstr + (size_t)(k0 + kl) * krs + (j % cph)];
    }
    __syncthreads();
#pragma unroll
    for (int i = 0; i < 4; i++) {
        int j = j0 + ty8 + i * 8;
        int k = k0 + tx;
        Yt[(size_t)j * Kd + k] = __float2half(t[tx][ty8 + i * 8]);
    }
}

// ---------------- HMMA fp16 GEMM: 128x128x64, 4 warps, warp tile 64x64 ----------------
#define GSTAGES 3
#define STG_BYTES 32768
#define GEMM_SMEM (GSTAGES * STG_BYTES)

__global__ void __launch_bounds__(128, 2) gemm_hmma(
    const __half* __restrict__ A, const __half* __restrict__ Bw,
    void* __restrict__ Cv, int Kp, int Mpb, long long outBS, int rowOff, int ldc,
    int outHalf)
{
    extern __shared__ char smraw[];
    const uint32_t sb = smem_u32(smraw);
    const int tid = threadIdx.x;
    const int lane = tid & 31, wid = tid >> 5;
    const int wm = wid & 1, wn = wid >> 1;
    const int m0 = blockIdx.y * 128, n0 = blockIdx.x * 128;
    const int nIter = Kp >> 6;

    // cp.async mapping: 128 threads, idx = tid + p*128 -> row = idx>>3 (+16/p), kchunk = tid&7
    const int crow = tid >> 3;           // 0..15
    const int ckc = tid & 7;
    const uint32_t csw = gsw(crow, ckc); // row&7 invariant under +16 rows
    const __half* ga = A + (size_t)(m0 + crow) * Kp + ckc * 8;
    const __half* gb = Bw + (size_t)(n0 + crow) * Kp + ckc * 8;

    const int r8 = lane & 7, sel = lane >> 3;
    uint32_t aRB[4]; int aRX[4];
    const int dselA = sel >> 1;
#pragma unroll
    for (int mf = 0; mf < 4; mf++) {
        int row = wm * 64 + mf * 16 + r8 + ((sel & 1) << 3);
        aRB[mf] = (uint32_t)(row * 128);
        aRX[mf] = row & 7;
    }
    uint32_t bRB[4]; int bRX[4];
    const int dselB = sel & 1;
#pragma unroll
    for (int np = 0; np < 4; np++) {
        int row = wn * 64 + np * 16 + r8 + ((sel >> 1) << 3);
        bRB[np] = 16384u + (uint32_t)(row * 128);
        bRX[np] = row & 7;
    }

    float acc[4][8][4];
#pragma unroll
    for (int mf = 0; mf < 4; mf++)
#pragma unroll
        for (int nf = 0; nf < 8; nf++)
#pragma unroll
            for (int q = 0; q < 4; q++) acc[mf][nf][q] = 0.f;

    // prologue: stages 0,1
#pragma unroll
    for (int s = 0; s < 2; s++) {
        uint32_t base = sb + (uint32_t)s * STG_BYTES;
        const __half* pa = ga + s * 64;
        const __half* pb = gb + s * 64;
#pragma unroll
        for (int p = 0; p < 8; p++) {
            uint32_t so = csw + (uint32_t)p * 2048u;   // +16 rows per p
            CP16(base + so, pa + (size_t)p * 16 * Kp);
            CP16(base + 16384u + so, pb + (size_t)p * 16 * Kp);
        }
        CP_COMMIT;
    }

    for (int it = 0; it < nIter; it++) {
        if (it + 2 < nIter) {
            int s = (it + 2) % GSTAGES;
            uint32_t base = sb + (uint32_t)s * STG_BYTES;
            const __half* pa = ga + (size_t)(it + 2) * 64;
            const __half* pb = gb + (size_t)(it + 2) * 64;
#pragma unroll
            for (int p = 0; p < 8; p++) {
                uint32_t so = csw + (uint32_t)p * 2048u;
                CP16(base + so, pa + (size_t)p * 16 * Kp);
                CP16(base + 16384u + so, pb + (size_t)p * 16 * Kp);
            }
        }
        CP_COMMIT;
        CP_WAIT2;
        __syncthreads();

        uint32_t sbase = sb + (uint32_t)(it % GSTAGES) * STG_BYTES;
#pragma unroll
        for (int ks = 0; ks < 4; ks++) {
            uint32_t af[4][4];
#pragma unroll
            for (int mf = 0; mf < 4; mf++)
                LDSM4(af[mf][0], af[mf][1], af[mf][2], af[mf][3],
                      sbase + aRB[mf] + (uint32_t)((((ks << 1) + dselA) ^ aRX[mf]) << 4));
            uint32_t bf[4][4];
#pragma unroll
            for (int np = 0; np < 4; np++)
                LDSM4(bf[np][0], bf[np][1], bf[np][2], bf[np][3],
                      sbase + bRB[np] + (uint32_t)((((ks << 1) + dselB) ^ bRX[np]) << 4));
#pragma unroll
            for (int mf = 0; mf < 4; mf++)
#pragma unroll
                for (int np = 0; np < 4; np++) {
                    MMAH16816(acc[mf][np * 2 + 0], af[mf], bf[np][0], bf[np][1]);
                    MMAH16816(acc[mf][np * 2 + 1], af[mf], bf[np][2], bf[np][3]);
                }
        }
        __syncthreads();
    }

#pragma unroll
    for (int mf = 0; mf < 4; mf++)
#pragma unroll
        for (int rh = 0; rh < 2; rh++) {
            int gr = m0 + wm * 64 + mf * 16 + (lane >> 2) + rh * 8;
            int bi = gr / Mpb;
            int rr = gr - bi * Mpb;
            size_t base = (size_t)bi * outBS + (size_t)(rr + rowOff) * ldc
                        + n0 + wn * 64 + (lane & 3) * 2;
            if (outHalf) {
                __half* rowp = (__half*)Cv + base;
#pragma unroll
                for (int nf = 0; nf < 8; nf++) {
                    __half2 v = __floats2half2_rn(acc[mf][nf][rh * 2 + 0], acc[mf][nf][rh * 2 + 1]);
                    *(__half2*)(rowp + nf * 8) = v;
                }
            } else {
                float* rowp = (float*)Cv + base;
#pragma unroll
                for (int nf = 0; nf < 8; nf++) {
                    float2 v = make_float2(acc[mf][nf][rh * 2 + 0], acc[mf][nf][rh * 2 + 1]);
                    *(float2*)(rowp + nf * 8) = v;
                }
            }
        }
}

// ---------------- RMS-norm (+RoPE) -> fp16, warp-per-row ----------------
__global__ __launch_bounds__(256) void rms_rope_w_kernel(
    const float* __restrict__ buf, __half* __restrict__ outh,
    const float* __restrict__ scale,
    int heads, int rowsPerBatch, int bufRPB, int rowStart, int doRope, float outScale)
{
    int rowIdx = blockIdx.x * 8 + (threadIdx.x >> 5);
    int lane = threadIdx.x & 31;
    int head = rowIdx % heads;
    int tmp = rowIdx / heads;
    int t = tmp % rowsPerBatch;
    int b = tmp / rowsPerBatch;
    size_t off = ((size_t)((size_t)b * bufRPB + rowStart + t) * heads + head) * H_DIM;

    float4 x1 = *(const float4*)(buf + off + lane * 4);
    float4 x2 = *(const float4*)(buf + off + 128 + lane * 4);
    float ss = x1.x * x1.x + x1.y * x1.y + x1.z * x1.z + x1.w * x1.w
             + x2.x * x2.x + x2.y * x2.y + x2.z * x2.z + x2.w * x2.w;
#pragma unroll
    for (int o = 16; o > 0; o >>= 1) ss += __shfl_xor_sync(0xffffffffu, ss, o);
    float rinv = rsqrtf(ss * (1.f / 256.f) + 1e-6f) * outScale;

    float4 s1 = *(const float4*)(scale + lane * 4);
    float4 s2 = *(const float4*)(scale + 128 + lane * 4);
    float y1[4] = { x1.x * rinv * (1.f + s1.x), x1.y * rinv * (1.f + s1.y),
                    x1.z * rinv * (1.f + s1.z), x1.w * rinv * (1.f + s1.w) };
    float y2[4] = { x2.x * rinv * (1.f + s2.x), x2.y * rinv * (1.f + s2.y),
                    x2.z * rinv * (1.f + s2.z), x2.w * rinv * (1.f + s2.w) };
    float o1[4], o2[4];
    if (doRope) {
#pragma unroll
        for (int i = 0; i < 4; i++) {
            float ang = (float)t * exp2f(-(float)(lane * 4 + i) * 0.10381025296522988f);
            float sn, cs;
            sincosf(ang, &sn, &cs);
            o1[i] = y1[i] * cs - y2[i] * sn;
            o2[i] = y2[i] * cs + y1[i] * sn;
        }
    } else {
#pragma unroll
        for (int i = 0; i < 4; i++) { o1[i] = y1[i]; o2[i] = y2[i]; }
    }
    __half2 a0 = __floats2half2_rn(o1[0], o1[1]);
    __half2 a1 = __floats2half2_rn(o1[2], o1[3]);
    __half2 b0 = __floats2half2_rn(o2[0], o2[1]);
    __half2 b1 = __floats2half2_rn(o2[2], o2[3]);
    *(uint2*)(outh + off + lane * 4) = make_uint2(*(uint32_t*)&a0, *(uint32_t*)&a1);
    *(uint2*)(outh + off + 128 + lane * 4) = make_uint2(*(uint32_t*)&b0, *(uint32_t*)&b1);
}

// ---------------- flash attention fp16 HMMA (unchanged R8) ----------------
#define FH_K 32768u
#define FH_V 65536u
#define FH_STRIDE 65536u
#define FH_P 163840u
#define FH_RED 172032
#define FH_SMEM (172032 + 1536)

__global__ void __launch_bounds__(256, 1) flash_hmma(
    const __half* __restrict__ Qh, const __half* __restrict__ Kh,
    const __half* __restrict__ Vh, __half* __restrict__ Oh)
{
    extern __shared__ char smraw[];
    const uint32_t sb = smem_u32(smraw);
    float* red = (float*)(smraw + FH_RED);
    const int tid = threadIdx.x, lane = tid & 31, w = tid >> 5;
    const int wr = w & 3, wc = w >> 2;
    const int qt = blockIdx.x, n = blockIdx.y, b = blockIdx.z;
    const int kh = n >> 1, qbase = qt << 6;

    const char* qg = (const char*)(Qh + ((size_t)(b * T_LEN + qbase) * N_HEADS + n) * H_DIM);
#pragma unroll
    for (int p = 0; p < 8; p++) {
        int idx = tid + p * 256;
        int r = idx >> 5, c = idx & 31;
        CP16(sb + fsw(r, c * 16), qg + (size_t)r * (N_HEADS * H_DIM * 2) + c * 16);
    }
    if (tid < 64) { red[tid] = -INFINITY; red[64 + tid] = 0.f; }
    CP_COMMIT;

    const char* kg = (const char*)(Kh + ((size_t)b * S_LEN * K_HEADS + kh) * H_DIM);
    const char* vg = (const char*)(Vh + ((size_t)b * S_LEN * K_HEADS + kh) * H_DIM);
    const int kvstride = K_HEADS * H_DIM * 2;

    const int nSelf = qt + 1;
    const int nT = nSelf + (E_LEN >> 6);

#pragma unroll
    for (int p = 0; p < 8; p++) {
        int idx = tid + p * 256;
        int r = idx >> 5, c = idx & 31;
        uint32_t sw = fsw(r, c * 16);
        CP16(sb + FH_K + sw, kg + (size_t)r * kvstride + c * 16);
        CP16(sb + FH_V + sw, vg + (size_t)r * kvstride + c * 16);
    }
    CP_COMMIT;

    float oacc[16][4];
#pragma unroll
    for (int nf = 0; nf < 16; nf++)
#pragma unroll
        for (int q = 0; q < 4; q++) oacc[nf][q] = 0.f;

    const int r8 = lane & 7, sel = lane >> 3;
    const int rowA = wr * 16 + r8 + ((sel & 1) << 3);
    const int dselA = sel >> 1;
    const int rowB0 = wc * 32 + r8 + ((sel >> 1) << 3);
    const int dselB = sel & 1;
    const int r1 = wr * 16 + (lane >> 2), r2 = r1 + 8;

    for (int t = 0; t < nT; t++) {
        if (t + 1 < nT) {
            int s0n = (t + 1 < nSelf) ? ((t + 1) << 6) : (T_LEN + ((t + 1 - nSelf) << 6));
            uint32_t kb = sb + FH_K + (uint32_t)((t + 1) & 1) * FH_STRIDE;
            uint32_t vb = sb + FH_V + (uint32_t)((t + 1) & 1) * FH_STRIDE;
#pragma unroll
            for (int p = 0; p < 8; p++) {
                int idx = tid + p * 256;
                int r = idx >> 5, c = idx & 31;
                uint32_t sw = fsw(r, c * 16);
                CP16(kb + sw, kg + (size_t)(s0n + r) * kvstride + c * 16);
                CP16(vb + sw, vg + (size_t)(s0n + r) * kvstride + c * 16);
            }
            CP_COMMIT;
            CP_WAIT1;
        } else {
            CP_WAIT0;
        }
        __syncthreads();

        const int s0 = (t < nSelf) ? (t << 6) : (T_LEN + ((t - nSelf) << 6));
        const bool diag = (t == qt);
        const uint32_t sK = sb + FH_K + (uint32_t)(t & 1) * FH_STRIDE;
        const uint32_t sV = sb + FH_V + (uint32_t)(t & 1) * FH_STRIDE;
        const uint32_t aBase = sb + (uint32_t)rowA * 512u;
        const int rowAx = rowA & 7;

        float sacc[4][4];
#pragma unroll
        for (int nf = 0; nf < 4; nf++)
#pragma unroll
            for (int q = 0; q < 4; q++) sacc[nf][q] = 0.f;
#pragma unroll 4
        for (int ks = 0; ks < 16; ks++) {
            uint32_t a[4];
            LDSM4(a[0], a[1], a[2], a[3], aBase + (uint32_t)((((ks << 1) + dselA) ^ rowAx) << 4));
#pragma unroll
            for (int nf2 = 0; nf2 < 2; nf2++) {
                int rowB = rowB0 + nf2 * 16;
                uint32_t bb[4];
                LDSM4(bb[0], bb[1], bb[2], bb[3],
                      sK + (uint32_t)rowB * 512u + (uint32_t)((((ks << 1) + dselB) ^ (rowB & 7)) << 4));
                MMAH16816(sacc[nf2 * 2 + 0], a, bb[0], bb[1]);
                MMAH16816(sacc[nf2 * 2 + 1], a, bb[2], bb[3]);
            }
        }

        float mx1 = -INFINITY, mx2 = -INFINITY;
#pragma unroll
        for (int nf = 0; nf < 4; nf++)
#pragma unroll
            for (int e = 0; e < 4; e++) {
                float s = sacc[nf][e];
                float cpv = 50.f - __fdividef(100.f, __expf(0.04f * s) + 1.f);
                if (diag) {
                    int col = s0 + wc * 32 + nf * 8 + ((lane & 3) << 1) + (e & 1);
                    int row = qbase + ((e < 2) ? r1 : r2);
                    if (col > row) cpv = -INFINITY;
                }
                sacc[nf][e] = cpv;
                if (e < 2) mx1 = fmaxf(mx1, cpv); else mx2 = fmaxf(mx2, cpv);
            }
        mx1 = fmaxf(mx1, __shfl_xor_sync(0xffffffffu, mx1, 1));
        mx1 = fmaxf(mx1, __shfl_xor_sync(0xffffffffu, mx1, 2));
        mx2 = fmaxf(mx2, __shfl_xor_sync(0xffffffffu, mx2, 1));
        mx2 = fmaxf(mx2, __shfl_xor_sync(0xffffffffu, mx2, 2));
        if ((lane & 3) == 0) { red[128 + wc * 64 + r1] = mx1; red[128 + wc * 64 + r2] = mx2; }
        __syncthreads();

        float m1o = red[r1], m2o = red[r2];
        float mn1 = fmaxf(m1o, fmaxf(red[128 + r1], red[128 + 64 + r1]));
        float mn2 = fmaxf(m2o, fmaxf(red[128 + r2], red[128 + 64 + r2]));
        float corr1 = __expf(m1o - mn1), corr2 = __expf(m2o - mn2);

        float sum1 = 0.f, sum2 = 0.f;
        const uint32_t pwb = sb + FH_P;
#pragma unroll
        for (int nf = 0; nf < 4; nf++) {
            float p0 = __expf(sacc[nf][0] - mn1);
            float p1 = __expf(sacc[nf][1] - mn1);
            float p2 = __expf(sacc[nf][2] - mn2);
            float p3 = __expf(sacc[nf][3] - mn2);
            sum1 += p0 + p1; sum2 += p2 + p3;
            __half2 hA = __floats2half2_rn(p0, p1);
            __half2 hB = __floats2half2_rn(p2, p3);
            int chunk = wc * 4 + nf;
            uint32_t a1 = pwb + (uint32_t)r1 * 128u + (uint32_t)((chunk ^ (r1 & 7)) << 4) + ((lane & 3) << 2);
            uint32_t a2 = pwb + (uint32_t)r2 * 128u + (uint32_t)((chunk ^ (r2 & 7)) << 4) + ((lane & 3) << 2);
            asm volatile("st.shared.b32 [%0], %1;" :: "r"(a1), "r"(*(uint32_t*)&hA) : "memory");
            asm volatile("st.shared.b32 [%0], %1;" :: "r"(a2), "r"(*(uint32_t*)&hB) : "memory");
        }
        sum1 += __shfl_xor_sync(0xffffffffu, sum1, 1);
        sum1 += __shfl_xor_sync(0xffffffffu, sum1, 2);
        sum2 += __shfl_xor_sync(0xffffffffu, sum2, 1);
        sum2 += __shfl_xor_sync(0xffffffffu, sum2, 2);
        if ((lane & 3) == 0) { red[256 + wc * 64 + r1] = sum1; red[256 + wc * 64 + r2] = sum2; }

#pragma unroll
        for (int nf = 0; nf < 16; nf++) {
            oacc[nf][0] *= corr1; oacc[nf][1] *= corr1;
            oacc[nf][2] *= corr2; oacc[nf][3] *= corr2;
        }
        __syncthreads();

        if (wc == 0 && (lane & 3) == 0) {
            red[64 + r1] = red[64 + r1] * corr1 + red[256 + r1] + red[256 + 64 + r1];
            red[64 + r2] = red[64 + r2] * corr2 + red[256 + r2] + red[256 + 64 + r2];
            red[r1] = mn1; red[r2] = mn2;
        }

        const uint32_t paBase = pwb + (uint32_t)rowA * 128u;
        const int rowAp = rowA & 7;
#pragma unroll
        for (int ks = 0; ks < 4; ks++) {
            uint32_t a[4];
            LDSM4(a[0], a[1], a[2], a[3], paBase + (uint32_t)((((ks << 1) + dselA) ^ rowAp) << 4));
#pragma unroll
            for (int nf2 = 0; nf2 < 8; nf2++) {
                int rowV = ks * 16 + r8 + ((sel & 1) << 3);
                int chunk = wc * 16 + nf2 * 2 + (sel >> 1);
                uint32_t bb[4];
                LDSM4T(bb[0], bb[1], bb[2], bb[3],
                       sV + (uint32_t)rowV * 512u + (uint32_t)((chunk ^ (rowV & 7)) << 4));
                MMAH16816(oacc[nf2 * 2 + 0], a, bb[0], bb[1]);
                MMAH16816(oacc[nf2 * 2 + 1], a, bb[2], bb[3]);
            }
        }
        __syncthreads();
    }

    float inv1 = 1.f / red[64 + r1];
    float inv2 = 1.f / red[64 + r2];
    int t1 = qbase + r1, t2 = qbase + r2;
    __half* o1 = Oh + ((size_t)(b * T_LEN + t1)) * (N_HEADS * H_DIM) + n * H_DIM + wc * 128 + ((lane & 3) << 1);
    __half* o2 = Oh + ((size_t)(b * T_LEN + t2)) * (N_HEADS * H_DIM) + n * H_DIM + wc * 128 + ((lane & 3) << 1);
#pragma unroll
    for (int nf = 0; nf < 16; nf++) {
        __half2 v1 = __floats2half2_rn(oacc[nf][0] * inv1, oacc[nf][1] * inv1);
        __half2 v2 = __floats2half2_rn(oacc[nf][2] * inv2, oacc[nf][3] * inv2);
        *(__half2*)(o1 + nf * 8) = v1;
        *(__half2*)(o2 + nf * 8) = v2;
    }
}

// ---------------- launch ----------------
extern "C" void kernel_launch(void* const* d_in, const int* in_sizes, int n_in,
                              void* d_out, int out_size)
{
    (void)in_sizes; (void)n_in; (void)out_size;
    const float* hs  = (const float*)d_in[0];
    const float* enc = (const float*)d_in[1];
    const float* qw  = (const float*)d_in[4];
    const float* kw  = (const float*)d_in[5];
    const float* vw  = (const float*)d_in[6];
    const float* ow  = (const float*)d_in[7];
    const float* qsc = (const float*)d_in[8];
    const float* ksc = (const float*)d_in[9];
    float* out = (float*)d_out;

    float *qb, *kb;
    cudaGetSymbolAddress((void**)&qb, g_q);
    cudaGetSymbolAddress((void**)&kb, g_k);
    __half *q16, *k16, *v16;
    cudaGetSymbolAddress((void**)&q16, g_q16);
    cudaGetSymbolAddress((void**)&k16, g_k16);
    cudaGetSymbolAddress((void**)&v16, g_v16);
    __half *hs2, *enc2, *qw2, *kw2, *vw2, *ow2, *at2;
    cudaGetSymbolAddress((void**)&hs2, g_hs2);
    cudaGetSymbolAddress((void**)&enc2, g_enc2);
    cudaGetSymbolAddress((void**)&qw2, g_qw2);
    cudaGetSymbolAddress((void**)&kw2, g_kw2);
    cudaGetSymbolAddress((void**)&vw2, g_vw2);
    cudaGetSymbolAddress((void**)&ow2, g_ow2);
    cudaGetSymbolAddress((void**)&at2, g_at2);

    static int cfg = 0;
    if (!cfg) {
        cudaFuncSetAttribute(gemm_hmma, cudaFuncAttributeMaxDynamicSharedMemorySize, GEMM_SMEM);
        cudaFuncSetAttribute(flash_hmma, cudaFuncAttributeMaxDynamicSharedMemorySize, FH_SMEM);
        cfg = 1;
    }

    // converts
    a2h_kernel<<<(4096LL * 2048) / 1024, 256>>>(hs, hs2);
    a2h_kernel<<<(4096LL * 2048) / 1024, 256>>>(enc, enc2);
    wsplit_kernel<<<dim3(4096 / 32, D_DIM / 32), 256>>>(qw, qw2, D_DIM, H_DIM, (long long)D_DIM * H_DIM, H_DIM);
    wsplit_kernel<<<dim3(2048 / 32, D_DIM / 32), 256>>>(kw, kw2, D_DIM, H_DIM, (long long)D_DIM * H_DIM, H_DIM);
    wsplit_kernel<<<dim3(2048 / 32, D_DIM / 32), 256>>>(vw, vw2, D_DIM, H_DIM, (long long)D_DIM * H_DIM, H_DIM);
    wsplit_kernel<<<dim3(2048 / 32, 4096 / 32), 256>>>(ow, ow2, 4096, D_DIM, 0LL, D_DIM);

    const long long kvBS = (long long)S_LEN * K_HEADS * H_DIM;
    // Q (fp32 out, needs rms+rope)
    gemm_hmma<<<dim3(32, 32), 128, GEMM_SMEM>>>(hs2, qw2, qb, 2048, 4096, 0LL, 0, 4096, 0);
    // K (fp32 out, needs rms[+rope])
    gemm_hmma<<<dim3(16, 32), 128, GEMM_SMEM>>>(hs2, kw2, kb, 2048, T_LEN, kvBS, 0, 2048, 0);
    gemm_hmma<<<dim3(16, 32), 128, GEMM_SMEM>>>(enc2, kw2, kb, 2048, E_LEN, kvBS, T_LEN, 2048, 0);
    // V (fp16 out directly)
    gemm_hmma<<<dim3(16, 32), 128, GEMM_SMEM>>>(hs2, vw2, v16, 2048, T_LEN, kvBS, 0, 2048, 1);
    gemm_hmma<<<dim3(16, 32), 128, GEMM_SMEM>>>(enc2, vw2, v16, 2048, E_LEN, kvBS, T_LEN, 2048, 1);

    // rms(+rope) -> fp16 (warp-per-row)
    rms_rope_w_kernel<<<B_SZ * T_LEN * N_HEADS / 8, 256>>>(qb, q16, qsc, N_HEADS, T_LEN, T_LEN, 0, 1, 0.0625f);
    rms_rope_w_kernel<<<B_SZ * T_LEN * K_HEADS / 8, 256>>>(kb, k16, ksc, K_HEADS, T_LEN, S_LEN, 0, 1, 1.0f);
    rms_rope_w_kernel<<<B_SZ * E_LEN * K_HEADS / 8, 256>>>(kb, k16, ksc, K_HEADS, E_LEN, S_LEN, T_LEN, 0, 1.0f);

    // flash -> fp16 at2 directly
    flash_hmma<<<dim3(T_LEN / 64, N_HEADS, B_SZ), 256, FH_SMEM>>>(q16, k16, v16, at2);

    // O = attn @ ow  (fp32 out)
    gemm_hmma<<<dim3(16, 32), 128, GEMM_SMEM>>>(at2, ow2, out, 4096, 4096, 0LL, 0, 2048, 0);
}

// round 10
// speedup vs baseline: 8.4177x; 1.0524x over previous
#include <cuda_runtime.h>
#include <cuda_fp16.h>
#include <stdint.h>
#include <math.h>

#define B_SZ 4
#define T_LEN 1024
#define E_LEN 1024
#define S_LEN 2048
#define D_DIM 2048
#define H_DIM 256
#define N_HEADS 16
#define K_HEADS 8

__device__ float g_q[(size_t)B_SZ * T_LEN * N_HEADS * H_DIM];
__device__ float g_k[(size_t)B_SZ * S_LEN * K_HEADS * H_DIM];
__device__ __half g_q16[(size_t)B_SZ * T_LEN * N_HEADS * H_DIM];
__device__ __half g_k16[(size_t)B_SZ * S_LEN * K_HEADS * H_DIM];
__device__ __half g_v16[(size_t)B_SZ * S_LEN * K_HEADS * H_DIM];
__device__ __half g_hs2 [(size_t)4096 * 2048];
__device__ __half g_enc2[(size_t)4096 * 2048];
__device__ __half g_qw2 [(size_t)4096 * 2048];
__device__ __half g_kw2 [(size_t)2048 * 2048];
__device__ __half g_vw2 [(size_t)2048 * 2048];
__device__ __half g_ow2 [(size_t)2048 * 4096];
__device__ __half g_at2 [(size_t)4096 * 4096];

// ---------------- helpers ----------------
__device__ __forceinline__ uint32_t smem_u32(const void* p) {
    uint32_t a;
    asm("{ .reg .u64 t; cvta.to.shared.u64 t, %1; cvt.u32.u64 %0, t; }" : "=r"(a) : "l"(p));
    return a;
}
#define CP16(dst, src) \
    asm volatile("cp.async.cg.shared.global [%0], [%1], 16;" :: "r"(dst), "l"(src) : "memory")
#define CP_COMMIT asm volatile("cp.async.commit_group;" ::: "memory")
#define CP_WAIT2  asm volatile("cp.async.wait_group 2;" ::: "memory")
#define CP_WAIT1  asm volatile("cp.async.wait_group 1;" ::: "memory")
#define CP_WAIT0  asm volatile("cp.async.wait_group 0;" ::: "memory")
#define LDSM4(r0, r1, r2, r3, addr) \
    asm volatile("ldmatrix.sync.aligned.m8n8.x4.shared.b16 {%0,%1,%2,%3}, [%4];" \
        : "=r"(r0), "=r"(r1), "=r"(r2), "=r"(r3) : "r"(addr))
#define LDSM4T(r0, r1, r2, r3, addr) \
    asm volatile("ldmatrix.sync.aligned.m8n8.x4.trans.shared.b16 {%0,%1,%2,%3}, [%4];" \
        : "=r"(r0), "=r"(r1), "=r"(r2), "=r"(r3) : "r"(addr))
#define MMAH16816(d, a, b0, b1) \
    asm volatile("mma.sync.aligned.m16n8k16.row.col.f32.f16.f16.f32 " \
        "{%0,%1,%2,%3}, {%4,%5,%6,%7}, {%8,%9}, {%0,%1,%2,%3};" \
        : "+f"((d)[0]), "+f"((d)[1]), "+f"((d)[2]), "+f"((d)[3]) \
        : "r"((a)[0]), "r"((a)[1]), "r"((a)[2]), "r"((a)[3]), "r"(b0), "r"(b1))

__device__ __forceinline__ uint32_t gsw(int row, int kchunk) {
    return (uint32_t)(row * 128 + ((kchunk ^ (row & 7)) << 4));
}
__device__ __forceinline__ uint32_t fsw(int row, int kbyte) {
    return (uint32_t)(row * 512 + ((((kbyte >> 4) ^ (row & 7))) << 4) + (kbyte & 15));
}

// ---------------- convert kernels ----------------
__global__ __launch_bounds__(256) void a2h_kernel(
    const float* __restrict__ X, __half* __restrict__ Y)
{
    size_t idx = ((size_t)blockIdx.x * 256 + threadIdx.x) * 4;
    float4 v = *(const float4*)(X + idx);
    __half2 h0 = __floats2half2_rn(v.x, v.y);
    __half2 h1 = __floats2half2_rn(v.z, v.w);
    *(uint2*)(Y + idx) = make_uint2(*(uint32_t*)&h0, *(uint32_t*)&h1);
}

__global__ __launch_bounds__(256) void wsplit_kernel(
    const float* __restrict__ W, __half* __restrict__ Yt,
    int Kd, int cph, long long hstr, int krs)
{
    __shared__ float t[32][33];
    int k0 = blockIdx.y * 32, j0 = blockIdx.x * 32;
    int tx = threadIdx.x & 31, ty8 = threadIdx.x >> 5;
#pragma unroll
    for (int i = 0; i < 4; i++) {
        int kl = ty8 + i * 8;
        int j = j0 + tx;
        t[kl][tx] = W[(size_t)(j / cph) * hstr + (size_t)(k0 + kl) * krs + (j % cph)];
    }
    __syncthreads();
#pragma unroll
    for (int i = 0; i < 4; i++) {
        int j = j0 + ty8 + i * 8;
        int k = k0 + tx;
        Yt[(size_t)j * Kd + k] = __float2half(t[tx][ty8 + i * 8]);
    }
}

// ---------------- HMMA fp16 GEMM (unchanged R9) ----------------
#define GSTAGES 3
#define STG_BYTES 32768
#define GEMM_SMEM (GSTAGES * STG_BYTES)

__global__ void __launch_bounds__(128, 2) gemm_hmma(
    const __half* __restrict__ A, const __half* __restrict__ Bw,
    void* __restrict__ Cv, int Kp, int Mpb, long long outBS, int rowOff, int ldc,
    int outHalf)
{
    extern __shared__ char smraw[];
    const uint32_t sb = smem_u32(smraw);
    const int tid = threadIdx.x;
    const int lane = tid & 31, wid = tid >> 5;
    const int wm = wid & 1, wn = wid >> 1;
    const int m0 = blockIdx.y * 128, n0 = blockIdx.x * 128;
    const int nIter = Kp >> 6;

    const int crow = tid >> 3;
    const int ckc = tid & 7;
    const uint32_t csw = gsw(crow, ckc);
    const __half* ga = A + (size_t)(m0 + crow) * Kp + ckc * 8;
    const __half* gb = Bw + (size_t)(n0 + crow) * Kp + ckc * 8;

    const int r8 = lane & 7, sel = lane >> 3;
    uint32_t aRB[4]; int aRX[4];
    const int dselA = sel >> 1;
#pragma unroll
    for (int mf = 0; mf < 4; mf++) {
        int row = wm * 64 + mf * 16 + r8 + ((sel & 1) << 3);
        aRB[mf] = (uint32_t)(row * 128);
        aRX[mf] = row & 7;
    }
    uint32_t bRB[4]; int bRX[4];
    const int dselB = sel & 1;
#pragma unroll
    for (int np = 0; np < 4; np++) {
        int row = wn * 64 + np * 16 + r8 + ((sel >> 1) << 3);
        bRB[np] = 16384u + (uint32_t)(row * 128);
        bRX[np] = row & 7;
    }

    float acc[4][8][4];
#pragma unroll
    for (int mf = 0; mf < 4; mf++)
#pragma unroll
        for (int nf = 0; nf < 8; nf++)
#pragma unroll
            for (int q = 0; q < 4; q++) acc[mf][nf][q] = 0.f;

#pragma unroll
    for (int s = 0; s < 2; s++) {
        uint32_t base = sb + (uint32_t)s * STG_BYTES;
        const __half* pa = ga + s * 64;
        const __half* pb = gb + s * 64;
#pragma unroll
        for (int p = 0; p < 8; p++) {
            uint32_t so = csw + (uint32_t)p * 2048u;
            CP16(base + so, pa + (size_t)p * 16 * Kp);
            CP16(base + 16384u + so, pb + (size_t)p * 16 * Kp);
        }
        CP_COMMIT;
    }

    for (int it = 0; it < nIter; it++) {
        if (it + 2 < nIter) {
            int s = (it + 2) % GSTAGES;
            uint32_t base = sb + (uint32_t)s * STG_BYTES;
            const __half* pa = ga + (size_t)(it + 2) * 64;
            const __half* pb = gb + (size_t)(it + 2) * 64;
#pragma unroll
            for (int p = 0; p < 8; p++) {
                uint32_t so = csw + (uint32_t)p * 2048u;
                CP16(base + so, pa + (size_t)p * 16 * Kp);
                CP16(base + 16384u + so, pb + (size_t)p * 16 * Kp);
            }
        }
        CP_COMMIT;
        CP_WAIT2;
        __syncthreads();

        uint32_t sbase = sb + (uint32_t)(it % GSTAGES) * STG_BYTES;
#pragma unroll
        for (int ks = 0; ks < 4; ks++) {
            uint32_t af[4][4];
#pragma unroll
            for (int mf = 0; mf < 4; mf++)
                LDSM4(af[mf][0], af[mf][1], af[mf][2], af[mf][3],
                      sbase + aRB[mf] + (uint32_t)((((ks << 1) + dselA) ^ aRX[mf]) << 4));
            uint32_t bf[4][4];
#pragma unroll
            for (int np = 0; np < 4; np++)
                LDSM4(bf[np][0], bf[np][1], bf[np][2], bf[np][3],
                      sbase + bRB[np] + (uint32_t)((((ks << 1) + dselB) ^ bRX[np]) << 4));
#pragma unroll
            for (int mf = 0; mf < 4; mf++)
#pragma unroll
                for (int np = 0; np < 4; np++) {
                    MMAH16816(acc[mf][np * 2 + 0], af[mf], bf[np][0], bf[np][1]);
                    MMAH16816(acc[mf][np * 2 + 1], af[mf], bf[np][2], bf[np][3]);
                }
        }
        __syncthreads();
    }

#pragma unroll
    for (int mf = 0; mf < 4; mf++)
#pragma unroll
        for (int rh = 0; rh < 2; rh++) {
            int gr = m0 + wm * 64 + mf * 16 + (lane >> 2) + rh * 8;
            int bi = gr / Mpb;
            int rr = gr - bi * Mpb;
            size_t base = (size_t)bi * outBS + (size_t)(rr + rowOff) * ldc
                        + n0 + wn * 64 + (lane & 3) * 2;
            if (outHalf) {
                __half* rowp = (__half*)Cv + base;
#pragma unroll
                for (int nf = 0; nf < 8; nf++) {
                    __half2 v = __floats2half2_rn(acc[mf][nf][rh * 2 + 0], acc[mf][nf][rh * 2 + 1]);
                    *(__half2*)(rowp + nf * 8) = v;
                }
            } else {
                float* rowp = (float*)Cv + base;
#pragma unroll
                for (int nf = 0; nf < 8; nf++) {
                    float2 v = make_float2(acc[mf][nf][rh * 2 + 0], acc[mf][nf][rh * 2 + 1]);
                    *(float2*)(rowp + nf * 8) = v;
                }
            }
        }
}

// ---------------- RMS-norm (+RoPE) -> fp16, warp-per-row (unchanged R9) ----------------
__global__ __launch_bounds__(256) void rms_rope_w_kernel(
    const float* __restrict__ buf, __half* __restrict__ outh,
    const float* __restrict__ scale,
    int heads, int rowsPerBatch, int bufRPB, int rowStart, int doRope, float outScale)
{
    int rowIdx = blockIdx.x * 8 + (threadIdx.x >> 5);
    int lane = threadIdx.x & 31;
    int head = rowIdx % heads;
    int tmp = rowIdx / heads;
    int t = tmp % rowsPerBatch;
    int b = tmp / rowsPerBatch;
    size_t off = ((size_t)((size_t)b * bufRPB + rowStart + t) * heads + head) * H_DIM;

    float4 x1 = *(const float4*)(buf + off + lane * 4);
    float4 x2 = *(const float4*)(buf + off + 128 + lane * 4);
    float ss = x1.x * x1.x + x1.y * x1.y + x1.z * x1.z + x1.w * x1.w
             + x2.x * x2.x + x2.y * x2.y + x2.z * x2.z + x2.w * x2.w;
#pragma unroll
    for (int o = 16; o > 0; o >>= 1) ss += __shfl_xor_sync(0xffffffffu, ss, o);
    float rinv = rsqrtf(ss * (1.f / 256.f) + 1e-6f) * outScale;

    float4 s1 = *(const float4*)(scale + lane * 4);
    float4 s2 = *(const float4*)(scale + 128 + lane * 4);
    float y1[4] = { x1.x * rinv * (1.f + s1.x), x1.y * rinv * (1.f + s1.y),
                    x1.z * rinv * (1.f + s1.z), x1.w * rinv * (1.f + s1.w) };
    float y2[4] = { x2.x * rinv * (1.f + s2.x), x2.y * rinv * (1.f + s2.y),
                    x2.z * rinv * (1.f + s2.z), x2.w * rinv * (1.f + s2.w) };
    float o1[4], o2[4];
    if (doRope) {
#pragma unroll
        for (int i = 0; i < 4; i++) {
            float ang = (float)t * exp2f(-(float)(lane * 4 + i) * 0.10381025296522988f);
            float sn, cs;
            sincosf(ang, &sn, &cs);
            o1[i] = y1[i] * cs - y2[i] * sn;
            o2[i] = y2[i] * cs + y1[i] * sn;
        }
    } else {
#pragma unroll
        for (int i = 0; i < 4; i++) { o1[i] = y1[i]; o2[i] = y2[i]; }
    }
    __half2 a0 = __floats2half2_rn(o1[0], o1[1]);
    __half2 a1 = __floats2half2_rn(o1[2], o1[3]);
    __half2 b0 = __floats2half2_rn(o2[0], o2[1]);
    __half2 b1 = __floats2half2_rn(o2[2], o2[3]);
    *(uint2*)(outh + off + lane * 4) = make_uint2(*(uint32_t*)&a0, *(uint32_t*)&a1);
    *(uint2*)(outh + off + 128 + lane * 4) = make_uint2(*(uint32_t*)&b0, *(uint32_t*)&b1);
}

// ---------------- flash v2: 128-row q-tile, full-width warps ----------------
// smem: Q@0 (64K), K st: 65536+st*32768, V st: 131072+st*32768, P@196608 (16K)
#define F2_KB 65536u
#define F2_VB 131072u
#define F2_ST 32768u
#define F2_P  196608u
#define FH2_SMEM 212992

__global__ void __launch_bounds__(256, 1) flash2_hmma(
    const __half* __restrict__ Qh, const __half* __restrict__ Kh,
    const __half* __restrict__ Vh, __half* __restrict__ Oh)
{
    extern __shared__ char smraw[];
    const uint32_t sb = smem_u32(smraw);
    const int tid = threadIdx.x, lane = tid & 31, w = tid >> 5;
    const int qt = blockIdx.x, n = blockIdx.y, b = blockIdx.z;
    const int kh = n >> 1, qbase = qt << 7;

    // Q load: 128 rows x 512B
    const char* qg = (const char*)(Qh + ((size_t)(b * T_LEN + qbase) * N_HEADS + n) * H_DIM);
#pragma unroll
    for (int p = 0; p < 16; p++) {
        int idx = tid + p * 256;
        int r = idx >> 5, c = idx & 31;
        CP16(sb + fsw(r, c * 16), qg + (size_t)r * (N_HEADS * H_DIM * 2) + c * 16);
    }
    CP_COMMIT;

    const char* kg = (const char*)(Kh + ((size_t)b * S_LEN * K_HEADS + kh) * H_DIM);
    const char* vg = (const char*)(Vh + ((size_t)b * S_LEN * K_HEADS + kh) * H_DIM);
    const int kvstride = K_HEADS * H_DIM * 2;

    const int nSelf = (qt + 1) << 1;
    const int nT = nSelf + (E_LEN >> 6);

    // tile 0
#pragma unroll
    for (int p = 0; p < 8; p++) {
        int idx = tid + p * 256;
        int r = idx >> 5, c = idx & 31;
        uint32_t sw = fsw(r, c * 16);
        CP16(sb + F2_KB + sw, kg + (size_t)r * kvstride + c * 16);
        CP16(sb + F2_VB + sw, vg + (size_t)r * kvstride + c * 16);
    }
    CP_COMMIT;

    float oacc[32][4];
#pragma unroll
    for (int nf = 0; nf < 32; nf++)
#pragma unroll
        for (int q = 0; q < 4; q++) oacc[nf][q] = 0.f;
    float m1 = -INFINITY, m2 = -INFINITY, l1 = 0.f, l2 = 0.f;

    const int r8 = lane & 7, sel = lane >> 3;
    const int rowA = w * 16 + r8 + ((sel & 1) << 3);   // local q row for A frags
    const int dselA = sel >> 1;
    const int dselB = sel & 1;
    const int r1g = w * 16 + (lane >> 2), r2g = r1g + 8;  // local acc rows
    const uint32_t aBaseQ = sb + (uint32_t)rowA * 512u;
    const int rowAx = rowA & 7;
    const uint32_t pwb = sb + F2_P;
    const uint32_t paBase = pwb + (uint32_t)rowA * 128u;
    const int rowAp = rowA & 7;

    for (int t = 0; t < nT; t++) {
        if (t + 1 < nT) {
            int s0n = (t + 1 < nSelf) ? ((t + 1) << 6) : (T_LEN + ((t + 1 - nSelf) << 6));
            uint32_t kb = sb + F2_KB + (uint32_t)((t + 1) & 1) * F2_ST;
            uint32_t vb = sb + F2_VB + (uint32_t)((t + 1) & 1) * F2_ST;
#pragma unroll
            for (int p = 0; p < 8; p++) {
                int idx = tid + p * 256;
                int r = idx >> 5, c = idx & 31;
                uint32_t sw = fsw(r, c * 16);
                CP16(kb + sw, kg + (size_t)(s0n + r) * kvstride + c * 16);
                CP16(vb + sw, vg + (size_t)(s0n + r) * kvstride + c * 16);
            }
            CP_COMMIT;
            CP_WAIT1;
        } else {
            CP_WAIT0;
        }
        __syncthreads();

        const int s0 = (t < nSelf) ? (t << 6) : (T_LEN + ((t - nSelf) << 6));
        const bool diag = (t >= nSelf - 2) && (t < nSelf);
        const uint32_t sK = sb + F2_KB + (uint32_t)(t & 1) * F2_ST;
        const uint32_t sV = sb + F2_VB + (uint32_t)(t & 1) * F2_ST;

        // ---- S = Q K^T : warp covers 16 rows x 64 cols ----
        float sacc[8][4];
#pragma unroll
        for (int nf = 0; nf < 8; nf++)
#pragma unroll
            for (int q = 0; q < 4; q++) sacc[nf][q] = 0.f;
#pragma unroll 4
        for (int ks = 0; ks < 16; ks++) {
            uint32_t a[4];
            LDSM4(a[0], a[1], a[2], a[3], aBaseQ + (uint32_t)((((ks << 1) + dselA) ^ rowAx) << 4));
#pragma unroll
            for (int nf2 = 0; nf2 < 4; nf2++) {
                int rowB = nf2 * 16 + r8 + ((sel >> 1) << 3);
                uint32_t bb[4];
                LDSM4(bb[0], bb[1], bb[2], bb[3],
                      sK + (uint32_t)rowB * 512u + (uint32_t)((((ks << 1) + dselB) ^ (rowB & 7)) << 4));
                MMAH16816(sacc[nf2 * 2 + 0], a, bb[0], bb[1]);
                MMAH16816(sacc[nf2 * 2 + 1], a, bb[2], bb[3]);
            }
        }

        // ---- softcap + mask + warp-local softmax ----
        float mx1 = -INFINITY, mx2 = -INFINITY;
#pragma unroll
        for (int nf = 0; nf < 8; nf++)
#pragma unroll
            for (int e = 0; e < 4; e++) {
                float s = sacc[nf][e];
                float cpv = 50.f - __fdividef(100.f, __expf(0.04f * s) + 1.f);
                if (diag) {
                    int col = s0 + nf * 8 + ((lane & 3) << 1) + (e & 1);
                    int row = qbase + ((e < 2) ? r1g : r2g);
                    if (col > row) cpv = -INFINITY;
                }
                sacc[nf][e] = cpv;
                if (e < 2) mx1 = fmaxf(mx1, cpv); else mx2 = fmaxf(mx2, cpv);
            }
        mx1 = fmaxf(mx1, __shfl_xor_sync(0xffffffffu, mx1, 1));
        mx1 = fmaxf(mx1, __shfl_xor_sync(0xffffffffu, mx1, 2));
        mx2 = fmaxf(mx2, __shfl_xor_sync(0xffffffffu, mx2, 1));
        mx2 = fmaxf(mx2, __shfl_xor_sync(0xffffffffu, mx2, 2));
        float mn1 = fmaxf(m1, mx1), mn2 = fmaxf(m2, mx2);
        float corr1 = __expf(m1 - mn1), corr2 = __expf(m2 - mn2);
        m1 = mn1; m2 = mn2;

        float sum1 = 0.f, sum2 = 0.f;
#pragma unroll
        for (int nf = 0; nf < 8; nf++) {
            float p0 = __expf(sacc[nf][0] - mn1);
            float p1 = __expf(sacc[nf][1] - mn1);
            float p2 = __expf(sacc[nf][2] - mn2);
            float p3 = __expf(sacc[nf][3] - mn2);
            sum1 += p0 + p1; sum2 += p2 + p3;
            __half2 hA = __floats2half2_rn(p0, p1);
            __half2 hB = __floats2half2_rn(p2, p3);
            uint32_t a1 = pwb + (uint32_t)r1g * 128u + (uint32_t)((nf ^ (r1g & 7)) << 4) + ((lane & 3) << 2);
            uint32_t a2 = pwb + (uint32_t)r2g * 128u + (uint32_t)((nf ^ (r2g & 7)) << 4) + ((lane & 3) << 2);
            asm volatile("st.shared.b32 [%0], %1;" :: "r"(a1), "r"(*(uint32_t*)&hA) : "memory");
            asm volatile("st.shared.b32 [%0], %1;" :: "r"(a2), "r"(*(uint32_t*)&hB) : "memory");
        }
        sum1 += __shfl_xor_sync(0xffffffffu, sum1, 1);
        sum1 += __shfl_xor_sync(0xffffffffu, sum1, 2);
        sum2 += __shfl_xor_sync(0xffffffffu, sum2, 1);
        sum2 += __shfl_xor_sync(0xffffffffu, sum2, 2);
        l1 = l1 * corr1 + sum1;
        l2 = l2 * corr2 + sum2;

#pragma unroll
        for (int nf = 0; nf < 32; nf++) {
            oacc[nf][0] *= corr1; oacc[nf][1] *= corr1;
            oacc[nf][2] *= corr2; oacc[nf][3] *= corr2;
        }
        __syncwarp();

        // ---- O += P V : warp covers its 16 rows x 256 cols ----
#pragma unroll
        for (int ks = 0; ks < 4; ks++) {
            uint32_t a[4];
            LDSM4(a[0], a[1], a[2], a[3], paBase + (uint32_t)((((ks << 1) + dselA) ^ rowAp) << 4));
            int rowV = ks * 16 + r8 + ((sel & 1) << 3);
            uint32_t vBase = sV + (uint32_t)rowV * 512u;
            int rVx = rowV & 7;
#pragma unroll
            for (int nf2 = 0; nf2 < 16; nf2++) {
                int chunk = nf2 * 2 + (sel >> 1);
                uint32_t bb[4];
                LDSM4T(bb[0], bb[1], bb[2], bb[3], vBase + (uint32_t)((chunk ^ rVx) << 4));
                MMAH16816(oacc[nf2 * 2 + 0], a, bb[0], bb[1]);
                MMAH16816(oacc[nf2 * 2 + 1], a, bb[2], bb[3]);
            }
        }
        __syncthreads();
    }

    // ---- epilogue: fp16 to O-GEMM input [tok, N*H] ----
    float inv1 = 1.f / l1;
    float inv2 = 1.f / l2;
    int t1 = qbase + r1g, t2 = qbase + r2g;
    __half* o1 = Oh + ((size_t)(b * T_LEN + t1)) * (N_HEADS * H_DIM) + n * H_DIM + ((lane & 3) << 1);
    __half* o2 = Oh + ((size_t)(b * T_LEN + t2)) * (N_HEADS * H_DIM) + n * H_DIM + ((lane & 3) << 1);
#pragma unroll
    for (int nf = 0; nf < 32; nf++) {
        __half2 v1 = __floats2half2_rn(oacc[nf][0] * inv1, oacc[nf][1] * inv1);
        __half2 v2 = __floats2half2_rn(oacc[nf][2] * inv2, oacc[nf][3] * inv2);
        *(__half2*)(o1 + nf * 8) = v1;
        *(__half2*)(o2 + nf * 8) = v2;
    }
}

// ---------------- launch ----------------
extern "C" void kernel_launch(void* const* d_in, const int* in_sizes, int n_in,
                              void* d_out, int out_size)
{
    (void)in_sizes; (void)n_in; (void)out_size;
    const float* hs  = (const float*)d_in[0];
    const float* enc = (const float*)d_in[1];
    const float* qw  = (const float*)d_in[4];
    const float* kw  = (const float*)d_in[5];
    const float* vw  = (const float*)d_in[6];
    const float* ow  = (const float*)d_in[7];
    const float* qsc = (const float*)d_in[8];
    const float* ksc = (const float*)d_in[9];
    float* out = (float*)d_out;

    float *qb, *kb;
    cudaGetSymbolAddress((void**)&qb, g_q);
    cudaGetSymbolAddress((void**)&kb, g_k);
    __half *q16, *k16, *v16;
    cudaGetSymbolAddress((void**)&q16, g_q16);
    cudaGetSymbolAddress((void**)&k16, g_k16);
    cudaGetSymbolAddress((void**)&v16, g_v16);
    __half *hs2, *enc2, *qw2, *kw2, *vw2, *ow2, *at2;
    cudaGetSymbolAddress((void**)&hs2, g_hs2);
    cudaGetSymbolAddress((void**)&enc2, g_enc2);
    cudaGetSymbolAddress((void**)&qw2, g_qw2);
    cudaGetSymbolAddress((void**)&kw2, g_kw2);
    cudaGetSymbolAddress((void**)&vw2, g_vw2);
    cudaGetSymbolAddress((void**)&ow2, g_ow2);
    cudaGetSymbolAddress((void**)&at2, g_at2);

    static int cfg = 0;
    if (!cfg) {
        cudaFuncSetAttribute(gemm_hmma, cudaFuncAttributeMaxDynamicSharedMemorySize, GEMM_SMEM);
        cudaFuncSetAttribute(flash2_hmma, cudaFuncAttributeMaxDynamicSharedMemorySize, FH2_SMEM);
        cfg = 1;
    }

    // converts
    a2h_kernel<<<(4096LL * 2048) / 1024, 256>>>(hs, hs2);
    a2h_kernel<<<(4096LL * 2048) / 1024, 256>>>(enc, enc2);
    wsplit_kernel<<<dim3(4096 / 32, D_DIM / 32), 256>>>(qw, qw2, D_DIM, H_DIM, (long long)D_DIM * H_DIM, H_DIM);
    wsplit_kernel<<<dim3(2048 / 32, D_DIM / 32), 256>>>(kw, kw2, D_DIM, H_DIM, (long long)D_DIM * H_DIM, H_DIM);
    wsplit_kernel<<<dim3(2048 / 32, D_DIM / 32), 256>>>(vw, vw2, D_DIM, H_DIM, (long long)D_DIM * H_DIM, H_DIM);
    wsplit_kernel<<<dim3(2048 / 32, 4096 / 32), 256>>>(ow, ow2, 4096, D_DIM, 0LL, D_DIM);

    const long long kvBS = (long long)S_LEN * K_HEADS * H_DIM;
    gemm_hmma<<<dim3(32, 32), 128, GEMM_SMEM>>>(hs2, qw2, qb, 2048, 4096, 0LL, 0, 4096, 0);
    gemm_hmma<<<dim3(16, 32), 128, GEMM_SMEM>>>(hs2, kw2, kb, 2048, T_LEN, kvBS, 0, 2048, 0);
    gemm_hmma<<<dim3(16, 32), 128, GEMM_SMEM>>>(enc2, kw2, kb, 2048, E_LEN, kvBS, T_LEN, 2048, 0);
    gemm_hmma<<<dim3(16, 32), 128, GEMM_SMEM>>>(hs2, vw2, v16, 2048, T_LEN, kvBS, 0, 2048, 1);
    gemm_hmma<<<dim3(16, 32), 128, GEMM_SMEM>>>(enc2, vw2, v16, 2048, E_LEN, kvBS, T_LEN, 2048, 1);

    rms_rope_w_kernel<<<B_SZ * T_LEN * N_HEADS / 8, 256>>>(qb, q16, qsc, N_HEADS, T_LEN, T_LEN, 0, 1, 0.0625f);
    rms_rope_w_kernel<<<B_SZ * T_LEN * K_HEADS / 8, 256>>>(kb, k16, ksc, K_HEADS, T_LEN, S_LEN, 0, 1, 1.0f);
    rms_rope_w_kernel<<<B_SZ * E_LEN * K_HEADS / 8, 256>>>(kb, k16, ksc, K_HEADS, E_LEN, S_LEN, T_LEN, 0, 1.0f);

    flash2_hmma<<<dim3(T_LEN / 128, N_HEADS, B_SZ), 256, FH2_SMEM>>>(q16, k16, v16, at2);

    gemm_hmma<<<dim3(16, 32), 128, GEMM_SMEM>>>(at2, ow2, out, 4096, 4096, 0LL, 0, 2048, 0);
}

// round 11
// speedup vs baseline: 8.5906x; 1.0205x over previous
#include <cuda_runtime.h>
#include <cuda_fp16.h>
#include <stdint.h>
#include <math.h>

#define B_SZ 4
#define T_LEN 1024
#define E_LEN 1024
#define S_LEN 2048
#define D_DIM 2048
#define H_DIM 256
#define N_HEADS 16
#define K_HEADS 8

__device__ float g_q[(size_t)B_SZ * T_LEN * N_HEADS * H_DIM];
__device__ float g_k[(size_t)B_SZ * S_LEN * K_HEADS * H_DIM];
__device__ __half g_q16[(size_t)B_SZ * T_LEN * N_HEADS * H_DIM];
__device__ __half g_k16[(size_t)B_SZ * S_LEN * K_HEADS * H_DIM];
__device__ __half g_v16[(size_t)B_SZ * S_LEN * K_HEADS * H_DIM];
__device__ __half g_hs2 [(size_t)4096 * 2048];
__device__ __half g_enc2[(size_t)4096 * 2048];
__device__ __half g_qw2 [(size_t)4096 * 2048];
__device__ __half g_kw2 [(size_t)2048 * 2048];
__device__ __half g_vw2 [(size_t)2048 * 2048];
__device__ __half g_ow2 [(size_t)2048 * 4096];
__device__ __half g_at2 [(size_t)4096 * 4096];

// ---------------- helpers ----------------
__device__ __forceinline__ uint32_t smem_u32(const void* p) {
    uint32_t a;
    asm("{ .reg .u64 t; cvta.to.shared.u64 t, %1; cvt.u32.u64 %0, t; }" : "=r"(a) : "l"(p));
    return a;
}
#define CP16(dst, src) \
    asm volatile("cp.async.cg.shared.global [%0], [%1], 16;" :: "r"(dst), "l"(src) : "memory")
#define CP_COMMIT asm volatile("cp.async.commit_group;" ::: "memory")
#define CP_WAIT2  asm volatile("cp.async.wait_group 2;" ::: "memory")
#define CP_WAIT1  asm volatile("cp.async.wait_group 1;" ::: "memory")
#define CP_WAIT0  asm volatile("cp.async.wait_group 0;" ::: "memory")
#define LDSM4(r0, r1, r2, r3, addr) \
    asm volatile("ldmatrix.sync.aligned.m8n8.x4.shared.b16 {%0,%1,%2,%3}, [%4];" \
        : "=r"(r0), "=r"(r1), "=r"(r2), "=r"(r3) : "r"(addr))
#define LDSM4T(r0, r1, r2, r3, addr) \
    asm volatile("ldmatrix.sync.aligned.m8n8.x4.trans.shared.b16 {%0,%1,%2,%3}, [%4];" \
        : "=r"(r0), "=r"(r1), "=r"(r2), "=r"(r3) : "r"(addr))
#define MMAH16816(d, a, b0, b1) \
    asm volatile("mma.sync.aligned.m16n8k16.row.col.f32.f16.f16.f32 " \
        "{%0,%1,%2,%3}, {%4,%5,%6,%7}, {%8,%9}, {%0,%1,%2,%3};" \
        : "+f"((d)[0]), "+f"((d)[1]), "+f"((d)[2]), "+f"((d)[3]) \
        : "r"((a)[0]), "r"((a)[1]), "r"((a)[2]), "r"((a)[3]), "r"(b0), "r"(b1))

__device__ __forceinline__ uint32_t gsw(int row, int kchunk) {
    return (uint32_t)(row * 128 + ((kchunk ^ (row & 7)) << 4));
}
__device__ __forceinline__ uint32_t fsw(int row, int kbyte) {
    return (uint32_t)(row * 512 + ((((kbyte >> 4) ^ (row & 7))) << 4) + (kbyte & 15));
}
__device__ __forceinline__ uint32_t packh2(float a, float b) {
    __half2 h = __floats2half2_rn(a, b);
    return *(uint32_t*)&h;
}

// ---------------- convert kernels ----------------
__global__ __launch_bounds__(256) void a2h_kernel(
    const float* __restrict__ X, __half* __restrict__ Y)
{
    size_t idx = ((size_t)blockIdx.x * 256 + threadIdx.x) * 4;
    float4 v = *(const float4*)(X + idx);
    __half2 h0 = __floats2half2_rn(v.x, v.y);
    __half2 h1 = __floats2half2_rn(v.z, v.w);
    *(uint2*)(Y + idx) = make_uint2(*(uint32_t*)&h0, *(uint32_t*)&h1);
}

__global__ __launch_bounds__(256) void wsplit_kernel(
    const float* __restrict__ W, __half* __restrict__ Yt,
    int Kd, int cph, long long hstr, int krs)
{
    __shared__ float t[32][33];
    int k0 = blockIdx.y * 32, j0 = blockIdx.x * 32;
    int tx = threadIdx.x & 31, ty8 = threadIdx.x >> 5;
#pragma unroll
    for (int i = 0; i < 4; i++) {
        int kl = ty8 + i * 8;
        int j = j0 + tx;
        t[kl][tx] = W[(size_t)(j / cph) * hstr + (size_t)(k0 + kl) * krs + (j % cph)];
    }
    __syncthreads();
#pragma unroll
    for (int i = 0; i < 4; i++) {
        int j = j0 + ty8 + i * 8;
        int k = k0 + tx;
        Yt[(size_t)j * Kd + k] = __float2half(t[tx][ty8 + i * 8]);
    }
}

// ---------------- HMMA fp16 GEMM (unchanged) ----------------
#define GSTAGES 3
#define STG_BYTES 32768
#define GEMM_SMEM (GSTAGES * STG_BYTES)

__global__ void __launch_bounds__(128, 2) gemm_hmma(
    const __half* __restrict__ A, const __half* __restrict__ Bw,
    void* __restrict__ Cv, int Kp, int Mpb, long long outBS, int rowOff, int ldc,
    int outHalf)
{
    extern __shared__ char smraw[];
    const uint32_t sb = smem_u32(smraw);
    const int tid = threadIdx.x;
    const int lane = tid & 31, wid = tid >> 5;
    const int wm = wid & 1, wn = wid >> 1;
    const int m0 = blockIdx.y * 128, n0 = blockIdx.x * 128;
    const int nIter = Kp >> 6;

    const int crow = tid >> 3;
    const int ckc = tid & 7;
    const uint32_t csw = gsw(crow, ckc);
    const __half* ga = A + (size_t)(m0 + crow) * Kp + ckc * 8;
    const __half* gb = Bw + (size_t)(n0 + crow) * Kp + ckc * 8;

    const int r8 = lane & 7, sel = lane >> 3;
    uint32_t aRB[4]; int aRX[4];
    const int dselA = sel >> 1;
#pragma unroll
    for (int mf = 0; mf < 4; mf++) {
        int row = wm * 64 + mf * 16 + r8 + ((sel & 1) << 3);
        aRB[mf] = (uint32_t)(row * 128);
        aRX[mf] = row & 7;
    }
    uint32_t bRB[4]; int bRX[4];
    const int dselB = sel & 1;
#pragma unroll
    for (int np = 0; np < 4; np++) {
        int row = wn * 64 + np * 16 + r8 + ((sel >> 1) << 3);
        bRB[np] = 16384u + (uint32_t)(row * 128);
        bRX[np] = row & 7;
    }

    float acc[4][8][4];
#pragma unroll
    for (int mf = 0; mf < 4; mf++)
#pragma unroll
        for (int nf = 0; nf < 8; nf++)
#pragma unroll
            for (int q = 0; q < 4; q++) acc[mf][nf][q] = 0.f;

#pragma unroll
    for (int s = 0; s < 2; s++) {
        uint32_t base = sb + (uint32_t)s * STG_BYTES;
        const __half* pa = ga + s * 64;
        const __half* pb = gb + s * 64;
#pragma unroll
        for (int p = 0; p < 8; p++) {
            uint32_t so = csw + (uint32_t)p * 2048u;
            CP16(base + so, pa + (size_t)p * 16 * Kp);
            CP16(base + 16384u + so, pb + (size_t)p * 16 * Kp);
        }
        CP_COMMIT;
    }

    for (int it = 0; it < nIter; it++) {
        if (it + 2 < nIter) {
            int s = (it + 2) % GSTAGES;
            uint32_t base = sb + (uint32_t)s * STG_BYTES;
            const __half* pa = ga + (size_t)(it + 2) * 64;
            const __half* pb = gb + (size_t)(it + 2) * 64;
#pragma unroll
            for (int p = 0; p < 8; p++) {
                uint32_t so = csw + (uint32_t)p * 2048u;
                CP16(base + so, pa + (size_t)p * 16 * Kp);
                CP16(base + 16384u + so, pb + (size_t)p * 16 * Kp);
            }
        }
        CP_COMMIT;
        CP_WAIT2;
        __syncthreads();

        uint32_t sbase = sb + (uint32_t)(it % GSTAGES) * STG_BYTES;
#pragma unroll
        for (int ks = 0; ks < 4; ks++) {
            uint32_t af[4][4];
#pragma unroll
            for (int mf = 0; mf < 4; mf++)
                LDSM4(af[mf][0], af[mf][1], af[mf][2], af[mf][3],
                      sbase + aRB[mf] + (uint32_t)((((ks << 1) + dselA) ^ aRX[mf]) << 4));
            uint32_t bf[4][4];
#pragma unroll
            for (int np = 0; np < 4; np++)
                LDSM4(bf[np][0], bf[np][1], bf[np][2], bf[np][3],
                      sbase + bRB[np] + (uint32_t)((((ks << 1) + dselB) ^ bRX[np]) << 4));
#pragma unroll
            for (int mf = 0; mf < 4; mf++)
#pragma unroll
                for (int np = 0; np < 4; np++) {
                    MMAH16816(acc[mf][np * 2 + 0], af[mf], bf[np][0], bf[np][1]);
                    MMAH16816(acc[mf][np * 2 + 1], af[mf], bf[np][2], bf[np][3]);
                }
        }
        __syncthreads();
    }

#pragma unroll
    for (int mf = 0; mf < 4; mf++)
#pragma unroll
        for (int rh = 0; rh < 2; rh++) {
            int gr = m0 + wm * 64 + mf * 16 + (lane >> 2) + rh * 8;
            int bi = gr / Mpb;
            int rr = gr - bi * Mpb;
            size_t base = (size_t)bi * outBS + (size_t)(rr + rowOff) * ldc
                        + n0 + wn * 64 + (lane & 3) * 2;
            if (outHalf) {
                __half* rowp = (__half*)Cv + base;
#pragma unroll
                for (int nf = 0; nf < 8; nf++) {
                    __half2 v = __floats2half2_rn(acc[mf][nf][rh * 2 + 0], acc[mf][nf][rh * 2 + 1]);
                    *(__half2*)(rowp + nf * 8) = v;
                }
            } else {
                float* rowp = (float*)Cv + base;
#pragma unroll
                for (int nf = 0; nf < 8; nf++) {
                    float2 v = make_float2(acc[mf][nf][rh * 2 + 0], acc[mf][nf][rh * 2 + 1]);
                    *(float2*)(rowp + nf * 8) = v;
                }
            }
        }
}

// ---------------- RMS-norm (+RoPE) -> fp16, warp-per-row (unchanged) ----------------
__global__ __launch_bounds__(256) void rms_rope_w_kernel(
    const float* __restrict__ buf, __half* __restrict__ outh,
    const float* __restrict__ scale,
    int heads, int rowsPerBatch, int bufRPB, int rowStart, int doRope, float outScale)
{
    int rowIdx = blockIdx.x * 8 + (threadIdx.x >> 5);
    int lane = threadIdx.x & 31;
    int head = rowIdx % heads;
    int tmp = rowIdx / heads;
    int t = tmp % rowsPerBatch;
    int b = tmp / rowsPerBatch;
    size_t off = ((size_t)((size_t)b * bufRPB + rowStart + t) * heads + head) * H_DIM;

    float4 x1 = *(const float4*)(buf + off + lane * 4);
    float4 x2 = *(const float4*)(buf + off + 128 + lane * 4);
    float ss = x1.x * x1.x + x1.y * x1.y + x1.z * x1.z + x1.w * x1.w
             + x2.x * x2.x + x2.y * x2.y + x2.z * x2.z + x2.w * x2.w;
#pragma unroll
    for (int o = 16; o > 0; o >>= 1) ss += __shfl_xor_sync(0xffffffffu, ss, o);
    float rinv = rsqrtf(ss * (1.f / 256.f) + 1e-6f) * outScale;

    float4 s1 = *(const float4*)(scale + lane * 4);
    float4 s2 = *(const float4*)(scale + 128 + lane * 4);
    float y1[4] = { x1.x * rinv * (1.f + s1.x), x1.y * rinv * (1.f + s1.y),
                    x1.z * rinv * (1.f + s1.z), x1.w * rinv * (1.f + s1.w) };
    float y2[4] = { x2.x * rinv * (1.f + s2.x), x2.y * rinv * (1.f + s2.y),
                    x2.z * rinv * (1.f + s2.z), x2.w * rinv * (1.f + s2.w) };
    float o1[4], o2[4];
    if (doRope) {
#pragma unroll
        for (int i = 0; i < 4; i++) {
            float ang = (float)t * exp2f(-(float)(lane * 4 + i) * 0.10381025296522988f);
            float sn, cs;
            sincosf(ang, &sn, &cs);
            o1[i] = y1[i] * cs - y2[i] * sn;
            o2[i] = y2[i] * cs + y1[i] * sn;
        }
    } else {
#pragma unroll
        for (int i = 0; i < 4; i++) { o1[i] = y1[i]; o2[i] = y2[i]; }
    }
    __half2 a0 = __floats2half2_rn(o1[0], o1[1]);
    __half2 a1 = __floats2half2_rn(o1[2], o1[3]);
    __half2 b0 = __floats2half2_rn(o2[0], o2[1]);
    __half2 b1 = __floats2half2_rn(o2[2], o2[3]);
    *(uint2*)(outh + off + lane * 4) = make_uint2(*(uint32_t*)&a0, *(uint32_t*)&a1);
    *(uint2*)(outh + off + 128 + lane * 4) = make_uint2(*(uint32_t*)&b0, *(uint32_t*)&b1);
}

// ---------------- flash v3: 128-row q-tile, register-resident P ----------------
// smem: Q@0 (64K), K st: 65536+st*32768, V st: 131072+st*32768
#define F2_KB 65536u
#define F2_VB 131072u
#define F2_ST 32768u
#define FH2_SMEM 196608

__global__ void __launch_bounds__(256, 1) flash2_hmma(
    const __half* __restrict__ Qh, const __half* __restrict__ Kh,
    const __half* __restrict__ Vh, __half* __restrict__ Oh)
{
    extern __shared__ char smraw[];
    const uint32_t sb = smem_u32(smraw);
    const int tid = threadIdx.x, lane = tid & 31, w = tid >> 5;
    const int qt = blockIdx.x, n = blockIdx.y, b = blockIdx.z;
    const int kh = n >> 1, qbase = qt << 7;

    const char* qg = (const char*)(Qh + ((size_t)(b * T_LEN + qbase) * N_HEADS + n) * H_DIM);
#pragma unroll
    for (int p = 0; p < 16; p++) {
        int idx = tid + p * 256;
        int r = idx >> 5, c = idx & 31;
        CP16(sb + fsw(r, c * 16), qg + (size_t)r * (N_HEADS * H_DIM * 2) + c * 16);
    }
    CP_COMMIT;

    const char* kg = (const char*)(Kh + ((size_t)b * S_LEN * K_HEADS + kh) * H_DIM);
    const char* vg = (const char*)(Vh + ((size_t)b * S_LEN * K_HEADS + kh) * H_DIM);
    const int kvstride = K_HEADS * H_DIM * 2;

    const int nSelf = (qt + 1) << 1;
    const int nT = nSelf + (E_LEN >> 6);

#pragma unroll
    for (int p = 0; p < 8; p++) {
        int idx = tid + p * 256;
        int r = idx >> 5, c = idx & 31;
        uint32_t sw = fsw(r, c * 16);
        CP16(sb + F2_KB + sw, kg + (size_t)r * kvstride + c * 16);
        CP16(sb + F2_VB + sw, vg + (size_t)r * kvstride + c * 16);
    }
    CP_COMMIT;

    float oacc[32][4];
#pragma unroll
    for (int nf = 0; nf < 32; nf++)
#pragma unroll
        for (int q = 0; q < 4; q++) oacc[nf][q] = 0.f;
    float m1 = -INFINITY, m2 = -INFINITY, l1 = 0.f, l2 = 0.f;

    const int r8 = lane & 7, sel = lane >> 3;
    const int rowA = w * 16 + r8 + ((sel & 1) << 3);
    const int dselA = sel >> 1;
    const int dselB = sel & 1;
    const int r1g = w * 16 + (lane >> 2), r2g = r1g + 8;
    const uint32_t aBaseQ = sb + (uint32_t)rowA * 512u;
    const int rowAx = rowA & 7;

    for (int t = 0; t < nT; t++) {
        if (t + 1 < nT) {
            int s0n = (t + 1 < nSelf) ? ((t + 1) << 6) : (T_LEN + ((t + 1 - nSelf) << 6));
            uint32_t kb = sb + F2_KB + (uint32_t)((t + 1) & 1) * F2_ST;
            uint32_t vb = sb + F2_VB + (uint32_t)((t + 1) & 1) * F2_ST;
#pragma unroll
            for (int p = 0; p < 8; p++) {
                int idx = tid + p * 256;
                int r = idx >> 5, c = idx & 31;
                uint32_t sw = fsw(r, c * 16);
                CP16(kb + sw, kg + (size_t)(s0n + r) * kvstride + c * 16);
                CP16(vb + sw, vg + (size_t)(s0n + r) * kvstride + c * 16);
            }
            CP_COMMIT;
            CP_WAIT1;
        } else {
            CP_WAIT0;
        }
        __syncthreads();

        const int s0 = (t < nSelf) ? (t << 6) : (T_LEN + ((t - nSelf) << 6));
        const bool diag = (t >= nSelf - 2) && (t < nSelf);
        const uint32_t sK = sb + F2_KB + (uint32_t)(t & 1) * F2_ST;
        const uint32_t sV = sb + F2_VB + (uint32_t)(t & 1) * F2_ST;

        // ---- S = Q K^T : warp covers 16 rows x 64 cols ----
        float sacc[8][4];
#pragma unroll
        for (int nf = 0; nf < 8; nf++)
#pragma unroll
            for (int q = 0; q < 4; q++) sacc[nf][q] = 0.f;
#pragma unroll 4
        for (int ks = 0; ks < 16; ks++) {
            uint32_t a[4];
            LDSM4(a[0], a[1], a[2], a[3], aBaseQ + (uint32_t)((((ks << 1) + dselA) ^ rowAx) << 4));
#pragma unroll
            for (int nf2 = 0; nf2 < 4; nf2++) {
                int rowB = nf2 * 16 + r8 + ((sel >> 1) << 3);
                uint32_t bb[4];
                LDSM4(bb[0], bb[1], bb[2], bb[3],
                      sK + (uint32_t)rowB * 512u + (uint32_t)((((ks << 1) + dselB) ^ (rowB & 7)) << 4));
                MMAH16816(sacc[nf2 * 2 + 0], a, bb[0], bb[1]);
                MMAH16816(sacc[nf2 * 2 + 1], a, bb[2], bb[3]);
            }
        }

        // ---- softcap + mask + warp-local softmax ----
        float mx1 = -INFINITY, mx2 = -INFINITY;
#pragma unroll
        for (int nf = 0; nf < 8; nf++)
#pragma unroll
            for (int e = 0; e < 4; e++) {
                float s = sacc[nf][e];
                float cpv = 50.f - __fdividef(100.f, __expf(0.04f * s) + 1.f);
                if (diag) {
                    int col = s0 + nf * 8 + ((lane & 3) << 1) + (e & 1);
                    int row = qbase + ((e < 2) ? r1g : r2g);
                    if (col > row) cpv = -INFINITY;
                }
                sacc[nf][e] = cpv;
                if (e < 2) mx1 = fmaxf(mx1, cpv); else mx2 = fmaxf(mx2, cpv);
            }
        mx1 = fmaxf(mx1, __shfl_xor_sync(0xffffffffu, mx1, 1));
        mx1 = fmaxf(mx1, __shfl_xor_sync(0xffffffffu, mx1, 2));
        mx2 = fmaxf(mx2, __shfl_xor_sync(0xffffffffu, mx2, 1));
        mx2 = fmaxf(mx2, __shfl_xor_sync(0xffffffffu, mx2, 2));
        float mn1 = fmaxf(m1, mx1), mn2 = fmaxf(m2, mx2);
        float corr1 = __expf(m1 - mn1), corr2 = __expf(m2 - mn2);
        m1 = mn1; m2 = mn2;

        // ---- P = exp(s-m) packed directly into A-fragments (FA2 register trick) ----
        // pfrag[ks][0..3]: A operand for PV k-chunk ks (S cols 16ks..16ks+15)
        uint32_t pfrag[4][4];
        float sum1 = 0.f, sum2 = 0.f;
#pragma unroll
        for (int nf = 0; nf < 8; nf++) {
            float p0 = __expf(sacc[nf][0] - mn1);
            float p1 = __expf(sacc[nf][1] - mn1);
            float p2 = __expf(sacc[nf][2] - mn2);
            float p3 = __expf(sacc[nf][3] - mn2);
            sum1 += p0 + p1; sum2 += p2 + p3;
            int ks = nf >> 1, hi = nf & 1;
            pfrag[ks][hi * 2 + 0] = packh2(p0, p1);
            pfrag[ks][hi * 2 + 1] = packh2(p2, p3);
        }
        sum1 += __shfl_xor_sync(0xffffffffu, sum1, 1);
        sum1 += __shfl_xor_sync(0xffffffffu, sum1, 2);
        sum2 += __shfl_xor_sync(0xffffffffu, sum2, 1);
        sum2 += __shfl_xor_sync(0xffffffffu, sum2, 2);
        l1 = l1 * corr1 + sum1;
        l2 = l2 * corr2 + sum2;

#pragma unroll
        for (int nf = 0; nf < 32; nf++) {
            oacc[nf][0] *= corr1; oacc[nf][1] *= corr1;
            oacc[nf][2] *= corr2; oacc[nf][3] *= corr2;
        }

        // ---- O += P V (A from registers, B via trans-ldmatrix) ----
#pragma unroll
        for (int ks = 0; ks < 4; ks++) {
            int rowV = ks * 16 + r8 + ((sel & 1) << 3);
            uint32_t vBase = sV + (uint32_t)rowV * 512u;
            int rVx = rowV & 7;
#pragma unroll
            for (int nf2 = 0; nf2 < 16; nf2++) {
                int chunk = nf2 * 2 + (sel >> 1);
                uint32_t bb[4];
                LDSM4T(bb[0], bb[1], bb[2], bb[3], vBase + (uint32_t)((chunk ^ rVx) << 4));
                MMAH16816(oacc[nf2 * 2 + 0], pfrag[ks], bb[0], bb[1]);
                MMAH16816(oacc[nf2 * 2 + 1], pfrag[ks], bb[2], bb[3]);
            }
        }
        __syncthreads();
    }

    float inv1 = 1.f / l1;
    float inv2 = 1.f / l2;
    int t1 = qbase + r1g, t2 = qbase + r2g;
    __half* o1 = Oh + ((size_t)(b * T_LEN + t1)) * (N_HEADS * H_DIM) + n * H_DIM + ((lane & 3) << 1);
    __half* o2 = Oh + ((size_t)(b * T_LEN + t2)) * (N_HEADS * H_DIM) + n * H_DIM + ((lane & 3) << 1);
#pragma unroll
    for (int nf = 0; nf < 32; nf++) {
        __half2 v1 = __floats2half2_rn(oacc[nf][0] * inv1, oacc[nf][1] * inv1);
        __half2 v2 = __floats2half2_rn(oacc[nf][2] * inv2, oacc[nf][3] * inv2);
        *(__half2*)(o1 + nf * 8) = v1;
        *(__half2*)(o2 + nf * 8) = v2;
    }
}

// ---------------- launch ----------------
extern "C" void kernel_launch(void* const* d_in, const int* in_sizes, int n_in,
                              void* d_out, int out_size)
{
    (void)in_sizes; (void)n_in; (void)out_size;
    const float* hs  = (const float*)d_in[0];
    const float* enc = (const float*)d_in[1];
    const float* qw  = (const float*)d_in[4];
    const float* kw  = (const float*)d_in[5];
    const float* vw  = (const float*)d_in[6];
    const float* ow  = (const float*)d_in[7];
    const float* qsc = (const float*)d_in[8];
    const float* ksc = (const float*)d_in[9];
    float* out = (float*)d_out;

    float *qb, *kb;
    cudaGetSymbolAddress((void**)&qb, g_q);
    cudaGetSymbolAddress((void**)&kb, g_k);
    __half *q16, *k16, *v16;
    cudaGetSymbolAddress((void**)&q16, g_q16);
    cudaGetSymbolAddress((void**)&k16, g_k16);
    cudaGetSymbolAddress((void**)&v16, g_v16);
    __half *hs2, *enc2, *qw2, *kw2, *vw2, *ow2, *at2;
    cudaGetSymbolAddress((void**)&hs2, g_hs2);
    cudaGetSymbolAddress((void**)&enc2, g_enc2);
    cudaGetSymbolAddress((void**)&qw2, g_qw2);
    cudaGetSymbolAddress((void**)&kw2, g_kw2);
    cudaGetSymbolAddress((void**)&vw2, g_vw2);
    cudaGetSymbolAddress((void**)&ow2, g_ow2);
    cudaGetSymbolAddress((void**)&at2, g_at2);

    static int cfg = 0;
    if (!cfg) {
        cudaFuncSetAttribute(gemm_hmma, cudaFuncAttributeMaxDynamicSharedMemorySize, GEMM_SMEM);
        cudaFuncSetAttribute(flash2_hmma, cudaFuncAttributeMaxDynamicSharedMemorySize, FH2_SMEM);
        cfg = 1;
    }

    a2h_kernel<<<(4096LL * 2048) / 1024, 256>>>(hs, hs2);
    a2h_kernel<<<(4096LL * 2048) / 1024, 256>>>(enc, enc2);
    wsplit_kernel<<<dim3(4096 / 32, D_DIM / 32), 256>>>(qw, qw2, D_DIM, H_DIM, (long long)D_DIM * H_DIM, H_DIM);
    wsplit_kernel<<<dim3(2048 / 32, D_DIM / 32), 256>>>(kw, kw2, D_DIM, H_DIM, (long long)D_DIM * H_DIM, H_DIM);
    wsplit_kernel<<<dim3(2048 / 32, D_DIM / 32), 256>>>(vw, vw2, D_DIM, H_DIM, (long long)D_DIM * H_DIM, H_DIM);
    wsplit_kernel<<<dim3(2048 / 32, 4096 / 32), 256>>>(ow, ow2, 4096, D_DIM, 0LL, D_DIM);

    const long long kvBS = (long long)S_LEN * K_HEADS * H_DIM;
    gemm_hmma<<<dim3(32, 32), 128, GEMM_SMEM>>>(hs2, qw2, qb, 2048, 4096, 0LL, 0, 4096, 0);
    gemm_hmma<<<dim3(16, 32), 128, GEMM_SMEM>>>(hs2, kw2, kb, 2048, T_LEN, kvBS, 0, 2048, 0);
    gemm_hmma<<<dim3(16, 32), 128, GEMM_SMEM>>>(enc2, kw2, kb, 2048, E_LEN, kvBS, T_LEN, 2048, 0);
    gemm_hmma<<<dim3(16, 32), 128, GEMM_SMEM>>>(hs2, vw2, v16, 2048, T_LEN, kvBS, 0, 2048, 1);
    gemm_hmma<<<dim3(16, 32), 128, GEMM_SMEM>>>(enc2, vw2, v16, 2048, E_LEN, kvBS, T_LEN, 2048, 1);

    rms_rope_w_kernel<<<B_SZ * T_LEN * N_HEADS / 8, 256>>>(qb, q16, qsc, N_HEADS, T_LEN, T_LEN, 0, 1, 0.0625f);
    rms_rope_w_kernel<<<B_SZ * T_LEN * K_HEADS / 8, 256>>>(kb, k16, ksc, K_HEADS, T_LEN, S_LEN, 0, 1, 1.0f);
    rms_rope_w_kernel<<<B_SZ * E_LEN * K_HEADS / 8, 256>>>(kb, k16, ksc, K_HEADS, E_LEN, S_LEN, T_LEN, 0, 1.0f);

    flash2_hmma<<<dim3(T_LEN / 128, N_HEADS, B_SZ), 256, FH2_SMEM>>>(q16, k16, v16, at2);

    gemm_hmma<<<dim3(16, 32), 128, GEMM_SMEM>>>(at2, ow2, out, 4096, 4096, 0LL, 0, 2048, 0);
}

// round 13
// speedup vs baseline: 9.3190x; 1.0848x over previous
#include <cuda_runtime.h>
#include <cuda_fp16.h>
#include <stdint.h>
#include <math.h>

#define B_SZ 4
#define T_LEN 1024
#define E_LEN 1024
#define S_LEN 2048
#define D_DIM 2048
#define H_DIM 256
#define N_HEADS 16
#define K_HEADS 8

__device__ float g_q[(size_t)B_SZ * T_LEN * N_HEADS * H_DIM];
__device__ float g_k[(size_t)B_SZ * S_LEN * K_HEADS * H_DIM];
__device__ __half g_q16[(size_t)B_SZ * T_LEN * N_HEADS * H_DIM];
__device__ __half g_k16[(size_t)B_SZ * S_LEN * K_HEADS * H_DIM];
__device__ __half g_v16[(size_t)B_SZ * S_LEN * K_HEADS * H_DIM];
__device__ __half g_hs2 [(size_t)4096 * 2048];
__device__ __half g_enc2[(size_t)4096 * 2048];
__device__ __half g_qw2 [(size_t)4096 * 2048];
__device__ __half g_kw2 [(size_t)2048 * 2048];
__device__ __half g_vw2 [(size_t)2048 * 2048];
__device__ __half g_ow2 [(size_t)2048 * 4096];
__device__ __half g_at2 [(size_t)4096 * 4096];

// ---------------- helpers ----------------
__device__ __forceinline__ uint32_t smem_u32(const void* p) {
    uint32_t a;
    asm("{ .reg .u64 t; cvta.to.shared.u64 t, %1; cvt.u32.u64 %0, t; }" : "=r"(a) : "l"(p));
    return a;
}
#define CP16(dst, src) \
    asm volatile("cp.async.cg.shared.global [%0], [%1], 16;" :: "r"(dst), "l"(src) : "memory")
#define CP_COMMIT asm volatile("cp.async.commit_group;" ::: "memory")
#define CP_WAIT2  asm volatile("cp.async.wait_group 2;" ::: "memory")
#define CP_WAIT1  asm volatile("cp.async.wait_group 1;" ::: "memory")
#define CP_WAIT0  asm volatile("cp.async.wait_group 0;" ::: "memory")
#define LDSM4(r0, r1, r2, r3, addr) \
    asm volatile("ldmatrix.sync.aligned.m8n8.x4.shared.b16 {%0,%1,%2,%3}, [%4];" \
        : "=r"(r0), "=r"(r1), "=r"(r2), "=r"(r3) : "r"(addr))
#define LDSM4T(r0, r1, r2, r3, addr) \
    asm volatile("ldmatrix.sync.aligned.m8n8.x4.trans.shared.b16 {%0,%1,%2,%3}, [%4];" \
        : "=r"(r0), "=r"(r1), "=r"(r2), "=r"(r3) : "r"(addr))
#define MMAH16816(d, a, b0, b1) \
    asm volatile("mma.sync.aligned.m16n8k16.row.col.f32.f16.f16.f32 " \
        "{%0,%1,%2,%3}, {%4,%5,%6,%7}, {%8,%9}, {%0,%1,%2,%3};" \
        : "+f"((d)[0]), "+f"((d)[1]), "+f"((d)[2]), "+f"((d)[3]) \
        : "r"((a)[0]), "r"((a)[1]), "r"((a)[2]), "r"((a)[3]), "r"(b0), "r"(b1))

__device__ __forceinline__ uint32_t gsw(int row, int kchunk) {
    return (uint32_t)(row * 128 + ((kchunk ^ (row & 7)) << 4));
}
__device__ __forceinline__ uint32_t fsw(int row, int kbyte) {
    return (uint32_t)(row * 512 + ((((kbyte >> 4) ^ (row & 7))) << 4) + (kbyte & 15));
}
__device__ __forceinline__ uint32_t packh2(float a, float b) {
    __half2 h = __floats2half2_rn(a, b);
    return *(uint32_t*)&h;
}

// ---------------- convert kernels ----------------
__global__ __launch_bounds__(256) void a2h_kernel(
    const float* __restrict__ X, __half* __restrict__ Y)
{
    size_t idx = ((size_t)blockIdx.x * 256 + threadIdx.x) * 4;
    float4 v = *(const float4*)(X + idx);
    __half2 h0 = __floats2half2_rn(v.x, v.y);
    __half2 h1 = __floats2half2_rn(v.z, v.w);
    *(uint2*)(Y + idx) = make_uint2(*(uint32_t*)&h0, *(uint32_t*)&h1);
}

__global__ __launch_bounds__(256) void wsplit_kernel(
    const float* __restrict__ W, __half* __restrict__ Yt,
    int Kd, int cph, long long hstr, int krs)
{
    __shared__ float t[32][33];
    int k0 = blockIdx.y * 32, j0 = blockIdx.x * 32;
    int tx = threadIdx.x & 31, ty8 = threadIdx.x >> 5;
#pragma unroll
    for (int i = 0; i < 4; i++) {
        int kl = ty8 + i * 8;
        int j = j0 + tx;
        t[kl][tx] = W[(size_t)(j / cph) * hstr + (size_t)(k0 + kl) * krs + (j % cph)];
    }
    __syncthreads();
#pragma unroll
    for (int i = 0; i < 4; i++) {
        int j = j0 + ty8 + i * 8;
        int k = k0 + tx;
        Yt[(size_t)j * Kd + k] = __float2half(t[tx][ty8 + i * 8]);
    }
}

// ---------------- HMMA fp16 GEMM (unchanged) ----------------
#define GSTAGES 3
#define STG_BYTES 32768
#define GEMM_SMEM (GSTAGES * STG_BYTES)

__global__ void __launch_bounds__(128, 2) gemm_hmma(
    const __half* __restrict__ A, const __half* __restrict__ Bw,
    void* __restrict__ Cv, int Kp, int Mpb, long long outBS, int rowOff, int ldc,
    int outHalf)
{
    extern __shared__ char smraw[];
    const uint32_t sb = smem_u32(smraw);
    const int tid = threadIdx.x;
    const int lane = tid & 31, wid = tid >> 5;
    const int wm = wid & 1, wn = wid >> 1;
    const int m0 = blockIdx.y * 128, n0 = blockIdx.x * 128;
    const int nIter = Kp >> 6;

    const int crow = tid >> 3;
    const int ckc = tid & 7;
    const uint32_t csw = gsw(crow, ckc);
    const __half* ga = A + (size_t)(m0 + crow) * Kp + ckc * 8;
    const __half* gb = Bw + (size_t)(n0 + crow) * Kp + ckc * 8;

    const int r8 = lane & 7, sel = lane >> 3;
    uint32_t aRB[4]; int aRX[4];
    const int dselA = sel >> 1;
#pragma unroll
    for (int mf = 0; mf < 4; mf++) {
        int row = wm * 64 + mf * 16 + r8 + ((sel & 1) << 3);
        aRB[mf] = (uint32_t)(row * 128);
        aRX[mf] = row & 7;
    }
    uint32_t bRB[4]; int bRX[4];
    const int dselB = sel & 1;
#pragma unroll
    for (int np = 0; np < 4; np++) {
        int row = wn * 64 + np * 16 + r8 + ((sel >> 1) << 3);
        bRB[np] = 16384u + (uint32_t)(row * 128);
        bRX[np] = row & 7;
    }

    float acc[4][8][4];
#pragma unroll
    for (int mf = 0; mf < 4; mf++)
#pragma unroll
        for (int nf = 0; nf < 8; nf++)
#pragma unroll
            for (int q = 0; q < 4; q++) acc[mf][nf][q] = 0.f;

#pragma unroll
    for (int s = 0; s < 2; s++) {
        uint32_t base = sb + (uint32_t)s * STG_BYTES;
        const __half* pa = ga + s * 64;
        const __half* pb = gb + s * 64;
#pragma unroll
        for (int p = 0; p < 8; p++) {
            uint32_t so = csw + (uint32_t)p * 2048u;
            CP16(base + so, pa + (size_t)p * 16 * Kp);
            CP16(base + 16384u + so, pb + (size_t)p * 16 * Kp);
        }
        CP_COMMIT;
    }

    for (int it = 0; it < nIter; it++) {
        if (it + 2 < nIter) {
            int s = (it + 2) % GSTAGES;
            uint32_t base = sb + (uint32_t)s * STG_BYTES;
            const __half* pa = ga + (size_t)(it + 2) * 64;
            const __half* pb = gb + (size_t)(it + 2) * 64;
#pragma unroll
            for (int p = 0; p < 8; p++) {
                uint32_t so = csw + (uint32_t)p * 2048u;
                CP16(base + so, pa + (size_t)p * 16 * Kp);
                CP16(base + 16384u + so, pb + (size_t)p * 16 * Kp);
            }
        }
        CP_COMMIT;
        CP_WAIT2;
        __syncthreads();

        uint32_t sbase = sb + (uint32_t)(it % GSTAGES) * STG_BYTES;
#pragma unroll
        for (int ks = 0; ks < 4; ks++) {
            uint32_t af[4][4];
#pragma unroll
            for (int mf = 0; mf < 4; mf++)
                LDSM4(af[mf][0], af[mf][1], af[mf][2], af[mf][3],
                      sbase + aRB[mf] + (uint32_t)((((ks << 1) + dselA) ^ aRX[mf]) << 4));
            uint32_t bf[4][4];
#pragma unroll
            for (int np = 0; np < 4; np++)
                LDSM4(bf[np][0], bf[np][1], bf[np][2], bf[np][3],
                      sbase + bRB[np] + (uint32_t)((((ks << 1) + dselB) ^ bRX[np]) << 4));
#pragma unroll
            for (int mf = 0; mf < 4; mf++)
#pragma unroll
                for (int np = 0; np < 4; np++) {
                    MMAH16816(acc[mf][np * 2 + 0], af[mf], bf[np][0], bf[np][1]);
                    MMAH16816(acc[mf][np * 2 + 1], af[mf], bf[np][2], bf[np][3]);
                }
        }
        __syncthreads();
    }

#pragma unroll
    for (int mf = 0; mf < 4; mf++)
#pragma unroll
        for (int rh = 0; rh < 2; rh++) {
            int gr = m0 + wm * 64 + mf * 16 + (lane >> 2) + rh * 8;
            int bi = gr / Mpb;
            int rr = gr - bi * Mpb;
            size_t base = (size_t)bi * outBS + (size_t)(rr + rowOff) * ldc
                        + n0 + wn * 64 + (lane & 3) * 2;
            if (outHalf) {
                __half* rowp = (__half*)Cv + base;
#pragma unroll
                for (int nf = 0; nf < 8; nf++) {
                    __half2 v = __floats2half2_rn(acc[mf][nf][rh * 2 + 0], acc[mf][nf][rh * 2 + 1]);
                    *(__half2*)(rowp + nf * 8) = v;
                }
            } else {
                float* rowp = (float*)Cv + base;
#pragma unroll
                for (int nf = 0; nf < 8; nf++) {
                    float2 v = make_float2(acc[mf][nf][rh * 2 + 0], acc[mf][nf][rh * 2 + 1]);
                    *(float2*)(rowp + nf * 8) = v;
                }
            }
        }
}

// ---------------- RMS-norm (+RoPE) -> fp16, warp-per-row (unchanged) ----------------
__global__ __launch_bounds__(256) void rms_rope_w_kernel(
    const float* __restrict__ buf, __half* __restrict__ outh,
    const float* __restrict__ scale,
    int heads, int rowsPerBatch, int bufRPB, int rowStart, int doRope, float outScale)
{
    int rowIdx = blockIdx.x * 8 + (threadIdx.x >> 5);
    int lane = threadIdx.x & 31;
    int head = rowIdx % heads;
    int tmp = rowIdx / heads;
    int t = tmp % rowsPerBatch;
    int b = tmp / rowsPerBatch;
    size_t off = ((size_t)((size_t)b * bufRPB + rowStart + t) * heads + head) * H_DIM;

    float4 x1 = *(const float4*)(buf + off + lane * 4);
    float4 x2 = *(const float4*)(buf + off + 128 + lane * 4);
    float ss = x1.x * x1.x + x1.y * x1.y + x1.z * x1.z + x1.w * x1.w
             + x2.x * x2.x + x2.y * x2.y + x2.z * x2.z + x2.w * x2.w;
#pragma unroll
    for (int o = 16; o > 0; o >>= 1) ss += __shfl_xor_sync(0xffffffffu, ss, o);
    float rinv = rsqrtf(ss * (1.f / 256.f) + 1e-6f) * outScale;

    float4 s1 = *(const float4*)(scale + lane * 4);
    float4 s2 = *(const float4*)(scale + 128 + lane * 4);
    float y1[4] = { x1.x * rinv * (1.f + s1.x), x1.y * rinv * (1.f + s1.y),
                    x1.z * rinv * (1.f + s1.z), x1.w * rinv * (1.f + s1.w) };
    float y2[4] = { x2.x * rinv * (1.f + s2.x), x2.y * rinv * (1.f + s2.y),
                    x2.z * rinv * (1.f + s2.z), x2.w * rinv * (1.f + s2.w) };
    float o1[4], o2[4];
    if (doRope) {
#pragma unroll
        for (int i = 0; i < 4; i++) {
            float ang = (float)t * exp2f(-(float)(lane * 4 + i) * 0.10381025296522988f);
            float sn, cs;
            sincosf(ang, &sn, &cs);
            o1[i] = y1[i] * cs - y2[i] * sn;
            o2[i] = y2[i] * cs + y1[i] * sn;
        }
    } else {
#pragma unroll
        for (int i = 0; i < 4; i++) { o1[i] = y1[i]; o2[i] = y2[i]; }
    }
    __half2 a0 = __floats2half2_rn(o1[0], o1[1]);
    __half2 a1 = __floats2half2_rn(o1[2], o1[3]);
    __half2 b0 = __floats2half2_rn(o2[0], o2[1]);
    __half2 b1 = __floats2half2_rn(o2[2], o2[3]);
    *(uint2*)(outh + off + lane * 4) = make_uint2(*(uint32_t*)&a0, *(uint32_t*)&a1);
    *(uint2*)(outh + off + 128 + lane * 4) = make_uint2(*(uint32_t*)&b0, *(uint32_t*)&b1);
}

// ---------------- flash v3 (unchanged R11) ----------------
#define F2_KB 65536u
#define F2_VB 131072u
#define F2_ST 32768u
#define FH2_SMEM 196608

__global__ void __launch_bounds__(256, 1) flash2_hmma(
    const __half* __restrict__ Qh, const __half* __restrict__ Kh,
    const __half* __restrict__ Vh, __half* __restrict__ Oh)
{
    extern __shared__ char smraw[];
    const uint32_t sb = smem_u32(smraw);
    const int tid = threadIdx.x, lane = tid & 31, w = tid >> 5;
    const int qt = blockIdx.x, n = blockIdx.y, b = blockIdx.z;
    const int kh = n >> 1, qbase = qt << 7;

    const char* qg = (const char*)(Qh + ((size_t)(b * T_LEN + qbase) * N_HEADS + n) * H_DIM);
#pragma unroll
    for (int p = 0; p < 16; p++) {
        int idx = tid + p * 256;
        int r = idx >> 5, c = idx & 31;
        CP16(sb + fsw(r, c * 16), qg + (size_t)r * (N_HEADS * H_DIM * 2) + c * 16);
    }
    CP_COMMIT;

    const char* kg = (const char*)(Kh + ((size_t)b * S_LEN * K_HEADS + kh) * H_DIM);
    const char* vg = (const char*)(Vh + ((size_t)b * S_LEN * K_HEADS + kh) * H_DIM);
    const int kvstride = K_HEADS * H_DIM * 2;

    const int nSelf = (qt + 1) << 1;
    const int nT = nSelf + (E_LEN >> 6);

#pragma unroll
    for (int p = 0; p < 8; p++) {
        int idx = tid + p * 256;
        int r = idx >> 5, c = idx & 31;
        uint32_t sw = fsw(r, c * 16);
        CP16(sb + F2_KB + sw, kg + (size_t)r * kvstride + c * 16);
        CP16(sb + F2_VB + sw, vg + (size_t)r * kvstride + c * 16);
    }
    CP_COMMIT;

    float oacc[32][4];
#pragma unroll
    for (int nf = 0; nf < 32; nf++)
#pragma unroll
        for (int q = 0; q < 4; q++) oacc[nf][q] = 0.f;
    float m1 = -INFINITY, m2 = -INFINITY, l1 = 0.f, l2 = 0.f;

    const int r8 = lane & 7, sel = lane >> 3;
    const int rowA = w * 16 + r8 + ((sel & 1) << 3);
    const int dselA = sel >> 1;
    const int dselB = sel & 1;
    const int r1g = w * 16 + (lane >> 2), r2g = r1g + 8;
    const uint32_t aBaseQ = sb + (uint32_t)rowA * 512u;
    const int rowAx = rowA & 7;

    for (int t = 0; t < nT; t++) {
        if (t + 1 < nT) {
            int s0n = (t + 1 < nSelf) ? ((t + 1) << 6) : (T_LEN + ((t + 1 - nSelf) << 6));
            uint32_t kb = sb + F2_KB + (uint32_t)((t + 1) & 1) * F2_ST;
            uint32_t vb = sb + F2_VB + (uint32_t)((t + 1) & 1) * F2_ST;
#pragma unroll
            for (int p = 0; p < 8; p++) {
                int idx = tid + p * 256;
                int r = idx >> 5, c = idx & 31;
                uint32_t sw = fsw(r, c * 16);
                CP16(kb + sw, kg + (size_t)(s0n + r) * kvstride + c * 16);
                CP16(vb + sw, vg + (size_t)(s0n + r) * kvstride + c * 16);
            }
            CP_COMMIT;
            CP_WAIT1;
        } else {
            CP_WAIT0;
        }
        __syncthreads();

        const int s0 = (t < nSelf) ? (t << 6) : (T_LEN + ((t - nSelf) << 6));
        const bool diag = (t >= nSelf - 2) && (t < nSelf);
        const uint32_t sK = sb + F2_KB + (uint32_t)(t & 1) * F2_ST;
        const uint32_t sV = sb + F2_VB + (uint32_t)(t & 1) * F2_ST;

        float sacc[8][4];
#pragma unroll
        for (int nf = 0; nf < 8; nf++)
#pragma unroll
            for (int q = 0; q < 4; q++) sacc[nf][q] = 0.f;
#pragma unroll 4
        for (int ks = 0; ks < 16; ks++) {
            uint32_t a[4];
            LDSM4(a[0], a[1], a[2], a[3], aBaseQ + (uint32_t)((((ks << 1) + dselA) ^ rowAx) << 4));
#pragma unroll
            for (int nf2 = 0; nf2 < 4; nf2++) {
                int rowB = nf2 * 16 + r8 + ((sel >> 1) << 3);
                uint32_t bb[4];
                LDSM4(bb[0], bb[1], bb[2], bb[3],
                      sK + (uint32_t)rowB * 512u + (uint32_t)((((ks << 1) + dselB) ^ (rowB & 7)) << 4));
                MMAH16816(sacc[nf2 * 2 + 0], a, bb[0], bb[1]);
                MMAH16816(sacc[nf2 * 2 + 1], a, bb[2], bb[3]);
            }
        }

        float mx1 = -INFINITY, mx2 = -INFINITY;
#pragma unroll
        for (int nf = 0; nf < 8; nf++)
#pragma unroll
            for (int e = 0; e < 4; e++) {
                float s = sacc[nf][e];
                float cpv = 50.f - __fdividef(100.f, __expf(0.04f * s) + 1.f);
                if (diag) {
                    int col = s0 + nf * 8 + ((lane & 3) << 1) + (e & 1);
                    int row = qbase + ((e < 2) ? r1g : r2g);
                    if (col > row) cpv = -INFINITY;
                }
                sacc[nf][e] = cpv;
                if (e < 2) mx1 = fmaxf(mx1, cpv); else mx2 = fmaxf(mx2, cpv);
            }
        mx1 = fmaxf(mx1, __shfl_xor_sync(0xffffffffu, mx1, 1));
        mx1 = fmaxf(mx1, __shfl_xor_sync(0xffffffffu, mx1, 2));
        mx2 = fmaxf(mx2, __shfl_xor_sync(0xffffffffu, mx2, 1));
        mx2 = fmaxf(mx2, __shfl_xor_sync(0xffffffffu, mx2, 2));
        float mn1 = fmaxf(m1, mx1), mn2 = fmaxf(m2, mx2);
        float corr1 = __expf(m1 - mn1), corr2 = __expf(m2 - mn2);
        m1 = mn1; m2 = mn2;

        uint32_t pfrag[4][4];
        float sum1 = 0.f, sum2 = 0.f;
#pragma unroll
        for (int nf = 0; nf < 8; nf++) {
            float p0 = __expf(sacc[nf][0] - mn1);
            float p1 = __expf(sacc[nf][1] - mn1);
            float p2 = __expf(sacc[nf][2] - mn2);
            float p3 = __expf(sacc[nf][3] - mn2);
            sum1 += p0 + p1; sum2 += p2 + p3;
            int ks = nf >> 1, hi = nf & 1;
            pfrag[ks][hi * 2 + 0] = packh2(p0, p1);
            pfrag[ks][hi * 2 + 1] = packh2(p2, p3);
        }
        sum1 += __shfl_xor_sync(0xffffffffu, sum1, 1);
        sum1 += __shfl_xor_sync(0xffffffffu, sum1, 2);
        sum2 += __shfl_xor_sync(0xffffffffu, sum2, 1);
        sum2 += __shfl_xor_sync(0xffffffffu, sum2, 2);
        l1 = l1 * corr1 + sum1;
        l2 = l2 * corr2 + sum2;

#pragma unroll
        for (int nf = 0; nf < 32; nf++) {
            oacc[nf][0] *= corr1; oacc[nf][1] *= corr1;
            oacc[nf][2] *= corr2; oacc[nf][3] *= corr2;
        }

#pragma unroll
        for (int ks = 0; ks < 4; ks++) {
            int rowV = ks * 16 + r8 + ((sel & 1) << 3);
            uint32_t vBase = sV + (uint32_t)rowV * 512u;
            int rVx = rowV & 7;
#pragma unroll
            for (int nf2 = 0; nf2 < 16; nf2++) {
                int chunk = nf2 * 2 + (sel >> 1);
                uint32_t bb[4];
                LDSM4T(bb[0], bb[1], bb[2], bb[3], vBase + (uint32_t)((chunk ^ rVx) << 4));
                MMAH16816(oacc[nf2 * 2 + 0], pfrag[ks], bb[0], bb[1]);
                MMAH16816(oacc[nf2 * 2 + 1], pfrag[ks], bb[2], bb[3]);
            }
        }
        __syncthreads();
    }

    float inv1 = 1.f / l1;
    float inv2 = 1.f / l2;
    int t1 = qbase + r1g, t2 = qbase + r2g;
    __half* o1 = Oh + ((size_t)(b * T_LEN + t1)) * (N_HEADS * H_DIM) + n * H_DIM + ((lane & 3) << 1);
    __half* o2 = Oh + ((size_t)(b * T_LEN + t2)) * (N_HEADS * H_DIM) + n * H_DIM + ((lane & 3) << 1);
#pragma unroll
    for (int nf = 0; nf < 32; nf++) {
        __half2 v1 = __floats2half2_rn(oacc[nf][0] * inv1, oacc[nf][1] * inv1);
        __half2 v2 = __floats2half2_rn(oacc[nf][2] * inv2, oacc[nf][3] * inv2);
        *(__half2*)(o1 + nf * 8) = v1;
        *(__half2*)(o2 + nf * 8) = v2;
    }
}

// ---------------- launch: multi-stream DAG with proper capture fork/join ----------------
extern "C" void kernel_launch(void* const* d_in, const int* in_sizes, int n_in,
                              void* d_out, int out_size)
{
    (void)in_sizes; (void)n_in; (void)out_size;
    const float* hs  = (const float*)d_in[0];
    const float* enc = (const float*)d_in[1];
    const float* qw  = (const float*)d_in[4];
    const float* kw  = (const float*)d_in[5];
    const float* vw  = (const float*)d_in[6];
    const float* ow  = (const float*)d_in[7];
    const float* qsc = (const float*)d_in[8];
    const float* ksc = (const float*)d_in[9];
    float* out = (float*)d_out;

    float *qb, *kb;
    cudaGetSymbolAddress((void**)&qb, g_q);
    cudaGetSymbolAddress((void**)&kb, g_k);
    __half *q16, *k16, *v16;
    cudaGetSymbolAddress((void**)&q16, g_q16);
    cudaGetSymbolAddress((void**)&k16, g_k16);
    cudaGetSymbolAddress((void**)&v16, g_v16);
    __half *hs2, *enc2, *qw2, *kw2, *vw2, *ow2, *at2;
    cudaGetSymbolAddress((void**)&hs2, g_hs2);
    cudaGetSymbolAddress((void**)&enc2, g_enc2);
    cudaGetSymbolAddress((void**)&qw2, g_qw2);
    cudaGetSymbolAddress((void**)&kw2, g_kw2);
    cudaGetSymbolAddress((void**)&vw2, g_vw2);
    cudaGetSymbolAddress((void**)&ow2, g_ow2);
    cudaGetSymbolAddress((void**)&at2, g_at2);

    static int cfg = 0;
    static cudaStream_t s1, s2;
    static cudaEvent_t eFork, eHs, eEnc, eQw, eKw, eKdone, eVdone, eOw;
    if (!cfg) {
        cudaFuncSetAttribute(gemm_hmma, cudaFuncAttributeMaxDynamicSharedMemorySize, GEMM_SMEM);
        cudaFuncSetAttribute(flash2_hmma, cudaFuncAttributeMaxDynamicSharedMemorySize, FH2_SMEM);
        cudaStreamCreateWithFlags(&s1, cudaStreamNonBlocking);
        cudaStreamCreateWithFlags(&s2, cudaStreamNonBlocking);
        cudaEventCreateWithFlags(&eFork, cudaEventDisableTiming);
        cudaEventCreateWithFlags(&eHs, cudaEventDisableTiming);
        cudaEventCreateWithFlags(&eEnc, cudaEventDisableTiming);
        cudaEventCreateWithFlags(&eQw, cudaEventDisableTiming);
        cudaEventCreateWithFlags(&eKw, cudaEventDisableTiming);
        cudaEventCreateWithFlags(&eKdone, cudaEventDisableTiming);
        cudaEventCreateWithFlags(&eVdone, cudaEventDisableTiming);
        cudaEventCreateWithFlags(&eOw, cudaEventDisableTiming);
        cfg = 1;
    }

    const long long kvBS = (long long)S_LEN * K_HEADS * H_DIM;
    const long long pHS = (long long)D_DIM * H_DIM;

    // --- FORK: side streams must join capture via an event from the origin stream ---
    cudaEventRecord(eFork, 0);
    cudaStreamWaitEvent(s1, eFork, 0);
    cudaStreamWaitEvent(s2, eFork, 0);

    // s0: hs convert
    a2h_kernel<<<(4096LL * 2048) / 1024, 256, 0, 0>>>(hs, hs2);
    cudaEventRecord(eHs, 0);
    // s1: enc convert
    a2h_kernel<<<(4096LL * 2048) / 1024, 256, 0, s1>>>(enc, enc2);
    cudaEventRecord(eEnc, s1);
    // s2: weight converts (qw, kw, vw)
    wsplit_kernel<<<dim3(4096 / 32, D_DIM / 32), 256, 0, s2>>>(qw, qw2, D_DIM, H_DIM, pHS, H_DIM);
    cudaEventRecord(eQw, s2);
    wsplit_kernel<<<dim3(2048 / 32, D_DIM / 32), 256, 0, s2>>>(kw, kw2, D_DIM, H_DIM, pHS, H_DIM);
    cudaEventRecord(eKw, s2);
    wsplit_kernel<<<dim3(2048 / 32, D_DIM / 32), 256, 0, s2>>>(vw, vw2, D_DIM, H_DIM, pHS, H_DIM);

    // s0: Q path (hs2 in-order; wait qw2)
    cudaStreamWaitEvent(0, eQw, 0);
    gemm_hmma<<<dim3(32, 32), 128, GEMM_SMEM, 0>>>(hs2, qw2, qb, 2048, 4096, 0LL, 0, 4096, 0);
    rms_rope_w_kernel<<<B_SZ * T_LEN * N_HEADS / 8, 256, 0, 0>>>(qb, q16, qsc, N_HEADS, T_LEN, T_LEN, 0, 1, 0.0625f);

    // s1: K path (enc2 in-order; wait hs2, kw2)
    cudaStreamWaitEvent(s1, eHs, 0);
    cudaStreamWaitEvent(s1, eKw, 0);
    gemm_hmma<<<dim3(16, 32), 128, GEMM_SMEM, s1>>>(hs2, kw2, kb, 2048, T_LEN, kvBS, 0, 2048, 0);
    gemm_hmma<<<dim3(16, 32), 128, GEMM_SMEM, s1>>>(enc2, kw2, kb, 2048, E_LEN, kvBS, T_LEN, 2048, 0);
    rms_rope_w_kernel<<<B_SZ * T_LEN * K_HEADS / 8, 256, 0, s1>>>(kb, k16, ksc, K_HEADS, T_LEN, S_LEN, 0, 1, 1.0f);
    rms_rope_w_kernel<<<B_SZ * E_LEN * K_HEADS / 8, 256, 0, s1>>>(kb, k16, ksc, K_HEADS, E_LEN, S_LEN, T_LEN, 0, 1.0f);
    cudaEventRecord(eKdone, s1);

    // s2: V path (vw2 in-order; wait hs2, enc2)
    cudaStreamWaitEvent(s2, eHs, 0);
    cudaStreamWaitEvent(s2, eEnc, 0);
    gemm_hmma<<<dim3(16, 32), 128, GEMM_SMEM, s2>>>(hs2, vw2, v16, 2048, T_LEN, kvBS, 0, 2048, 1);
    gemm_hmma<<<dim3(16, 32), 128, GEMM_SMEM, s2>>>(enc2, vw2, v16, 2048, E_LEN, kvBS, T_LEN, 2048, 1);
    cudaEventRecord(eVdone, s2);
    // ow convert on s2 (overlaps flash)
    wsplit_kernel<<<dim3(2048 / 32, 4096 / 32), 256, 0, s2>>>(ow, ow2, 4096, D_DIM, 0LL, D_DIM);
    cudaEventRecord(eOw, s2);

    // s0: flash (JOIN: waits K path and V path)
    cudaStreamWaitEvent(0, eKdone, 0);
    cudaStreamWaitEvent(0, eVdone, 0);
    flash2_hmma<<<dim3(T_LEN / 128, N_HEADS, B_SZ), 256, FH2_SMEM, 0>>>(q16, k16, v16, at2);

    // s0: O-GEMM (JOIN: waits ow2)
    cudaStreamWaitEvent(0, eOw, 0);
    gemm_hmma<<<dim3(16, 32), 128, GEMM_SMEM, 0>>>(at2, ow2, out, 4096, 4096, 0LL, 0, 2048, 0);
}

// round 14
// speedup vs baseline: 9.4385x; 1.0128x over previous
#include <cuda_runtime.h>
#include <cuda_fp16.h>
#include <stdint.h>
#include <math.h>

#define B_SZ 4
#define T_LEN 1024
#define E_LEN 1024
#define S_LEN 2048
#define D_DIM 2048
#define H_DIM 256
#define N_HEADS 16
#define K_HEADS 8

__device__ float g_q[(size_t)B_SZ * T_LEN * N_HEADS * H_DIM];
__device__ float g_k[(size_t)B_SZ * S_LEN * K_HEADS * H_DIM];
__device__ __half g_q16[(size_t)B_SZ * T_LEN * N_HEADS * H_DIM];
__device__ __half g_k16[(size_t)B_SZ * S_LEN * K_HEADS * H_DIM];
__device__ __half g_v16[(size_t)B_SZ * S_LEN * K_HEADS * H_DIM];
__device__ __half g_hs2 [(size_t)4096 * 2048];
__device__ __half g_enc2[(size_t)4096 * 2048];
__device__ __half g_qw2 [(size_t)4096 * 2048];
__device__ __half g_kw2 [(size_t)2048 * 2048];
__device__ __half g_vw2 [(size_t)2048 * 2048];
__device__ __half g_ow2 [(size_t)2048 * 4096];
__device__ __half g_at2 [(size_t)4096 * 4096];

// ---------------- helpers ----------------
__device__ __forceinline__ uint32_t smem_u32(const void* p) {
    uint32_t a;
    asm("{ .reg .u64 t; cvta.to.shared.u64 t, %1; cvt.u32.u64 %0, t; }" : "=r"(a) : "l"(p));
    return a;
}
#define CP16(dst, src) \
    asm volatile("cp.async.cg.shared.global [%0], [%1], 16;" :: "r"(dst), "l"(src) : "memory")
#define CP_COMMIT asm volatile("cp.async.commit_group;" ::: "memory")
#define CP_WAIT2  asm volatile("cp.async.wait_group 2;" ::: "memory")
#define CP_WAIT1  asm volatile("cp.async.wait_group 1;" ::: "memory")
#define CP_WAIT0  asm volatile("cp.async.wait_group 0;" ::: "memory")
#define LDSM4(r0, r1, r2, r3, addr) \
    asm volatile("ldmatrix.sync.aligned.m8n8.x4.shared.b16 {%0,%1,%2,%3}, [%4];" \
        : "=r"(r0), "=r"(r1), "=r"(r2), "=r"(r3) : "r"(addr))
#define LDSM4T(r0, r1, r2, r3, addr) \
    asm volatile("ldmatrix.sync.aligned.m8n8.x4.trans.shared.b16 {%0,%1,%2,%3}, [%4];" \
        : "=r"(r0), "=r"(r1), "=r"(r2), "=r"(r3) : "r"(addr))
#define MMAH16816(d, a, b0, b1) \
    asm volatile("mma.sync.aligned.m16n8k16.row.col.f32.f16.f16.f32 " \
        "{%0,%1,%2,%3}, {%4,%5,%6,%7}, {%8,%9}, {%0,%1,%2,%3};" \
        : "+f"((d)[0]), "+f"((d)[1]), "+f"((d)[2]), "+f"((d)[3]) \
        : "r"((a)[0]), "r"((a)[1]), "r"((a)[2]), "r"((a)[3]), "r"(b0), "r"(b1))

__device__ __forceinline__ uint32_t gsw(int row, int kchunk) {
    return (uint32_t)(row * 128 + ((kchunk ^ (row & 7)) << 4));
}
__device__ __forceinline__ uint32_t fsw(int row, int kbyte) {
    return (uint32_t)(row * 512 + ((((kbyte >> 4) ^ (row & 7))) << 4) + (kbyte & 15));
}
__device__ __forceinline__ uint32_t packh2(float a, float b) {
    __half2 h = __floats2half2_rn(a, b);
    return *(uint32_t*)&h;
}

// ---------------- convert kernels ----------------
__global__ __launch_bounds__(256) void a2h_kernel(
    const float* __restrict__ X, __half* __restrict__ Y)
{
    size_t idx = ((size_t)blockIdx.x * 256 + threadIdx.x) * 4;
    float4 v = *(const float4*)(X + idx);
    __half2 h0 = __floats2half2_rn(v.x, v.y);
    __half2 h1 = __floats2half2_rn(v.z, v.w);
    *(uint2*)(Y + idx) = make_uint2(*(uint32_t*)&h0, *(uint32_t*)&h1);
}

__global__ __launch_bounds__(256) void wsplit_kernel(
    const float* __restrict__ W, __half* __restrict__ Yt,
    int Kd, int cph, long long hstr, int krs)
{
    __shared__ float t[32][33];
    int k0 = blockIdx.y * 32, j0 = blockIdx.x * 32;
    int tx = threadIdx.x & 31, ty8 = threadIdx.x >> 5;
#pragma unroll
    for (int i = 0; i < 4; i++) {
        int kl = ty8 + i * 8;
        int j = j0 + tx;
        t[kl][tx] = W[(size_t)(j / cph) * hstr + (size_t)(k0 + kl) * krs + (j % cph)];
    }
    __syncthreads();
#pragma unroll
    for (int i = 0; i < 4; i++) {
        int j = j0 + ty8 + i * 8;
        int k = k0 + tx;
        Yt[(size_t)j * Kd + k] = __float2half(t[tx][ty8 + i * 8]);
    }
}

// ---------------- HMMA fp16 GEMM (R9 core + M-tile mapping) ----------------
#define GSTAGES 3
#define STG_BYTES 32768
#define GEMM_SMEM (GSTAGES * STG_BYTES)

__global__ void __launch_bounds__(128, 2) gemm_hmma(
    const __half* __restrict__ A, const __half* __restrict__ Bw,
    void* __restrict__ Cv, int Kp, int Mpb, long long outBS, int rowOff, int ldc,
    int outHalf, int mGT, int mGS, int mOff)
{
    extern __shared__ char smraw[];
    const uint32_t sb = smem_u32(smraw);
    const int tid = threadIdx.x;
    const int lane = tid & 31, wid = tid >> 5;
    const int wm = wid & 1, wn = wid >> 1;
    const int m0 = (blockIdx.y / mGT) * mGS + (blockIdx.y % mGT) * 128 + mOff;
    const int n0 = blockIdx.x * 128;
    const int nIter = Kp >> 6;

    const int crow = tid >> 3;
    const int ckc = tid & 7;
    const uint32_t csw = gsw(crow, ckc);
    const __half* ga = A + (size_t)(m0 + crow) * Kp + ckc * 8;
    const __half* gb = Bw + (size_t)(n0 + crow) * Kp + ckc * 8;

    const int r8 = lane & 7, sel = lane >> 3;
    uint32_t aRB[4]; int aRX[4];
    const int dselA = sel >> 1;
#pragma unroll
    for (int mf = 0; mf < 4; mf++) {
        int row = wm * 64 + mf * 16 + r8 + ((sel & 1) << 3);
        aRB[mf] = (uint32_t)(row * 128);
        aRX[mf] = row & 7;
    }
    uint32_t bRB[4]; int bRX[4];
    const int dselB = sel & 1;
#pragma unroll
    for (int np = 0; np < 4; np++) {
        int row = wn * 64 + np * 16 + r8 + ((sel >> 1) << 3);
        bRB[np] = 16384u + (uint32_t)(row * 128);
        bRX[np] = row & 7;
    }

    float acc[4][8][4];
#pragma unroll
    for (int mf = 0; mf < 4; mf++)
#pragma unroll
        for (int nf = 0; nf < 8; nf++)
#pragma unroll
            for (int q = 0; q < 4; q++) acc[mf][nf][q] = 0.f;

#pragma unroll
    for (int s = 0; s < 2; s++) {
        uint32_t base = sb + (uint32_t)s * STG_BYTES;
        const __half* pa = ga + s * 64;
        const __half* pb = gb + s * 64;
#pragma unroll
        for (int p = 0; p < 8; p++) {
            uint32_t so = csw + (uint32_t)p * 2048u;
            CP16(base + so, pa + (size_t)p * 16 * Kp);
            CP16(base + 16384u + so, pb + (size_t)p * 16 * Kp);
        }
        CP_COMMIT;
    }

    for (int it = 0; it < nIter; it++) {
        if (it + 2 < nIter) {
            int s = (it + 2) % GSTAGES;
            uint32_t base = sb + (uint32_t)s * STG_BYTES;
            const __half* pa = ga + (size_t)(it + 2) * 64;
            const __half* pb = gb + (size_t)(it + 2) * 64;
#pragma unroll
            for (int p = 0; p < 8; p++) {
                uint32_t so = csw + (uint32_t)p * 2048u;
                CP16(base + so, pa + (size_t)p * 16 * Kp);
                CP16(base + 16384u + so, pb + (size_t)p * 16 * Kp);
            }
        }
        CP_COMMIT;
        CP_WAIT2;
        __syncthreads();

        uint32_t sbase = sb + (uint32_t)(it % GSTAGES) * STG_BYTES;
#pragma unroll
        for (int ks = 0; ks < 4; ks++) {
            uint32_t af[4][4];
#pragma unroll
            for (int mf = 0; mf < 4; mf++)
                LDSM4(af[mf][0], af[mf][1], af[mf][2], af[mf][3],
                      sbase + aRB[mf] + (uint32_t)((((ks << 1) + dselA) ^ aRX[mf]) << 4));
            uint32_t bf[4][4];
#pragma unroll
            for (int np = 0; np < 4; np++)
                LDSM4(bf[np][0], bf[np][1], bf[np][2], bf[np][3],
                      sbase + bRB[np] + (uint32_t)((((ks << 1) + dselB) ^ bRX[np]) << 4));
#pragma unroll
            for (int mf = 0; mf < 4; mf++)
#pragma unroll
                for (int np = 0; np < 4; np++) {
                    MMAH16816(acc[mf][np * 2 + 0], af[mf], bf[np][0], bf[np][1]);
                    MMAH16816(acc[mf][np * 2 + 1], af[mf], bf[np][2], bf[np][3]);
                }
        }
        __syncthreads();
    }

#pragma unroll
    for (int mf = 0; mf < 4; mf++)
#pragma unroll
        for (int rh = 0; rh < 2; rh++) {
            int gr = m0 + wm * 64 + mf * 16 + (lane >> 2) + rh * 8;
            int bi = gr / Mpb;
            int rr = gr - bi * Mpb;
            size_t base = (size_t)bi * outBS + (size_t)(rr + rowOff) * ldc
                        + n0 + wn * 64 + (lane & 3) * 2;
            if (outHalf) {
                __half* rowp = (__half*)Cv + base;
#pragma unroll
                for (int nf = 0; nf < 8; nf++) {
                    __half2 v = __floats2half2_rn(acc[mf][nf][rh * 2 + 0], acc[mf][nf][rh * 2 + 1]);
                    *(__half2*)(rowp + nf * 8) = v;
                }
            } else {
                float* rowp = (float*)Cv + base;
#pragma unroll
                for (int nf = 0; nf < 8; nf++) {
                    float2 v = make_float2(acc[mf][nf][rh * 2 + 0], acc[mf][nf][rh * 2 + 1]);
                    *(float2*)(rowp + nf * 8) = v;
                }
            }
        }
}

// ---------------- RMS-norm (+RoPE) -> fp16, warp-per-row (unchanged) ----------------
__global__ __launch_bounds__(256) void rms_rope_w_kernel(
    const float* __restrict__ buf, __half* __restrict__ outh,
    const float* __restrict__ scale,
    int heads, int rowsPerBatch, int bufRPB, int rowStart, int doRope, float outScale)
{
    int rowIdx = blockIdx.x * 8 + (threadIdx.x >> 5);
    int lane = threadIdx.x & 31;
    int head = rowIdx % heads;
    int tmp = rowIdx / heads;
    int t = tmp % rowsPerBatch;
    int b = tmp / rowsPerBatch;
    size_t off = ((size_t)((size_t)b * bufRPB + rowStart + t) * heads + head) * H_DIM;

    float4 x1 = *(const float4*)(buf + off + lane * 4);
    float4 x2 = *(const float4*)(buf + off + 128 + lane * 4);
    float ss = x1.x * x1.x + x1.y * x1.y + x1.z * x1.z + x1.w * x1.w
             + x2.x * x2.x + x2.y * x2.y + x2.z * x2.z + x2.w * x2.w;
#pragma unroll
    for (int o = 16; o > 0; o >>= 1) ss += __shfl_xor_sync(0xffffffffu, ss, o);
    float rinv = rsqrtf(ss * (1.f / 256.f) + 1e-6f) * outScale;

    float4 s1 = *(const float4*)(scale + lane * 4);
    float4 s2 = *(const float4*)(scale + 128 + lane * 4);
    float y1[4] = { x1.x * rinv * (1.f + s1.x), x1.y * rinv * (1.f + s1.y),
                    x1.z * rinv * (1.f + s1.z), x1.w * rinv * (1.f + s1.w) };
    float y2[4] = { x2.x * rinv * (1.f + s2.x), x2.y * rinv * (1.f + s2.y),
                    x2.z * rinv * (1.f + s2.z), x2.w * rinv * (1.f + s2.w) };
    float o1[4], o2[4];
    if (doRope) {
#pragma unroll
        for (int i = 0; i < 4; i++) {
            float ang = (float)t * exp2f(-(float)(lane * 4 + i) * 0.10381025296522988f);
            float sn, cs;
            sincosf(ang, &sn, &cs);
            o1[i] = y1[i] * cs - y2[i] * sn;
            o2[i] = y2[i] * cs + y1[i] * sn;
        }
    } else {
#pragma unroll
        for (int i = 0; i < 4; i++) { o1[i] = y1[i]; o2[i] = y2[i]; }
    }
    __half2 a0 = __floats2half2_rn(o1[0], o1[1]);
    __half2 a1 = __floats2half2_rn(o1[2], o1[3]);
    __half2 b0 = __floats2half2_rn(o2[0], o2[1]);
    __half2 b1 = __floats2half2_rn(o2[2], o2[3]);
    *(uint2*)(outh + off + lane * 4) = make_uint2(*(uint32_t*)&a0, *(uint32_t*)&a1);
    *(uint2*)(outh + off + 128 + lane * 4) = make_uint2(*(uint32_t*)&b0, *(uint32_t*)&b1);
}

// ---------------- flash v3 (R11 core + qt0 split param) ----------------
#define F2_KB 65536u
#define F2_VB 131072u
#define F2_ST 32768u
#define FH2_SMEM 196608

__global__ void __launch_bounds__(256, 1) flash2_hmma(
    const __half* __restrict__ Qh, const __half* __restrict__ Kh,
    const __half* __restrict__ Vh, __half* __restrict__ Oh, int qt0)
{
    extern __shared__ char smraw[];
    const uint32_t sb = smem_u32(smraw);
    const int tid = threadIdx.x, lane = tid & 31, w = tid >> 5;
    const int qt = blockIdx.x + qt0, n = blockIdx.y, b = blockIdx.z;
    const int kh = n >> 1, qbase = qt << 7;

    const char* qg = (const char*)(Qh + ((size_t)(b * T_LEN + qbase) * N_HEADS + n) * H_DIM);
#pragma unroll
    for (int p = 0; p < 16; p++) {
        int idx = tid + p * 256;
        int r = idx >> 5, c = idx & 31;
        CP16(sb + fsw(r, c * 16), qg + (size_t)r * (N_HEADS * H_DIM * 2) + c * 16);
    }
    CP_COMMIT;

    const char* kg = (const char*)(Kh + ((size_t)b * S_LEN * K_HEADS + kh) * H_DIM);
    const char* vg = (const char*)(Vh + ((size_t)b * S_LEN * K_HEADS + kh) * H_DIM);
    const int kvstride = K_HEADS * H_DIM * 2;

    const int nSelf = (qt + 1) << 1;
    const int nT = nSelf + (E_LEN >> 6);

#pragma unroll
    for (int p = 0; p < 8; p++) {
        int idx = tid + p * 256;
        int r = idx >> 5, c = idx & 31;
        uint32_t sw = fsw(r, c * 16);
        CP16(sb + F2_KB + sw, kg + (size_t)r * kvstride + c * 16);
        CP16(sb + F2_VB + sw, vg + (size_t)r * kvstride + c * 16);
    }
    CP_COMMIT;

    float oacc[32][4];
#pragma unroll
    for (int nf = 0; nf < 32; nf++)
#pragma unroll
        for (int q = 0; q < 4; q++) oacc[nf][q] = 0.f;
    float m1 = -INFINITY, m2 = -INFINITY, l1 = 0.f, l2 = 0.f;

    const int r8 = lane & 7, sel = lane >> 3;
    const int rowA = w * 16 + r8 + ((sel & 1) << 3);
    const int dselA = sel >> 1;
    const int dselB = sel & 1;
    const int r1g = w * 16 + (lane >> 2), r2g = r1g + 8;
    const uint32_t aBaseQ = sb + (uint32_t)rowA * 512u;
    const int rowAx = rowA & 7;

    for (int t = 0; t < nT; t++) {
        if (t + 1 < nT) {
            int s0n = (t + 1 < nSelf) ? ((t + 1) << 6) : (T_LEN + ((t + 1 - nSelf) << 6));
            uint32_t kb = sb + F2_KB + (uint32_t)((t + 1) & 1) * F2_ST;
            uint32_t vb = sb + F2_VB + (uint32_t)((t + 1) & 1) * F2_ST;
#pragma unroll
            for (int p = 0; p < 8; p++) {
                int idx = tid + p * 256;
                int r = idx >> 5, c = idx & 31;
                uint32_t sw = fsw(r, c * 16);
                CP16(kb + sw, kg + (size_t)(s0n + r) * kvstride + c * 16);
                CP16(vb + sw, vg + (size_t)(s0n + r) * kvstride + c * 16);
            }
            CP_COMMIT;
            CP_WAIT1;
        } else {
            CP_WAIT0;
        }
        __syncthreads();

        const int s0 = (t < nSelf) ? (t << 6) : (T_LEN + ((t - nSelf) << 6));
        const bool diag = (t >= nSelf - 2) && (t < nSelf);
        const uint32_t sK = sb + F2_KB + (uint32_t)(t & 1) * F2_ST;
        const uint32_t sV = sb + F2_VB + (uint32_t)(t & 1) * F2_ST;

        float sacc[8][4];
#pragma unroll
        for (int nf = 0; nf < 8; nf++)
#pragma unroll
            for (int q = 0; q < 4; q++) sacc[nf][q] = 0.f;
#pragma unroll 4
        for (int ks = 0; ks < 16; ks++) {
            uint32_t a[4];
            LDSM4(a[0], a[1], a[2], a[3], aBaseQ + (uint32_t)((((ks << 1) + dselA) ^ rowAx) << 4));
#pragma unroll
            for (int nf2 = 0; nf2 < 4; nf2++) {
                int rowB = nf2 * 16 + r8 + ((sel >> 1) << 3);
                uint32_t bb[4];
                LDSM4(bb[0], bb[1], bb[2], bb[3],
                      sK + (uint32_t)rowB * 512u + (uint32_t)((((ks << 1) + dselB) ^ (rowB & 7)) << 4));
                MMAH16816(sacc[nf2 * 2 + 0], a, bb[0], bb[1]);
                MMAH16816(sacc[nf2 * 2 + 1], a, bb[2], bb[3]);
            }
        }

        float mx1 = -INFINITY, mx2 = -INFINITY;
#pragma unroll
        for (int nf = 0; nf < 8; nf++)
#pragma unroll
            for (int e = 0; e < 4; e++) {
                float s = sacc[nf][e];
                float cpv = 50.f - __fdividef(100.f, __expf(0.04f * s) + 1.f);
                if (diag) {
                    int col = s0 + nf * 8 + ((lane & 3) << 1) + (e & 1);
                    int row = qbase + ((e < 2) ? r1g : r2g);
                    if (col > row) cpv = -INFINITY;
                }
                sacc[nf][e] = cpv;
                if (e < 2) mx1 = fmaxf(mx1, cpv); else mx2 = fmaxf(mx2, cpv);
            }
        mx1 = fmaxf(mx1, __shfl_xor_sync(0xffffffffu, mx1, 1));
        mx1 = fmaxf(mx1, __shfl_xor_sync(0xffffffffu, mx1, 2));
        mx2 = fmaxf(mx2, __shfl_xor_sync(0xffffffffu, mx2, 1));
        mx2 = fmaxf(mx2, __shfl_xor_sync(0xffffffffu, mx2, 2));
        float mn1 = fmaxf(m1, mx1), mn2 = fmaxf(m2, mx2);
        float corr1 = __expf(m1 - mn1), corr2 = __expf(m2 - mn2);
        m1 = mn1; m2 = mn2;

        uint32_t pfrag[4][4];
        float sum1 = 0.f, sum2 = 0.f;
#pragma unroll
        for (int nf = 0; nf < 8; nf++) {
            float p0 = __expf(sacc[nf][0] - mn1);
            float p1 = __expf(sacc[nf][1] - mn1);
            float p2 = __expf(sacc[nf][2] - mn2);
            float p3 = __expf(sacc[nf][3] - mn2);
            sum1 += p0 + p1; sum2 += p2 + p3;
            int ks = nf >> 1, hi = nf & 1;
            pfrag[ks][hi * 2 + 0] = packh2(p0, p1);
            pfrag[ks][hi * 2 + 1] = packh2(p2, p3);
        }
        sum1 += __shfl_xor_sync(0xffffffffu, sum1, 1);
        sum1 += __shfl_xor_sync(0xffffffffu, sum1, 2);
        sum2 += __shfl_xor_sync(0xffffffffu, sum2, 1);
        sum2 += __shfl_xor_sync(0xffffffffu, sum2, 2);
        l1 = l1 * corr1 + sum1;
        l2 = l2 * corr2 + sum2;

#pragma unroll
        for (int nf = 0; nf < 32; nf++) {
            oacc[nf][0] *= corr1; oacc[nf][1] *= corr1;
            oacc[nf][2] *= corr2; oacc[nf][3] *= corr2;
        }

#pragma unroll
        for (int ks = 0; ks < 4; ks++) {
            int rowV = ks * 16 + r8 + ((sel & 1) << 3);
            uint32_t vBase = sV + (uint32_t)rowV * 512u;
            int rVx = rowV & 7;
#pragma unroll
            for (int nf2 = 0; nf2 < 16; nf2++) {
                int chunk = nf2 * 2 + (sel >> 1);
                uint32_t bb[4];
                LDSM4T(bb[0], bb[1], bb[2], bb[3], vBase + (uint32_t)((chunk ^ rVx) << 4));
                MMAH16816(oacc[nf2 * 2 + 0], pfrag[ks], bb[0], bb[1]);
                MMAH16816(oacc[nf2 * 2 + 1], pfrag[ks], bb[2], bb[3]);
            }
        }
        __syncthreads();
    }

    float inv1 = 1.f / l1;
    float inv2 = 1.f / l2;
    int t1 = qbase + r1g, t2 = qbase + r2g;
    __half* o1 = Oh + ((size_t)(b * T_LEN + t1)) * (N_HEADS * H_DIM) + n * H_DIM + ((lane & 3) << 1);
    __half* o2 = Oh + ((size_t)(b * T_LEN + t2)) * (N_HEADS * H_DIM) + n * H_DIM + ((lane & 3) << 1);
#pragma unroll
    for (int nf = 0; nf < 32; nf++) {
        __half2 v1 = __floats2half2_rn(oacc[nf][0] * inv1, oacc[nf][1] * inv1);
        __half2 v2 = __floats2half2_rn(oacc[nf][2] * inv2, oacc[nf][3] * inv2);
        *(__half2*)(o1 + nf * 8) = v1;
        *(__half2*)(o2 + nf * 8) = v2;
    }
}

// ---------------- launch: DAG + split flash/O-GEMM pipeline ----------------
extern "C" void kernel_launch(void* const* d_in, const int* in_sizes, int n_in,
                              void* d_out, int out_size)
{
    (void)in_sizes; (void)n_in; (void)out_size;
    const float* hs  = (const float*)d_in[0];
    const float* enc = (const float*)d_in[1];
    const float* qw  = (const float*)d_in[4];
    const float* kw  = (const float*)d_in[5];
    const float* vw  = (const float*)d_in[6];
    const float* ow  = (const float*)d_in[7];
    const float* qsc = (const float*)d_in[8];
    const float* ksc = (const float*)d_in[9];
    float* out = (float*)d_out;

    float *qb, *kb;
    cudaGetSymbolAddress((void**)&qb, g_q);
    cudaGetSymbolAddress((void**)&kb, g_k);
    __half *q16, *k16, *v16;
    cudaGetSymbolAddress((void**)&q16, g_q16);
    cudaGetSymbolAddress((void**)&k16, g_k16);
    cudaGetSymbolAddress((void**)&v16, g_v16);
    __half *hs2, *enc2, *qw2, *kw2, *vw2, *ow2, *at2;
    cudaGetSymbolAddress((void**)&hs2, g_hs2);
    cudaGetSymbolAddress((void**)&enc2, g_enc2);
    cudaGetSymbolAddress((void**)&qw2, g_qw2);
    cudaGetSymbolAddress((void**)&kw2, g_kw2);
    cudaGetSymbolAddress((void**)&vw2, g_vw2);
    cudaGetSymbolAddress((void**)&ow2, g_ow2);
    cudaGetSymbolAddress((void**)&at2, g_at2);

    static int cfg = 0;
    static cudaStream_t s1, s2;
    static cudaEvent_t eFork, eHs, eEnc, eQw, eKw, eKdone, eVdone, eOw, eF1, eOg1;
    if (!cfg) {
        cudaFuncSetAttribute(gemm_hmma, cudaFuncAttributeMaxDynamicSharedMemorySize, GEMM_SMEM);
        cudaFuncSetAttribute(flash2_hmma, cudaFuncAttributeMaxDynamicSharedMemorySize, FH2_SMEM);
        cudaStreamCreateWithFlags(&s1, cudaStreamNonBlocking);
        cudaStreamCreateWithFlags(&s2, cudaStreamNonBlocking);
        cudaEventCreateWithFlags(&eFork, cudaEventDisableTiming);
        cudaEventCreateWithFlags(&eHs, cudaEventDisableTiming);
        cudaEventCreateWithFlags(&eEnc, cudaEventDisableTiming);
        cudaEventCreateWithFlags(&eQw, cudaEventDisableTiming);
        cudaEventCreateWithFlags(&eKw, cudaEventDisableTiming);
        cudaEventCreateWithFlags(&eKdone, cudaEventDisableTiming);
        cudaEventCreateWithFlags(&eVdone, cudaEventDisableTiming);
        cudaEventCreateWithFlags(&eOw, cudaEventDisableTiming);
        cudaEventCreateWithFlags(&eF1, cudaEventDisableTiming);
        cudaEventCreateWithFlags(&eOg1, cudaEventDisableTiming);
        cfg = 1;
    }

    const long long kvBS = (long long)S_LEN * K_HEADS * H_DIM;
    const long long pHS = (long long)D_DIM * H_DIM;

    // FORK
    cudaEventRecord(eFork, 0);
    cudaStreamWaitEvent(s1, eFork, 0);
    cudaStreamWaitEvent(s2, eFork, 0);

    // s0: hs convert
    a2h_kernel<<<(4096LL * 2048) / 1024, 256, 0, 0>>>(hs, hs2);
    cudaEventRecord(eHs, 0);
    // s1: enc convert
    a2h_kernel<<<(4096LL * 2048) / 1024, 256, 0, s1>>>(enc, enc2);
    cudaEventRecord(eEnc, s1);
    // s2: weight converts
    wsplit_kernel<<<dim3(4096 / 32, D_DIM / 32), 256, 0, s2>>>(qw, qw2, D_DIM, H_DIM, pHS, H_DIM);
    cudaEventRecord(eQw, s2);
    wsplit_kernel<<<dim3(2048 / 32, D_DIM / 32), 256, 0, s2>>>(kw, kw2, D_DIM, H_DIM, pHS, H_DIM);
    cudaEventRecord(eKw, s2);
    wsplit_kernel<<<dim3(2048 / 32, D_DIM / 32), 256, 0, s2>>>(vw, vw2, D_DIM, H_DIM, pHS, H_DIM);

    // s0: Q path
    cudaStreamWaitEvent(0, eQw, 0);
    gemm_hmma<<<dim3(32, 32), 128, GEMM_SMEM, 0>>>(hs2, qw2, qb, 2048, 4096, 0LL, 0, 4096, 0, 32, 0, 0);
    rms_rope_w_kernel<<<B_SZ * T_LEN * N_HEADS / 8, 256, 0, 0>>>(qb, q16, qsc, N_HEADS, T_LEN, T_LEN, 0, 1, 0.0625f);

    // s1: K path
    cudaStreamWaitEvent(s1, eHs, 0);
    cudaStreamWaitEvent(s1, eKw, 0);
    gemm_hmma<<<dim3(16, 32), 128, GEMM_SMEM, s1>>>(hs2, kw2, kb, 2048, T_LEN, kvBS, 0, 2048, 0, 32, 0, 0);
    gemm_hmma<<<dim3(16, 32), 128, GEMM_SMEM, s1>>>(enc2, kw2, kb, 2048, E_LEN, kvBS, T_LEN, 2048, 0, 32, 0, 0);
    rms_rope_w_kernel<<<B_SZ * T_LEN * K_HEADS / 8, 256, 0, s1>>>(kb, k16, ksc, K_HEADS, T_LEN, S_LEN, 0, 1, 1.0f);
    rms_rope_w_kernel<<<B_SZ * E_LEN * K_HEADS / 8, 256, 0, s1>>>(kb, k16, ksc, K_HEADS, E_LEN, S_LEN, T_LEN, 0, 1.0f);
    cudaEventRecord(eKdone, s1);

    // s2: V path
    cudaStreamWaitEvent(s2, eHs, 0);
    cudaStreamWaitEvent(s2, eEnc, 0);
    gemm_hmma<<<dim3(16, 32), 128, GEMM_SMEM, s2>>>(hs2, vw2, v16, 2048, T_LEN, kvBS, 0, 2048, 1, 32, 0, 0);
    gemm_hmma<<<dim3(16, 32), 128, GEMM_SMEM, s2>>>(enc2, vw2, v16, 2048, E_LEN, kvBS, T_LEN, 2048, 1, 32, 0, 0);
    cudaEventRecord(eVdone, s2);
    wsplit_kernel<<<dim3(2048 / 32, 4096 / 32), 256, 0, s2>>>(ow, ow2, 4096, D_DIM, 0LL, D_DIM);
    cudaEventRecord(eOw, s2);

    // s0: flash half 1 (qt 0..3, tokens t<512)
    cudaStreamWaitEvent(0, eKdone, 0);
    cudaStreamWaitEvent(0, eVdone, 0);
    flash2_hmma<<<dim3(4, N_HEADS, B_SZ), 256, FH2_SMEM, 0>>>(q16, k16, v16, at2, 0);
    cudaEventRecord(eF1, 0);
    // s0: flash half 2 (qt 4..7)
    flash2_hmma<<<dim3(4, N_HEADS, B_SZ), 256, FH2_SMEM, 0>>>(q16, k16, v16, at2, 4);

    // s1: O-GEMM half 1 (rows t<512) overlaps flash half 2
    cudaStreamWaitEvent(s1, eF1, 0);
    cudaStreamWaitEvent(s1, eOw, 0);
    gemm_hmma<<<dim3(16, 16), 128, GEMM_SMEM, s1>>>(at2, ow2, out, 4096, 4096, 0LL, 0, 2048, 0, 4, 1024, 0);
    cudaEventRecord(eOg1, s1);

    // s0: O-GEMM half 2 (rows t>=512), join all
    cudaStreamWaitEvent(0, eOw, 0);
    cudaStreamWaitEvent(0, eOg1, 0);
    gemm_hmma<<<dim3(16, 16), 128, GEMM_SMEM, 0>>>(at2, ow2, out, 4096, 4096, 0LL, 0, 2048, 0, 4, 1024, 512);
}